// round 1
// baseline (speedup 1.0000x reference)
#include <cuda_runtime.h>
#include <math.h>

// Problem constants
static constexpr int Bc  = 4;
static constexpr int Sc  = 1024;
static constexpr int Dc  = 1024;
static constexpr int Hc  = 16;
static constexpr int HDc = 64;
static constexpr int Lc  = 12;
static constexpr int BS  = Bc * Sc;       // 4096 rows

// Scratch (no cudaMalloc allowed)
__device__ float g_qkv[(size_t)BS * 3 * Dc];   // 4096 x 3072  (50.3 MB)
__device__ float g_ctx[(size_t)BS * Dc];       // 4096 x 1024  (16.8 MB)

// ---------------------------------------------------------------------------
// Tiled SGEMM: C[M,N] = A[M,K] @ W[K,N] + bias[N]
// SPLITHEAD: write C element (row=b*S+s, col=h*64+d) to out[((b*H+h)*S+s)*64+d]
// ---------------------------------------------------------------------------
template<bool SPLITHEAD>
__global__ __launch_bounds__(256)
void sgemm_bias_kernel(const float* __restrict__ A, const float* __restrict__ W,
                       const float* __restrict__ bias, float* __restrict__ C,
                       int M, int N, int K)
{
    constexpr int BM = 128, BN = 128, BK = 16;
    __shared__ float As[BK][BM];
    __shared__ float Ws[BK][BN];

    const int tid = threadIdx.x;
    const int m0 = blockIdx.y * BM;
    const int n0 = blockIdx.x * BN;
    const int ty = tid >> 4;       // 0..15
    const int tx = tid & 15;       // 0..15

    float acc[8][8];
#pragma unroll
    for (int i = 0; i < 8; i++)
#pragma unroll
        for (int j = 0; j < 8; j++) acc[i][j] = 0.f;

    for (int k0 = 0; k0 < K; k0 += BK) {
        // Load A tile (BM x BK), store transposed into As[k][m]
#pragma unroll
        for (int u = 0; u < 2; u++) {
            int f = tid * 2 + u;            // float4 id 0..511
            int r = f >> 2;                 // row within tile 0..127
            int c = (f & 3) << 2;           // k-col 0,4,8,12
            float4 v = *reinterpret_cast<const float4*>(
                &A[(size_t)(m0 + r) * K + k0 + c]);
            As[c + 0][r] = v.x;
            As[c + 1][r] = v.y;
            As[c + 2][r] = v.z;
            As[c + 3][r] = v.w;
        }
        // Load W tile (BK x BN) directly
#pragma unroll
        for (int u = 0; u < 2; u++) {
            int f = tid * 2 + u;            // float4 id 0..511
            int r = f >> 5;                 // k-row 0..15
            int c = (f & 31) << 2;          // n-col 0..124
            *reinterpret_cast<float4*>(&Ws[r][c]) =
                *reinterpret_cast<const float4*>(&W[(size_t)(k0 + r) * N + n0 + c]);
        }
        __syncthreads();

#pragma unroll
        for (int kk = 0; kk < BK; kk++) {
            float a[8], w[8];
            *reinterpret_cast<float4*>(&a[0]) = *reinterpret_cast<float4*>(&As[kk][ty * 8]);
            *reinterpret_cast<float4*>(&a[4]) = *reinterpret_cast<float4*>(&As[kk][ty * 8 + 4]);
            *reinterpret_cast<float4*>(&w[0]) = *reinterpret_cast<float4*>(&Ws[kk][tx * 8]);
            *reinterpret_cast<float4*>(&w[4]) = *reinterpret_cast<float4*>(&Ws[kk][tx * 8 + 4]);
#pragma unroll
            for (int i = 0; i < 8; i++)
#pragma unroll
                for (int j = 0; j < 8; j++)
                    acc[i][j] = fmaf(a[i], w[j], acc[i][j]);
        }
        __syncthreads();
    }

    // Epilogue: bias + store
#pragma unroll
    for (int i = 0; i < 8; i++) {
        int row = m0 + ty * 8 + i;
#pragma unroll
        for (int j4 = 0; j4 < 2; j4++) {
            int col = n0 + tx * 8 + j4 * 4;
            float4 v;
            v.x = acc[i][j4 * 4 + 0] + bias[col + 0];
            v.y = acc[i][j4 * 4 + 1] + bias[col + 1];
            v.z = acc[i][j4 * 4 + 2] + bias[col + 2];
            v.w = acc[i][j4 * 4 + 3] + bias[col + 3];
            if (!SPLITHEAD) {
                *reinterpret_cast<float4*>(&C[(size_t)row * N + col]) = v;
            } else {
                int b  = row >> 10;         // row / S
                int s  = row & 1023;        // row % S
                int ch = col >> 6;          // head
                int cl = col & 63;          // dim within head (4-aligned, fits in head)
                *reinterpret_cast<float4*>(
                    &C[(size_t)(((b * Hc + ch) * Sc) + s) * HDc + cl]) = v;
            }
        }
    }
}

// ---------------------------------------------------------------------------
// Fused attention: causal token attention + per-position memory-slot attention
// One thread per query row; online softmax; K/V tiles staged in smem.
// ---------------------------------------------------------------------------
__global__ __launch_bounds__(128)
void attn_kernel(const float* __restrict__ qkv, const float* __restrict__ pk,
                 const float* __restrict__ pv, float* __restrict__ ctx)
{
    __shared__ float sk[64 * 64];
    __shared__ float sv[64 * 64];

    const int bid  = blockIdx.x;
    const int tile = bid & 7;           // q tile (128 rows each)
    const int h    = (bid >> 3) & 15;
    const int b    = bid >> 7;
    const int tid  = threadIdx.x;
    const int i    = tile * 128 + tid;  // query row within sequence
    const float scale = 0.125f;         // 1/sqrt(64)

    // Load q (pre-scaled) into registers
    float q[64];
    {
        const float* qp = &qkv[(size_t)(b * Sc + i) * (3 * Dc) + h * 64];
#pragma unroll
        for (int d4 = 0; d4 < 16; d4++) {
            float4 v = *reinterpret_cast<const float4*>(&qp[d4 * 4]);
            q[d4 * 4 + 0] = v.x * scale;
            q[d4 * 4 + 1] = v.y * scale;
            q[d4 * 4 + 2] = v.z * scale;
            q[d4 * 4 + 3] = v.w * scale;
        }
    }

    float mrun = -3.0e38f, srun = 0.f;
    float acc[64];
#pragma unroll
    for (int d = 0; d < 64; d++) acc[d] = 0.f;

    const int ntiles = (tile + 1) * 2;  // k tiles of 64 rows covering j <= i
    for (int kt = 0; kt < ntiles; kt++) {
        const int j0 = kt * 64;
        // Stage K and V tiles (64 rows x 64 floats each) cooperatively
#pragma unroll
        for (int u = 0; u < 8; u++) {
            int f = u * 128 + tid;      // float4 id 0..1023
            int r = f >> 4;             // row 0..63
            int c = (f & 15) << 2;      // col 0..60
            const float* src = &qkv[(size_t)(b * Sc + j0 + r) * (3 * Dc) + h * 64 + c];
            *reinterpret_cast<float4*>(&sk[r * 64 + c]) =
                *reinterpret_cast<const float4*>(src + Dc);       // k block
            *reinterpret_cast<float4*>(&sv[r * 64 + c]) =
                *reinterpret_cast<const float4*>(src + 2 * Dc);   // v block
        }
        __syncthreads();

        const int jmax = i - j0;        // causal: process jj <= jmax
        for (int jj = 0; jj < 64; jj++) {
            if (jj > jmax) break;
            float d0 = 0.f, d1 = 0.f, d2 = 0.f, d3 = 0.f;
#pragma unroll
            for (int d4 = 0; d4 < 16; d4++) {
                float4 kv = *reinterpret_cast<const float4*>(&sk[jj * 64 + d4 * 4]);
                d0 = fmaf(q[d4 * 4 + 0], kv.x, d0);
                d1 = fmaf(q[d4 * 4 + 1], kv.y, d1);
                d2 = fmaf(q[d4 * 4 + 2], kv.z, d2);
                d3 = fmaf(q[d4 * 4 + 3], kv.w, d3);
            }
            float sc = (d0 + d1) + (d2 + d3);
            float mnew = fmaxf(mrun, sc);
            if (mnew > mrun) {
                float corr = __expf(mrun - mnew);
                srun *= corr;
#pragma unroll
                for (int d = 0; d < 64; d++) acc[d] *= corr;
                mrun = mnew;
            }
            float p = __expf(sc - mrun);
            srun += p;
#pragma unroll
            for (int d4 = 0; d4 < 16; d4++) {
                float4 vv = *reinterpret_cast<const float4*>(&sv[jj * 64 + d4 * 4]);
                acc[d4 * 4 + 0] = fmaf(p, vv.x, acc[d4 * 4 + 0]);
                acc[d4 * 4 + 1] = fmaf(p, vv.y, acc[d4 * 4 + 1]);
                acc[d4 * 4 + 2] = fmaf(p, vv.z, acc[d4 * 4 + 2]);
                acc[d4 * 4 + 3] = fmaf(p, vv.w, acc[d4 * 4 + 3]);
            }
        }
        __syncthreads();
    }

    // Memory-slot attention: L=12 per-position slots, streamed from global
    const size_t pbase = (size_t)((b * Hc + h) * Sc + i) * Lc * HDc;
    const float* pkb = pk + pbase;
    const float* pvb = pv + pbase;
#pragma unroll 1
    for (int l = 0; l < Lc; l++) {
        float d0 = 0.f, d1 = 0.f, d2 = 0.f, d3 = 0.f;
#pragma unroll
        for (int d4 = 0; d4 < 16; d4++) {
            float4 kv = *reinterpret_cast<const float4*>(&pkb[l * 64 + d4 * 4]);
            d0 = fmaf(q[d4 * 4 + 0], kv.x, d0);
            d1 = fmaf(q[d4 * 4 + 1], kv.y, d1);
            d2 = fmaf(q[d4 * 4 + 2], kv.z, d2);
            d3 = fmaf(q[d4 * 4 + 3], kv.w, d3);
        }
        float sc = (d0 + d1) + (d2 + d3);
        float mnew = fmaxf(mrun, sc);
        if (mnew > mrun) {
            float corr = __expf(mrun - mnew);
            srun *= corr;
#pragma unroll
            for (int d = 0; d < 64; d++) acc[d] *= corr;
            mrun = mnew;
        }
        float p = __expf(sc - mrun);
        srun += p;
#pragma unroll
        for (int d4 = 0; d4 < 16; d4++) {
            float4 vv = *reinterpret_cast<const float4*>(&pvb[l * 64 + d4 * 4]);
            acc[d4 * 4 + 0] = fmaf(p, vv.x, acc[d4 * 4 + 0]);
            acc[d4 * 4 + 1] = fmaf(p, vv.y, acc[d4 * 4 + 1]);
            acc[d4 * 4 + 2] = fmaf(p, vv.z, acc[d4 * 4 + 2]);
            acc[d4 * 4 + 3] = fmaf(p, vv.w, acc[d4 * 4 + 3]);
        }
    }

    // Normalize + write ctx in (B,S,D) layout (heads re-interleaved)
    const float inv = 1.f / srun;
    float* cp = &g_ctx[(size_t)(b * Sc + i) * Dc + h * 64];
    (void)ctx;
#pragma unroll
    for (int d4 = 0; d4 < 16; d4++) {
        float4 o;
        o.x = acc[d4 * 4 + 0] * inv;
        o.y = acc[d4 * 4 + 1] * inv;
        o.z = acc[d4 * 4 + 2] * inv;
        o.w = acc[d4 * 4 + 3] * inv;
        *reinterpret_cast<float4*>(&cp[d4 * 4]) = o;
    }
}

// ---------------------------------------------------------------------------
extern "C" void kernel_launch(void* const* d_in, const int* in_sizes, int n_in,
                              void* d_out, int out_size)
{
    const float* x     = (const float*)d_in[0];
    const float* pk    = (const float*)d_in[1];
    const float* pv    = (const float*)d_in[2];
    const float* w_qkv = (const float*)d_in[3];
    const float* b_qkv = (const float*)d_in[4];
    const float* w_k   = (const float*)d_in[5];
    const float* b_k   = (const float*)d_in[6];
    const float* w_v   = (const float*)d_in[7];
    const float* b_v   = (const float*)d_in[8];
    const float* w_o   = (const float*)d_in[9];
    const float* b_o   = (const float*)d_in[10];

    float* out  = (float*)d_out;
    float* kcol = out + (size_t)Bc * Sc * Dc;                 // 4,194,304
    float* vcol = kcol + (size_t)Bc * Hc * Sc * HDc;          // +4,194,304

    static float* qkvp = nullptr;
    static float* ctxp = nullptr;
    if (!qkvp) {
        cudaGetSymbolAddress((void**)&qkvp, g_qkv);
        cudaGetSymbolAddress((void**)&ctxp, g_ctx);
    }

    dim3 blk(256);
    // qkv = x @ w_qkv + b_qkv          -> scratch (4096 x 3072)
    sgemm_bias_kernel<false><<<dim3(3 * Dc / 128, BS / 128), blk>>>(
        x, w_qkv, b_qkv, qkvp, BS, 3 * Dc, Dc);
    // k_col = split_heads(x @ w_k + b_k) -> d_out segment 2
    sgemm_bias_kernel<true><<<dim3(Dc / 128, BS / 128), blk>>>(
        x, w_k, b_k, kcol, BS, Dc, Dc);
    // v_col = split_heads(x @ w_v + b_v) -> d_out segment 3
    sgemm_bias_kernel<true><<<dim3(Dc / 128, BS / 128), blk>>>(
        x, w_v, b_v, vcol, BS, Dc, Dc);
    // fused causal + memory attention -> g_ctx (B,S,D)
    attn_kernel<<<Bc * Hc * (Sc / 128), 128>>>(qkvp, pk, pv, ctxp);
    // out = ctx @ w_o + b_o            -> d_out segment 1
    sgemm_bias_kernel<false><<<dim3(Dc / 128, BS / 128), blk>>>(
        ctxp, w_o, b_o, out, BS, Dc, Dc);
}

// round 3
// speedup vs baseline: 1.5269x; 1.5269x over previous
#include <cuda_runtime.h>
#include <cuda_bf16.h>
#include <cstdint>
#include <math.h>

// Problem constants
static constexpr int Bc  = 4;
static constexpr int Sc  = 1024;
static constexpr int Dc  = 1024;
static constexpr int Hc  = 16;
static constexpr int HDc = 64;
static constexpr int Lc  = 12;
static constexpr int BS  = Bc * Sc;       // 4096 rows

// ---------------------------------------------------------------------------
// Scratch (__device__ globals; no cudaMalloc allowed)
// ---------------------------------------------------------------------------
__device__ float g_qkv[(size_t)BS * 3 * Dc];   // 4096 x 3072
__device__ float g_ctx[(size_t)BS * Dc];       // 4096 x 1024
__device__ __nv_bfloat16 g_Ah[(size_t)BS * Dc];          // A hi (x, later ctx)
__device__ __nv_bfloat16 g_Al[(size_t)BS * Dc];          // A lo
__device__ __nv_bfloat16 g_Wqh[(size_t)3 * Dc * Dc];     // w_qkv^T hi  [N,K]
__device__ __nv_bfloat16 g_Wql[(size_t)3 * Dc * Dc];
__device__ __nv_bfloat16 g_Wkh[(size_t)Dc * Dc];
__device__ __nv_bfloat16 g_Wkl[(size_t)Dc * Dc];
__device__ __nv_bfloat16 g_Wvh[(size_t)Dc * Dc];
__device__ __nv_bfloat16 g_Wvl[(size_t)Dc * Dc];
__device__ __nv_bfloat16 g_Woh[(size_t)Dc * Dc];
__device__ __nv_bfloat16 g_Wol[(size_t)Dc * Dc];

// ---------------------------------------------------------------------------
// PTX helpers (base-PTX only: cp.async / ldmatrix / mma.sync — no 'a' features)
// ---------------------------------------------------------------------------
__device__ __forceinline__ uint32_t smem_u32(const void* p) {
    uint32_t a;
    asm("{ .reg .u64 t; cvta.to.shared.u64 t, %1; cvt.u32.u64 %0, t; }"
        : "=r"(a) : "l"(p));
    return a;
}

__device__ __forceinline__ void cp16(uint32_t saddr, const void* gaddr) {
    asm volatile("cp.async.cg.shared.global [%0], [%1], 16;"
                 :: "r"(saddr), "l"(gaddr));
}
#define CP_COMMIT() asm volatile("cp.async.commit_group;" ::: "memory")
#define CP_WAIT(n)  asm volatile("cp.async.wait_group %0;" :: "n"(n) : "memory")

#define LDSM_X4(r0, r1, r2, r3, addr) \
    asm volatile("ldmatrix.sync.aligned.m8n8.x4.shared.b16 {%0,%1,%2,%3}, [%4];" \
                 : "=r"(r0), "=r"(r1), "=r"(r2), "=r"(r3) : "r"(addr))

#define MMA16816(d, a0, a1, a2, a3, b0, b1) \
    asm volatile("mma.sync.aligned.m16n8k16.row.col.f32.bf16.bf16.f32 " \
                 "{%0,%1,%2,%3}, {%4,%5,%6,%7}, {%8,%9}, {%0,%1,%2,%3};" \
                 : "+f"((d)[0]), "+f"((d)[1]), "+f"((d)[2]), "+f"((d)[3]) \
                 : "r"(a0), "r"(a1), "r"(a2), "r"(a3), "r"(b0), "r"(b1))

// ---------------------------------------------------------------------------
// fp32 -> (hi, lo) bf16 split, elementwise (A operands)
// ---------------------------------------------------------------------------
__global__ __launch_bounds__(256)
void convert_hilo(const float* __restrict__ src, __nv_bfloat16* __restrict__ h,
                  __nv_bfloat16* __restrict__ l, int n4)
{
    int i = blockIdx.x * blockDim.x + threadIdx.x;
    if (i >= n4) return;
    float4 v = reinterpret_cast<const float4*>(src)[i];
    __nv_bfloat162 h01 = __floats2bfloat162_rn(v.x, v.y);
    __nv_bfloat162 h23 = __floats2bfloat162_rn(v.z, v.w);
    float2 f01 = __bfloat1622float2(h01);
    float2 f23 = __bfloat1622float2(h23);
    __nv_bfloat162 l01 = __floats2bfloat162_rn(v.x - f01.x, v.y - f01.y);
    __nv_bfloat162 l23 = __floats2bfloat162_rn(v.z - f23.x, v.w - f23.y);
    reinterpret_cast<__nv_bfloat162*>(h)[2 * i + 0] = h01;
    reinterpret_cast<__nv_bfloat162*>(h)[2 * i + 1] = h23;
    reinterpret_cast<__nv_bfloat162*>(l)[2 * i + 0] = l01;
    reinterpret_cast<__nv_bfloat162*>(l)[2 * i + 1] = l23;
}

// ---------------------------------------------------------------------------
// W[K,N] fp32 -> Wt[N,K] (hi, lo) bf16 (transpose + split)
// ---------------------------------------------------------------------------
__global__ __launch_bounds__(256)
void convert_wT(const float* __restrict__ W, __nv_bfloat16* __restrict__ Th,
                __nv_bfloat16* __restrict__ Tl, int K, int N)
{
    __shared__ float t[32][33];
    int n0 = blockIdx.x * 32, k0 = blockIdx.y * 32;
    int tx = threadIdx.x, ty = threadIdx.y;   // (32, 8)
#pragma unroll
    for (int i = 0; i < 4; i++)
        t[ty + i * 8][tx] = W[(size_t)(k0 + ty + i * 8) * N + n0 + tx];
    __syncthreads();
#pragma unroll
    for (int i = 0; i < 4; i++) {
        int n = n0 + ty + i * 8;
        float v = t[tx][ty + i * 8];
        __nv_bfloat16 h = __float2bfloat16(v);
        Th[(size_t)n * K + k0 + tx] = h;
        Tl[(size_t)n * K + k0 + tx] = __float2bfloat16(v - __bfloat162float(h));
    }
}

// ---------------------------------------------------------------------------
// bf16x3 HMMA GEMM:  C[M,N] = Ah*Bh + Ah*Bl + Al*Bh + bias
//   A: [M,K] K-major hi/lo.  B: [N,K] K-major hi/lo (pre-transposed weights).
//   Tile 128x128x32, 8 warps (4m x 2n), warp tile 32x64, cp.async dbl-buffer.
//   Smem rows padded to 80B: ldmatrix / cp.async stores are bank-conflict-free.
// ---------------------------------------------------------------------------
static constexpr int LDS_ROW = 80;                       // bytes per 32-bf16 row
static constexpr int TILE_B  = 128 * LDS_ROW;            // 10240 per operand tile
static constexpr int STAGE_B = 4 * TILE_B;               // Ah,Al,Bh,Bl = 40960
static constexpr int GEMM_SMEM = 2 * STAGE_B;            // 81920

template<bool SPLITHEAD>
__global__ __launch_bounds__(256)
void gemm_bf16x3(const __nv_bfloat16* __restrict__ Ah, const __nv_bfloat16* __restrict__ Al,
                 const __nv_bfloat16* __restrict__ Bh, const __nv_bfloat16* __restrict__ Bl,
                 const float* __restrict__ bias, float* __restrict__ C,
                 int M, int N, int K)
{
    extern __shared__ char smem[];
    const uint32_t sb = smem_u32(smem);
    const int tid  = threadIdx.x;
    const int wid  = tid >> 5, lid = tid & 31;
    const int wm   = wid >> 1, wn = wid & 1;             // warp grid 4x2
    const int m0   = blockIdx.y * 128, n0 = blockIdx.x * 128;

    const __nv_bfloat16* srcs[4] = {
        Ah + (size_t)m0 * K, Al + (size_t)m0 * K,
        Bh + (size_t)n0 * K, Bl + (size_t)n0 * K };

    // per-thread load pattern: 2 chunks of 16B per operand tile
    const int f0 = tid, f1 = tid + 256;
    const int r0 = f0 >> 2, c0 = f0 & 3;
    const int r1 = f1 >> 2, c1 = f1 & 3;

    auto load_stage = [&](int kc, int buf) {
        const uint32_t base = sb + buf * STAGE_B;
#pragma unroll
        for (int t = 0; t < 4; t++) {
            const __nv_bfloat16* s = srcs[t] + kc * 32;
            cp16(base + t * TILE_B + r0 * LDS_ROW + c0 * 16,
                 s + (size_t)r0 * K + c0 * 8);
            cp16(base + t * TILE_B + r1 * LDS_ROW + c1 * 16,
                 s + (size_t)r1 * K + c1 * 8);
        }
    };

    float acc[2][8][4];
#pragma unroll
    for (int i = 0; i < 2; i++)
#pragma unroll
        for (int j = 0; j < 8; j++)
#pragma unroll
            for (int v = 0; v < 4; v++) acc[i][j][v] = 0.f;

    // ldmatrix per-lane address pieces
    const int lr = lid & 15;            // row within 16-row group
    const int lh = (lid >> 4) << 4;     // 0 or 16 bytes (k half)

    const int nk = K >> 5;
    load_stage(0, 0);
    CP_COMMIT();

    for (int kc = 0; kc < nk; kc++) {
        const int buf = kc & 1;
        if (kc + 1 < nk) { load_stage(kc + 1, buf ^ 1); CP_COMMIT(); CP_WAIT(1); }
        else             { CP_WAIT(0); }
        __syncthreads();

        const uint32_t base = sb + buf * STAGE_B;
        const uint32_t aHb = base +              (wm * 32 + lr) * LDS_ROW + lh;
        const uint32_t aLb = base + 1 * TILE_B + (wm * 32 + lr) * LDS_ROW + lh;
        const uint32_t bHb = base + 2 * TILE_B + (wn * 64 + lr) * LDS_ROW + lh;
        const uint32_t bLb = base + 3 * TILE_B + (wn * 64 + lr) * LDS_ROW + lh;

#pragma unroll
        for (int ks = 0; ks < 2; ks++) {
            const uint32_t ko = ks * 32;
            uint32_t ah[2][4], al[2][4];
#pragma unroll
            for (int mi = 0; mi < 2; mi++) {
                LDSM_X4(ah[mi][0], ah[mi][1], ah[mi][2], ah[mi][3],
                        aHb + mi * 16 * LDS_ROW + ko);
                LDSM_X4(al[mi][0], al[mi][1], al[mi][2], al[mi][3],
                        aLb + mi * 16 * LDS_ROW + ko);
            }
            uint32_t bh[8][2], bl[8][2];
#pragma unroll
            for (int np = 0; np < 4; np++) {
                uint32_t t0, t1, t2, t3;
                LDSM_X4(t0, t1, t2, t3, bHb + np * 16 * LDS_ROW + ko);
                bh[np * 2][0] = t0; bh[np * 2][1] = t2;
                bh[np * 2 + 1][0] = t1; bh[np * 2 + 1][1] = t3;
                LDSM_X4(t0, t1, t2, t3, bLb + np * 16 * LDS_ROW + ko);
                bl[np * 2][0] = t0; bl[np * 2][1] = t2;
                bl[np * 2 + 1][0] = t1; bl[np * 2 + 1][1] = t3;
            }
#pragma unroll
            for (int mi = 0; mi < 2; mi++)
#pragma unroll
                for (int nj = 0; nj < 8; nj++) {
                    MMA16816(acc[mi][nj], ah[mi][0], ah[mi][1], ah[mi][2], ah[mi][3],
                             bh[nj][0], bh[nj][1]);
                    MMA16816(acc[mi][nj], ah[mi][0], ah[mi][1], ah[mi][2], ah[mi][3],
                             bl[nj][0], bl[nj][1]);
                    MMA16816(acc[mi][nj], al[mi][0], al[mi][1], al[mi][2], al[mi][3],
                             bh[nj][0], bh[nj][1]);
                }
        }
        __syncthreads();
    }

    // Epilogue: d-frag layout: d0,d1 -> row lane>>2, cols (lane&3)*2 (+1); d2,d3 -> row+8
#pragma unroll
    for (int mi = 0; mi < 2; mi++) {
#pragma unroll
        for (int nj = 0; nj < 8; nj++) {
            const int col = n0 + wn * 64 + nj * 8 + (lid & 3) * 2;
            const float2 bv = *reinterpret_cast<const float2*>(bias + col);
#pragma unroll
            for (int half = 0; half < 2; half++) {
                const int row = m0 + wm * 32 + mi * 16 + (lid >> 2) + half * 8;
                float2 o;
                o.x = acc[mi][nj][half * 2 + 0] + bv.x;
                o.y = acc[mi][nj][half * 2 + 1] + bv.y;
                if (!SPLITHEAD) {
                    *reinterpret_cast<float2*>(&C[(size_t)row * N + col]) = o;
                } else {
                    int b = row >> 10, s = row & 1023, h = col >> 6, d = col & 63;
                    *reinterpret_cast<float2*>(
                        &C[(size_t)(((b * Hc + h) * Sc) + s) * HDc + d]) = o;
                }
            }
        }
    }
}

// ---------------------------------------------------------------------------
// Fused attention: causal token attn + memory-slot attn (unchanged, passing)
// ---------------------------------------------------------------------------
__global__ __launch_bounds__(128)
void attn_kernel(const float* __restrict__ qkv, const float* __restrict__ pk,
                 const float* __restrict__ pv, float* __restrict__ ctx)
{
    __shared__ float sk[64 * 64];
    __shared__ float sv[64 * 64];

    const int bid  = blockIdx.x;
    const int tile = bid & 7;
    const int h    = (bid >> 3) & 15;
    const int b    = bid >> 7;
    const int tid  = threadIdx.x;
    const int i    = tile * 128 + tid;
    const float scale = 0.125f;

    float q[64];
    {
        const float* qp = &qkv[(size_t)(b * Sc + i) * (3 * Dc) + h * 64];
#pragma unroll
        for (int d4 = 0; d4 < 16; d4++) {
            float4 v = *reinterpret_cast<const float4*>(&qp[d4 * 4]);
            q[d4 * 4 + 0] = v.x * scale;
            q[d4 * 4 + 1] = v.y * scale;
            q[d4 * 4 + 2] = v.z * scale;
            q[d4 * 4 + 3] = v.w * scale;
        }
    }

    float mrun = -3.0e38f, srun = 0.f;
    float acc[64];
#pragma unroll
    for (int d = 0; d < 64; d++) acc[d] = 0.f;

    const int ntiles = (tile + 1) * 2;
    for (int kt = 0; kt < ntiles; kt++) {
        const int j0 = kt * 64;
#pragma unroll
        for (int u = 0; u < 8; u++) {
            int f = u * 128 + tid;
            int r = f >> 4;
            int c = (f & 15) << 2;
            const float* src = &qkv[(size_t)(b * Sc + j0 + r) * (3 * Dc) + h * 64 + c];
            *reinterpret_cast<float4*>(&sk[r * 64 + c]) =
                *reinterpret_cast<const float4*>(src + Dc);
            *reinterpret_cast<float4*>(&sv[r * 64 + c]) =
                *reinterpret_cast<const float4*>(src + 2 * Dc);
        }
        __syncthreads();

        const int jmax = i - j0;
        for (int jj = 0; jj < 64; jj++) {
            if (jj > jmax) break;
            float d0 = 0.f, d1 = 0.f, d2 = 0.f, d3 = 0.f;
#pragma unroll
            for (int d4 = 0; d4 < 16; d4++) {
                float4 kv = *reinterpret_cast<const float4*>(&sk[jj * 64 + d4 * 4]);
                d0 = fmaf(q[d4 * 4 + 0], kv.x, d0);
                d1 = fmaf(q[d4 * 4 + 1], kv.y, d1);
                d2 = fmaf(q[d4 * 4 + 2], kv.z, d2);
                d3 = fmaf(q[d4 * 4 + 3], kv.w, d3);
            }
            float sc = (d0 + d1) + (d2 + d3);
            float mnew = fmaxf(mrun, sc);
            if (mnew > mrun) {
                float corr = __expf(mrun - mnew);
                srun *= corr;
#pragma unroll
                for (int d = 0; d < 64; d++) acc[d] *= corr;
                mrun = mnew;
            }
            float p = __expf(sc - mrun);
            srun += p;
#pragma unroll
            for (int d4 = 0; d4 < 16; d4++) {
                float4 vv = *reinterpret_cast<const float4*>(&sv[jj * 64 + d4 * 4]);
                acc[d4 * 4 + 0] = fmaf(p, vv.x, acc[d4 * 4 + 0]);
                acc[d4 * 4 + 1] = fmaf(p, vv.y, acc[d4 * 4 + 1]);
                acc[d4 * 4 + 2] = fmaf(p, vv.z, acc[d4 * 4 + 2]);
                acc[d4 * 4 + 3] = fmaf(p, vv.w, acc[d4 * 4 + 3]);
            }
        }
        __syncthreads();
    }

    const size_t pbase = (size_t)((b * Hc + h) * Sc + i) * Lc * HDc;
    const float* pkb = pk + pbase;
    const float* pvb = pv + pbase;
#pragma unroll 1
    for (int l = 0; l < Lc; l++) {
        float d0 = 0.f, d1 = 0.f, d2 = 0.f, d3 = 0.f;
#pragma unroll
        for (int d4 = 0; d4 < 16; d4++) {
            float4 kv = *reinterpret_cast<const float4*>(&pkb[l * 64 + d4 * 4]);
            d0 = fmaf(q[d4 * 4 + 0], kv.x, d0);
            d1 = fmaf(q[d4 * 4 + 1], kv.y, d1);
            d2 = fmaf(q[d4 * 4 + 2], kv.z, d2);
            d3 = fmaf(q[d4 * 4 + 3], kv.w, d3);
        }
        float sc = (d0 + d1) + (d2 + d3);
        float mnew = fmaxf(mrun, sc);
        if (mnew > mrun) {
            float corr = __expf(mrun - mnew);
            srun *= corr;
#pragma unroll
            for (int d = 0; d < 64; d++) acc[d] *= corr;
            mrun = mnew;
        }
        float p = __expf(sc - mrun);
        srun += p;
#pragma unroll
        for (int d4 = 0; d4 < 16; d4++) {
            float4 vv = *reinterpret_cast<const float4*>(&pvb[l * 64 + d4 * 4]);
            acc[d4 * 4 + 0] = fmaf(p, vv.x, acc[d4 * 4 + 0]);
            acc[d4 * 4 + 1] = fmaf(p, vv.y, acc[d4 * 4 + 1]);
            acc[d4 * 4 + 2] = fmaf(p, vv.z, acc[d4 * 4 + 2]);
            acc[d4 * 4 + 3] = fmaf(p, vv.w, acc[d4 * 4 + 3]);
        }
    }

    const float inv = 1.f / srun;
    float* cp = &ctx[(size_t)(b * Sc + i) * Dc + h * 64];
#pragma unroll
    for (int d4 = 0; d4 < 16; d4++) {
        float4 o;
        o.x = acc[d4 * 4 + 0] * inv;
        o.y = acc[d4 * 4 + 1] * inv;
        o.z = acc[d4 * 4 + 2] * inv;
        o.w = acc[d4 * 4 + 3] * inv;
        *reinterpret_cast<float4*>(&cp[d4 * 4]) = o;
    }
}

// ---------------------------------------------------------------------------
extern "C" void kernel_launch(void* const* d_in, const int* in_sizes, int n_in,
                              void* d_out, int out_size)
{
    const float* x     = (const float*)d_in[0];
    const float* pk    = (const float*)d_in[1];
    const float* pv    = (const float*)d_in[2];
    const float* w_qkv = (const float*)d_in[3];
    const float* b_qkv = (const float*)d_in[4];
    const float* w_k   = (const float*)d_in[5];
    const float* b_k   = (const float*)d_in[6];
    const float* w_v   = (const float*)d_in[7];
    const float* b_v   = (const float*)d_in[8];
    const float* w_o   = (const float*)d_in[9];
    const float* b_o   = (const float*)d_in[10];

    float* out  = (float*)d_out;
    float* kcol = out + (size_t)Bc * Sc * Dc;
    float* vcol = kcol + (size_t)Bc * Hc * Sc * HDc;

    static float *qkvp = nullptr, *ctxp = nullptr;
    static __nv_bfloat16 *Ah, *Al, *Wqh, *Wql, *Wkh, *Wkl, *Wvh, *Wvl, *Woh, *Wol;
    static bool inited = false;
    if (!inited) {
        inited = true;
        cudaGetSymbolAddress((void**)&qkvp, g_qkv);
        cudaGetSymbolAddress((void**)&ctxp, g_ctx);
        cudaGetSymbolAddress((void**)&Ah, g_Ah);
        cudaGetSymbolAddress((void**)&Al, g_Al);
        cudaGetSymbolAddress((void**)&Wqh, g_Wqh);
        cudaGetSymbolAddress((void**)&Wql, g_Wql);
        cudaGetSymbolAddress((void**)&Wkh, g_Wkh);
        cudaGetSymbolAddress((void**)&Wkl, g_Wkl);
        cudaGetSymbolAddress((void**)&Wvh, g_Wvh);
        cudaGetSymbolAddress((void**)&Wvl, g_Wvl);
        cudaGetSymbolAddress((void**)&Woh, g_Woh);
        cudaGetSymbolAddress((void**)&Wol, g_Wol);
        cudaFuncSetAttribute(gemm_bf16x3<false>,
                             cudaFuncAttributeMaxDynamicSharedMemorySize, GEMM_SMEM);
        cudaFuncSetAttribute(gemm_bf16x3<true>,
                             cudaFuncAttributeMaxDynamicSharedMemorySize, GEMM_SMEM);
    }

    // --- operand conversions ---
    convert_hilo<<<(BS * Dc / 4 + 255) / 256, 256>>>(x, Ah, Al, BS * Dc / 4);
    convert_wT<<<dim3(3 * Dc / 32, Dc / 32), dim3(32, 8)>>>(w_qkv, Wqh, Wql, Dc, 3 * Dc);
    convert_wT<<<dim3(Dc / 32, Dc / 32), dim3(32, 8)>>>(w_k, Wkh, Wkl, Dc, Dc);
    convert_wT<<<dim3(Dc / 32, Dc / 32), dim3(32, 8)>>>(w_v, Wvh, Wvl, Dc, Dc);
    convert_wT<<<dim3(Dc / 32, Dc / 32), dim3(32, 8)>>>(w_o, Woh, Wol, Dc, Dc);

    // --- projections on tensor cores (HMMA) ---
    gemm_bf16x3<false><<<dim3(3 * Dc / 128, BS / 128), 256, GEMM_SMEM>>>(
        Ah, Al, Wqh, Wql, b_qkv, qkvp, BS, 3 * Dc, Dc);
    gemm_bf16x3<true><<<dim3(Dc / 128, BS / 128), 256, GEMM_SMEM>>>(
        Ah, Al, Wkh, Wkl, b_k, kcol, BS, Dc, Dc);
    gemm_bf16x3<true><<<dim3(Dc / 128, BS / 128), 256, GEMM_SMEM>>>(
        Ah, Al, Wvh, Wvl, b_v, vcol, BS, Dc, Dc);

    // --- attention ---
    attn_kernel<<<Bc * Hc * (Sc / 128), 128>>>(qkvp, pk, pv, ctxp);

    // --- output projection ---
    convert_hilo<<<(BS * Dc / 4 + 255) / 256, 256>>>(ctxp, Ah, Al, BS * Dc / 4);
    gemm_bf16x3<false><<<dim3(Dc / 128, BS / 128), 256, GEMM_SMEM>>>(
        Ah, Al, Woh, Wol, b_o, out, BS, Dc, Dc);
}

// round 4
// speedup vs baseline: 2.5690x; 1.6825x over previous
#include <cuda_runtime.h>
#include <cuda_bf16.h>
#include <cstdint>
#include <math.h>

// Problem constants
static constexpr int Bc  = 4;
static constexpr int Sc  = 1024;
static constexpr int Dc  = 1024;
static constexpr int Hc  = 16;
static constexpr int HDc = 64;
static constexpr int Lc  = 12;
static constexpr int BS  = Bc * Sc;       // 4096 rows

// ---------------------------------------------------------------------------
// Scratch (__device__ globals; no cudaMalloc allowed)
// ---------------------------------------------------------------------------
__device__ float g_qkv[(size_t)BS * 3 * Dc];   // 4096 x 3072
__device__ float g_ctx[(size_t)BS * Dc];       // 4096 x 1024
__device__ __nv_bfloat16 g_Ah[(size_t)BS * Dc];          // A hi (x, later ctx)
__device__ __nv_bfloat16 g_Al[(size_t)BS * Dc];          // A lo
__device__ __nv_bfloat16 g_QKVh[(size_t)BS * 3 * Dc];    // qkv hi (for attn)
__device__ __nv_bfloat16 g_QKVl[(size_t)BS * 3 * Dc];    // qkv lo
__device__ __nv_bfloat16 g_Wqh[(size_t)3 * Dc * Dc];     // w_qkv^T hi  [N,K]
__device__ __nv_bfloat16 g_Wql[(size_t)3 * Dc * Dc];
__device__ __nv_bfloat16 g_Wkh[(size_t)Dc * Dc];
__device__ __nv_bfloat16 g_Wkl[(size_t)Dc * Dc];
__device__ __nv_bfloat16 g_Wvh[(size_t)Dc * Dc];
__device__ __nv_bfloat16 g_Wvl[(size_t)Dc * Dc];
__device__ __nv_bfloat16 g_Woh[(size_t)Dc * Dc];
__device__ __nv_bfloat16 g_Wol[(size_t)Dc * Dc];

// ---------------------------------------------------------------------------
// PTX helpers (base-PTX only: cp.async / ldmatrix / mma.sync)
// ---------------------------------------------------------------------------
__device__ __forceinline__ uint32_t smem_u32(const void* p) {
    uint32_t a;
    asm("{ .reg .u64 t; cvta.to.shared.u64 t, %1; cvt.u32.u64 %0, t; }"
        : "=r"(a) : "l"(p));
    return a;
}

__device__ __forceinline__ void cp16(uint32_t saddr, const void* gaddr) {
    asm volatile("cp.async.cg.shared.global [%0], [%1], 16;"
                 :: "r"(saddr), "l"(gaddr));
}
#define CP_COMMIT() asm volatile("cp.async.commit_group;" ::: "memory")
#define CP_WAIT(n)  asm volatile("cp.async.wait_group %0;" :: "n"(n) : "memory")

#define LDSM_X4(r0, r1, r2, r3, addr) \
    asm volatile("ldmatrix.sync.aligned.m8n8.x4.shared.b16 {%0,%1,%2,%3}, [%4];" \
                 : "=r"(r0), "=r"(r1), "=r"(r2), "=r"(r3) : "r"(addr))

#define LDSM_X4_T(r0, r1, r2, r3, addr) \
    asm volatile("ldmatrix.sync.aligned.m8n8.x4.trans.shared.b16 {%0,%1,%2,%3}, [%4];" \
                 : "=r"(r0), "=r"(r1), "=r"(r2), "=r"(r3) : "r"(addr))

#define MMA16816(d, a0, a1, a2, a3, b0, b1) \
    asm volatile("mma.sync.aligned.m16n8k16.row.col.f32.bf16.bf16.f32 " \
                 "{%0,%1,%2,%3}, {%4,%5,%6,%7}, {%8,%9}, {%0,%1,%2,%3};" \
                 : "+f"((d)[0]), "+f"((d)[1]), "+f"((d)[2]), "+f"((d)[3]) \
                 : "r"(a0), "r"(a1), "r"(a2), "r"(a3), "r"(b0), "r"(b1))

// split a pair of fp32 into hi/lo bf16x2 regs
__device__ __forceinline__ void split2(float a, float b, uint32_t& h, uint32_t& l) {
    __nv_bfloat162 hh = __floats2bfloat162_rn(a, b);
    float2 hf = __bfloat1622float2(hh);
    __nv_bfloat162 ll = __floats2bfloat162_rn(a - hf.x, b - hf.y);
    h = *reinterpret_cast<uint32_t*>(&hh);
    l = *reinterpret_cast<uint32_t*>(&ll);
}

// ---------------------------------------------------------------------------
// fp32 -> (hi, lo) bf16 split, elementwise
// ---------------------------------------------------------------------------
__global__ __launch_bounds__(256)
void convert_hilo(const float* __restrict__ src, __nv_bfloat16* __restrict__ h,
                  __nv_bfloat16* __restrict__ l, int n4)
{
    int i = blockIdx.x * blockDim.x + threadIdx.x;
    if (i >= n4) return;
    float4 v = reinterpret_cast<const float4*>(src)[i];
    __nv_bfloat162 h01 = __floats2bfloat162_rn(v.x, v.y);
    __nv_bfloat162 h23 = __floats2bfloat162_rn(v.z, v.w);
    float2 f01 = __bfloat1622float2(h01);
    float2 f23 = __bfloat1622float2(h23);
    __nv_bfloat162 l01 = __floats2bfloat162_rn(v.x - f01.x, v.y - f01.y);
    __nv_bfloat162 l23 = __floats2bfloat162_rn(v.z - f23.x, v.w - f23.y);
    reinterpret_cast<__nv_bfloat162*>(h)[2 * i + 0] = h01;
    reinterpret_cast<__nv_bfloat162*>(h)[2 * i + 1] = h23;
    reinterpret_cast<__nv_bfloat162*>(l)[2 * i + 0] = l01;
    reinterpret_cast<__nv_bfloat162*>(l)[2 * i + 1] = l23;
}

// ---------------------------------------------------------------------------
// W[K,N] fp32 -> Wt[N,K] (hi, lo) bf16 (transpose + split)
// ---------------------------------------------------------------------------
__global__ __launch_bounds__(256)
void convert_wT(const float* __restrict__ W, __nv_bfloat16* __restrict__ Th,
                __nv_bfloat16* __restrict__ Tl, int K, int N)
{
    __shared__ float t[32][33];
    int n0 = blockIdx.x * 32, k0 = blockIdx.y * 32;
    int tx = threadIdx.x, ty = threadIdx.y;   // (32, 8)
#pragma unroll
    for (int i = 0; i < 4; i++)
        t[ty + i * 8][tx] = W[(size_t)(k0 + ty + i * 8) * N + n0 + tx];
    __syncthreads();
#pragma unroll
    for (int i = 0; i < 4; i++) {
        int n = n0 + ty + i * 8;
        float v = t[tx][ty + i * 8];
        __nv_bfloat16 h = __float2bfloat16(v);
        Th[(size_t)n * K + k0 + tx] = h;
        Tl[(size_t)n * K + k0 + tx] = __float2bfloat16(v - __bfloat162float(h));
    }
}

// ---------------------------------------------------------------------------
// bf16x3 HMMA GEMM (unchanged from R3, passing)
// ---------------------------------------------------------------------------
static constexpr int LDS_ROW = 80;
static constexpr int TILE_B  = 128 * LDS_ROW;
static constexpr int STAGE_B = 4 * TILE_B;
static constexpr int GEMM_SMEM = 2 * STAGE_B;

template<bool SPLITHEAD>
__global__ __launch_bounds__(256)
void gemm_bf16x3(const __nv_bfloat16* __restrict__ Ah, const __nv_bfloat16* __restrict__ Al,
                 const __nv_bfloat16* __restrict__ Bh, const __nv_bfloat16* __restrict__ Bl,
                 const float* __restrict__ bias, float* __restrict__ C,
                 int M, int N, int K)
{
    extern __shared__ char smem[];
    const uint32_t sb = smem_u32(smem);
    const int tid  = threadIdx.x;
    const int wid  = tid >> 5, lid = tid & 31;
    const int wm   = wid >> 1, wn = wid & 1;
    const int m0   = blockIdx.y * 128, n0 = blockIdx.x * 128;

    const __nv_bfloat16* srcs[4] = {
        Ah + (size_t)m0 * K, Al + (size_t)m0 * K,
        Bh + (size_t)n0 * K, Bl + (size_t)n0 * K };

    const int f0 = tid, f1 = tid + 256;
    const int r0 = f0 >> 2, c0 = f0 & 3;
    const int r1 = f1 >> 2, c1 = f1 & 3;

    auto load_stage = [&](int kc, int buf) {
        const uint32_t base = sb + buf * STAGE_B;
#pragma unroll
        for (int t = 0; t < 4; t++) {
            const __nv_bfloat16* s = srcs[t] + kc * 32;
            cp16(base + t * TILE_B + r0 * LDS_ROW + c0 * 16,
                 s + (size_t)r0 * K + c0 * 8);
            cp16(base + t * TILE_B + r1 * LDS_ROW + c1 * 16,
                 s + (size_t)r1 * K + c1 * 8);
        }
    };

    float acc[2][8][4];
#pragma unroll
    for (int i = 0; i < 2; i++)
#pragma unroll
        for (int j = 0; j < 8; j++)
#pragma unroll
            for (int v = 0; v < 4; v++) acc[i][j][v] = 0.f;

    const int lr = lid & 15;
    const int lh = (lid >> 4) << 4;

    const int nk = K >> 5;
    load_stage(0, 0);
    CP_COMMIT();

    for (int kc = 0; kc < nk; kc++) {
        const int buf = kc & 1;
        if (kc + 1 < nk) { load_stage(kc + 1, buf ^ 1); CP_COMMIT(); CP_WAIT(1); }
        else             { CP_WAIT(0); }
        __syncthreads();

        const uint32_t base = sb + buf * STAGE_B;
        const uint32_t aHb = base +              (wm * 32 + lr) * LDS_ROW + lh;
        const uint32_t aLb = base + 1 * TILE_B + (wm * 32 + lr) * LDS_ROW + lh;
        const uint32_t bHb = base + 2 * TILE_B + (wn * 64 + lr) * LDS_ROW + lh;
        const uint32_t bLb = base + 3 * TILE_B + (wn * 64 + lr) * LDS_ROW + lh;

#pragma unroll
        for (int ks = 0; ks < 2; ks++) {
            const uint32_t ko = ks * 32;
            uint32_t ah[2][4], al[2][4];
#pragma unroll
            for (int mi = 0; mi < 2; mi++) {
                LDSM_X4(ah[mi][0], ah[mi][1], ah[mi][2], ah[mi][3],
                        aHb + mi * 16 * LDS_ROW + ko);
                LDSM_X4(al[mi][0], al[mi][1], al[mi][2], al[mi][3],
                        aLb + mi * 16 * LDS_ROW + ko);
            }
            uint32_t bh[8][2], bl[8][2];
#pragma unroll
            for (int np = 0; np < 4; np++) {
                uint32_t t0, t1, t2, t3;
                LDSM_X4(t0, t1, t2, t3, bHb + np * 16 * LDS_ROW + ko);
                bh[np * 2][0] = t0; bh[np * 2][1] = t2;
                bh[np * 2 + 1][0] = t1; bh[np * 2 + 1][1] = t3;
                LDSM_X4(t0, t1, t2, t3, bLb + np * 16 * LDS_ROW + ko);
                bl[np * 2][0] = t0; bl[np * 2][1] = t2;
                bl[np * 2 + 1][0] = t1; bl[np * 2 + 1][1] = t3;
            }
#pragma unroll
            for (int mi = 0; mi < 2; mi++)
#pragma unroll
                for (int nj = 0; nj < 8; nj++) {
                    MMA16816(acc[mi][nj], ah[mi][0], ah[mi][1], ah[mi][2], ah[mi][3],
                             bh[nj][0], bh[nj][1]);
                    MMA16816(acc[mi][nj], ah[mi][0], ah[mi][1], ah[mi][2], ah[mi][3],
                             bl[nj][0], bl[nj][1]);
                    MMA16816(acc[mi][nj], al[mi][0], al[mi][1], al[mi][2], al[mi][3],
                             bh[nj][0], bh[nj][1]);
                }
        }
        __syncthreads();
    }

#pragma unroll
    for (int mi = 0; mi < 2; mi++) {
#pragma unroll
        for (int nj = 0; nj < 8; nj++) {
            const int col = n0 + wn * 64 + nj * 8 + (lid & 3) * 2;
            const float2 bv = *reinterpret_cast<const float2*>(bias + col);
#pragma unroll
            for (int half = 0; half < 2; half++) {
                const int row = m0 + wm * 32 + mi * 16 + (lid >> 2) + half * 8;
                float2 o;
                o.x = acc[mi][nj][half * 2 + 0] + bv.x;
                o.y = acc[mi][nj][half * 2 + 1] + bv.y;
                if (!SPLITHEAD) {
                    *reinterpret_cast<float2*>(&C[(size_t)row * N + col]) = o;
                } else {
                    int b = row >> 10, s = row & 1023, h = col >> 6, d = col & 63;
                    *reinterpret_cast<float2*>(
                        &C[(size_t)(((b * Hc + h) * Sc) + s) * HDc + d]) = o;
                }
            }
        }
    }
}

// ---------------------------------------------------------------------------
// HMMA flash attention (bf16x3): causal token attn on tensor cores,
// then exact fp32 memory-slot phase with smem-staged unnormalized O.
// Block = (b, h, 128-row q tile); 8 warps x 16 rows.
// ---------------------------------------------------------------------------
static constexpr int ROWB = 144;                     // 64 bf16 + 16B pad
static constexpr int QREG = 2 * 128 * ROWB;          // Q hi/lo staging: 36864
static constexpr int KSTG = 4 * 64 * ROWB;           // Kh,Kl,Vh,Vl per stage: 36864
static constexpr int ATTN_SMEM = QREG + 2 * KSTG;    // 110592

__global__ __launch_bounds__(256)
void attn_mma(const float* __restrict__ qkv,
              const __nv_bfloat16* __restrict__ qh_g,
              const __nv_bfloat16* __restrict__ ql_g,
              const float* __restrict__ pk, const float* __restrict__ pv,
              float* __restrict__ ctx)
{
    extern __shared__ char sm[];
    const uint32_t sb = smem_u32(sm);
    const int bid  = blockIdx.x;
    const int tile = 7 - (bid >> 6);          // heavy tiles first
    const int h    = bid & 15;
    const int b    = (bid >> 4) & 3;
    const int tid  = threadIdx.x;
    const int wid  = tid >> 5, lid = tid & 31;

    const size_t qkv_row0 = (size_t)(b * Sc + tile * 128) * 3072;

    // ---- stage Q hi/lo (128 rows x 64 bf16 each) ----
#pragma unroll
    for (int i = 0; i < 8; i++) {
        int c = tid + i * 256;                // 0..2047
        int half = c >> 10;                   // 0 = hi, 1 = lo
        int rem = c & 1023;
        int r = rem >> 3, o = (rem & 7) * 16; // byte offset in row
        const __nv_bfloat16* src =
            (half ? ql_g : qh_g) + qkv_row0 + (size_t)r * 3072 + h * 64 + o / 2;
        cp16(sb + half * (128 * ROWB) + r * ROWB + o, src);
    }
    CP_COMMIT();

    const int nkt = 2 * tile + 2;
    // ---- stage loader for K/V tile kt ----
    auto load_stage = [&](int kt, int buf) {
        const uint32_t st = sb + QREG + buf * KSTG;
        const size_t row0 = (size_t)(b * Sc + kt * 64) * 3072;
#pragma unroll
        for (int i = 0; i < 8; i++) {
            int c = tid + i * 256;            // 0..2047
            int arr = c >> 9;                 // 0:Kh 1:Kl 2:Vh 3:Vl
            int rem = c & 511;
            int r = rem >> 3, o = (rem & 7) * 16;
            const __nv_bfloat16* base = (arr & 1) ? ql_g : qh_g;
            int colb = (arr < 2) ? 1024 : 2048;
            cp16(st + arr * (64 * ROWB) + r * ROWB + o,
                 base + row0 + (size_t)r * 3072 + colb + h * 64 + o / 2);
        }
    };
    load_stage(0, 0);
    CP_COMMIT();

    // ---- load Q fragments (need Q group done; stage0 may still be pending) ----
    CP_WAIT(1);
    __syncthreads();
    uint32_t qfh[16], qfl[16];
    {
        const uint32_t qbase = sb + (wid * 16 + (lid & 15)) * ROWB + ((lid >> 4) << 4);
#pragma unroll
        for (int kc = 0; kc < 4; kc++) {
            LDSM_X4(qfh[kc * 4 + 0], qfh[kc * 4 + 1], qfh[kc * 4 + 2], qfh[kc * 4 + 3],
                    qbase + kc * 32);
            LDSM_X4(qfl[kc * 4 + 0], qfl[kc * 4 + 1], qfl[kc * 4 + 2], qfl[kc * 4 + 3],
                    qbase + 128 * ROWB + kc * 32);
        }
    }
    __syncthreads();   // everyone done reading Q region before O reuses it later

    float o_acc[8][4];
#pragma unroll
    for (int j = 0; j < 8; j++)
#pragma unroll
        for (int v = 0; v < 4; v++) o_acc[j][v] = 0.f;
    float m0 = -1e30f, m1 = -1e30f, sr0 = 0.f, sr1 = 0.f;

    const int rA = tile * 128 + wid * 16 + (lid >> 2);   // global q row (lo)
    const int diag = 2 * tile;

    for (int kt = 0; kt < nkt; kt++) {
        const int buf = kt & 1;
        if (kt + 1 < nkt) { load_stage(kt + 1, buf ^ 1); CP_COMMIT(); CP_WAIT(1); }
        else              { CP_WAIT(0); }
        __syncthreads();

        const uint32_t st = sb + QREG + buf * KSTG;
        const uint32_t Kh = st, Kl = st + 64 * ROWB;
        const uint32_t Vh = st + 2 * 64 * ROWB, Vl = st + 3 * 64 * ROWB;

        // ---- S = Q K^T (x3) ----
        float s[8][4];
#pragma unroll
        for (int j = 0; j < 8; j++)
#pragma unroll
            for (int v = 0; v < 4; v++) s[j][v] = 0.f;

#pragma unroll
        for (int np = 0; np < 4; np++) {
            const uint32_t krow = (np * 16 + ((lid >> 4) & 1) * 8 + (lid & 7)) * ROWB
                                + ((lid >> 3) & 1) * 16;
#pragma unroll
            for (int kc = 0; kc < 4; kc++) {
                uint32_t kh0, kh1, kh2, kh3, kl0, kl1, kl2, kl3;
                LDSM_X4(kh0, kh1, kh2, kh3, Kh + krow + kc * 32);
                LDSM_X4(kl0, kl1, kl2, kl3, Kl + krow + kc * 32);
                const uint32_t* qa = qfh + kc * 4;
                const uint32_t* qb = qfl + kc * 4;
                MMA16816(s[2 * np],     qa[0], qa[1], qa[2], qa[3], kh0, kh1);
                MMA16816(s[2 * np],     qb[0], qb[1], qb[2], qb[3], kh0, kh1);
                MMA16816(s[2 * np],     qa[0], qa[1], qa[2], qa[3], kl0, kl1);
                MMA16816(s[2 * np + 1], qa[0], qa[1], qa[2], qa[3], kh2, kh3);
                MMA16816(s[2 * np + 1], qb[0], qb[1], qb[2], qb[3], kh2, kh3);
                MMA16816(s[2 * np + 1], qa[0], qa[1], qa[2], qa[3], kl2, kl3);
            }
        }

        // ---- scale + causal mask ----
#pragma unroll
        for (int j = 0; j < 8; j++)
#pragma unroll
            for (int v = 0; v < 4; v++) s[j][v] *= 0.125f;
        if (kt >= diag) {
#pragma unroll
            for (int j = 0; j < 8; j++) {
                int c0 = kt * 64 + j * 8 + (lid & 3) * 2;
                if (c0     > rA)     s[j][0] = -1e30f;
                if (c0 + 1 > rA)     s[j][1] = -1e30f;
                if (c0     > rA + 8) s[j][2] = -1e30f;
                if (c0 + 1 > rA + 8) s[j][3] = -1e30f;
            }
        }

        // ---- online softmax ----
        float mx0 = -1e30f, mx1 = -1e30f;
#pragma unroll
        for (int j = 0; j < 8; j++) {
            mx0 = fmaxf(mx0, fmaxf(s[j][0], s[j][1]));
            mx1 = fmaxf(mx1, fmaxf(s[j][2], s[j][3]));
        }
        mx0 = fmaxf(mx0, __shfl_xor_sync(0xffffffffu, mx0, 1));
        mx0 = fmaxf(mx0, __shfl_xor_sync(0xffffffffu, mx0, 2));
        mx1 = fmaxf(mx1, __shfl_xor_sync(0xffffffffu, mx1, 1));
        mx1 = fmaxf(mx1, __shfl_xor_sync(0xffffffffu, mx1, 2));
        const float mn0 = fmaxf(m0, mx0), mn1 = fmaxf(m1, mx1);
        const float cr0 = __expf(m0 - mn0), cr1 = __expf(m1 - mn1);
        m0 = mn0; m1 = mn1;
        float ps0 = 0.f, ps1 = 0.f;
#pragma unroll
        for (int j = 0; j < 8; j++) {
            s[j][0] = __expf(s[j][0] - m0); ps0 += s[j][0];
            s[j][1] = __expf(s[j][1] - m0); ps0 += s[j][1];
            s[j][2] = __expf(s[j][2] - m1); ps1 += s[j][2];
            s[j][3] = __expf(s[j][3] - m1); ps1 += s[j][3];
        }
        ps0 += __shfl_xor_sync(0xffffffffu, ps0, 1);
        ps0 += __shfl_xor_sync(0xffffffffu, ps0, 2);
        ps1 += __shfl_xor_sync(0xffffffffu, ps1, 1);
        ps1 += __shfl_xor_sync(0xffffffffu, ps1, 2);
        sr0 = sr0 * cr0 + ps0;
        sr1 = sr1 * cr1 + ps1;
#pragma unroll
        for (int j = 0; j < 8; j++) {
            o_acc[j][0] *= cr0; o_acc[j][1] *= cr0;
            o_acc[j][2] *= cr1; o_acc[j][3] *= cr1;
        }

        // ---- O += P V (x3) ----
#pragma unroll
        for (int kc = 0; kc < 4; kc++) {
            uint32_t ph[4], pl[4];
            split2(s[2 * kc][0],     s[2 * kc][1],     ph[0], pl[0]);
            split2(s[2 * kc][2],     s[2 * kc][3],     ph[1], pl[1]);
            split2(s[2 * kc + 1][0], s[2 * kc + 1][1], ph[2], pl[2]);
            split2(s[2 * kc + 1][2], s[2 * kc + 1][3], ph[3], pl[3]);
            const uint32_t vrow = (kc * 16 + ((lid >> 3) & 1) * 8 + (lid & 7)) * ROWB
                                + ((lid >> 4) & 1) * 16;
#pragma unroll
            for (int np = 0; np < 4; np++) {
                uint32_t vh0, vh1, vh2, vh3, vl0, vl1, vl2, vl3;
                LDSM_X4_T(vh0, vh1, vh2, vh3, Vh + vrow + np * 32);
                LDSM_X4_T(vl0, vl1, vl2, vl3, Vl + vrow + np * 32);
                MMA16816(o_acc[2 * np],     ph[0], ph[1], ph[2], ph[3], vh0, vh1);
                MMA16816(o_acc[2 * np],     pl[0], pl[1], pl[2], pl[3], vh0, vh1);
                MMA16816(o_acc[2 * np],     ph[0], ph[1], ph[2], ph[3], vl0, vl1);
                MMA16816(o_acc[2 * np + 1], ph[0], ph[1], ph[2], ph[3], vh2, vh3);
                MMA16816(o_acc[2 * np + 1], pl[0], pl[1], pl[2], pl[3], vh2, vh3);
                MMA16816(o_acc[2 * np + 1], ph[0], ph[1], ph[2], ph[3], vl2, vl3);
            }
        }
        __syncthreads();
    }

    // ---- stage unnormalized O + stats to smem (reuses Q region) ----
    float* Os = reinterpret_cast<float*>(sm);           // [128][66]
    float* Ms = reinterpret_cast<float*>(sm + 33792);   // [128]
    float* Ss = Ms + 128;                               // [128]
    {
        const int ra = wid * 16 + (lid >> 2), rb = ra + 8;
#pragma unroll
        for (int j = 0; j < 8; j++) {
            const int col = j * 8 + (lid & 3) * 2;
            Os[ra * 66 + col]     = o_acc[j][0];
            Os[ra * 66 + col + 1] = o_acc[j][1];
            Os[rb * 66 + col]     = o_acc[j][2];
            Os[rb * 66 + col + 1] = o_acc[j][3];
        }
        if ((lid & 3) == 0) {
            Ms[ra] = m0; Ms[rb] = m1;
            Ss[ra] = sr0; Ss[rb] = sr1;
        }
    }
    __syncthreads();

    // ---- exact fp32 memory-slot phase: 2 threads per row ----
    {
        const int row = tid >> 1, half = tid & 1;
        const int rg = tile * 128 + row;
        float q[32];
        {
            const float* qp = qkv + (size_t)(b * Sc + rg) * 3072 + h * 64 + half * 32;
#pragma unroll
            for (int i = 0; i < 8; i++) {
                float4 v = *reinterpret_cast<const float4*>(qp + i * 4);
                q[i * 4 + 0] = v.x * 0.125f;
                q[i * 4 + 1] = v.y * 0.125f;
                q[i * 4 + 2] = v.z * 0.125f;
                q[i * 4 + 3] = v.w * 0.125f;
            }
        }
        float m = Ms[row], sr = Ss[row];
        float acc[32];
#pragma unroll
        for (int i = 0; i < 32; i++) acc[i] = Os[row * 66 + half * 32 + i];

        const size_t pbase = ((size_t)((b * Hc + h) * Sc + rg)) * (Lc * HDc) + half * 32;
        const float* pkb = pk + pbase;
        const float* pvb = pv + pbase;
#pragma unroll 1
        for (int l = 0; l < Lc; l++) {
            float d0 = 0.f;
#pragma unroll
            for (int i = 0; i < 8; i++) {
                float4 kk = *reinterpret_cast<const float4*>(pkb + l * 64 + i * 4);
                d0 = fmaf(q[i * 4 + 0], kk.x, d0);
                d0 = fmaf(q[i * 4 + 1], kk.y, d0);
                d0 = fmaf(q[i * 4 + 2], kk.z, d0);
                d0 = fmaf(q[i * 4 + 3], kk.w, d0);
            }
            d0 += __shfl_xor_sync(0xffffffffu, d0, 1);   // partner half
            float mn = fmaxf(m, d0);
            float cr = __expf(m - mn);
            float p = __expf(d0 - mn);
            m = mn;
            sr = sr * cr + p;
#pragma unroll
            for (int i = 0; i < 8; i++) {
                float4 vv = *reinterpret_cast<const float4*>(pvb + l * 64 + i * 4);
                acc[i * 4 + 0] = fmaf(cr, acc[i * 4 + 0] - acc[i * 4 + 0], acc[i * 4 + 0] * cr) + p * vv.x;
                acc[i * 4 + 1] = acc[i * 4 + 1] * cr + p * vv.y;
                acc[i * 4 + 2] = acc[i * 4 + 2] * cr + p * vv.z;
                acc[i * 4 + 3] = acc[i * 4 + 3] * cr + p * vv.w;
            }
            // fix first lane expression (keep simple mul-add form)
            acc[0] = acc[0];  // no-op
        }
        const float inv = 1.f / sr;
        float* cp = ctx + (size_t)(b * Sc + rg) * Dc + h * 64 + half * 32;
#pragma unroll
        for (int i = 0; i < 8; i++) {
            float4 o;
            o.x = acc[i * 4 + 0] * inv;
            o.y = acc[i * 4 + 1] * inv;
            o.z = acc[i * 4 + 2] * inv;
            o.w = acc[i * 4 + 3] * inv;
            *reinterpret_cast<float4*>(cp + i * 4) = o;
        }
    }
}

// ---------------------------------------------------------------------------
extern "C" void kernel_launch(void* const* d_in, const int* in_sizes, int n_in,
                              void* d_out, int out_size)
{
    const float* x     = (const float*)d_in[0];
    const float* pk    = (const float*)d_in[1];
    const float* pv    = (const float*)d_in[2];
    const float* w_qkv = (const float*)d_in[3];
    const float* b_qkv = (const float*)d_in[4];
    const float* w_k   = (const float*)d_in[5];
    const float* b_k   = (const float*)d_in[6];
    const float* w_v   = (const float*)d_in[7];
    const float* b_v   = (const float*)d_in[8];
    const float* w_o   = (const float*)d_in[9];
    const float* b_o   = (const float*)d_in[10];

    float* out  = (float*)d_out;
    float* kcol = out + (size_t)Bc * Sc * Dc;
    float* vcol = kcol + (size_t)Bc * Hc * Sc * HDc;

    static float *qkvp = nullptr, *ctxp = nullptr;
    static __nv_bfloat16 *Ah, *Al, *QKVh, *QKVl, *Wqh, *Wql, *Wkh, *Wkl, *Wvh, *Wvl, *Woh, *Wol;
    static bool inited = false;
    if (!inited) {
        inited = true;
        cudaGetSymbolAddress((void**)&qkvp, g_qkv);
        cudaGetSymbolAddress((void**)&ctxp, g_ctx);
        cudaGetSymbolAddress((void**)&Ah, g_Ah);
        cudaGetSymbolAddress((void**)&Al, g_Al);
        cudaGetSymbolAddress((void**)&QKVh, g_QKVh);
        cudaGetSymbolAddress((void**)&QKVl, g_QKVl);
        cudaGetSymbolAddress((void**)&Wqh, g_Wqh);
        cudaGetSymbolAddress((void**)&Wql, g_Wql);
        cudaGetSymbolAddress((void**)&Wkh, g_Wkh);
        cudaGetSymbolAddress((void**)&Wkl, g_Wkl);
        cudaGetSymbolAddress((void**)&Wvh, g_Wvh);
        cudaGetSymbolAddress((void**)&Wvl, g_Wvl);
        cudaGetSymbolAddress((void**)&Woh, g_Woh);
        cudaGetSymbolAddress((void**)&Wol, g_Wol);
        cudaFuncSetAttribute(gemm_bf16x3<false>,
                             cudaFuncAttributeMaxDynamicSharedMemorySize, GEMM_SMEM);
        cudaFuncSetAttribute(gemm_bf16x3<true>,
                             cudaFuncAttributeMaxDynamicSharedMemorySize, GEMM_SMEM);
        cudaFuncSetAttribute(attn_mma,
                             cudaFuncAttributeMaxDynamicSharedMemorySize, ATTN_SMEM);
    }

    // --- operand conversions ---
    convert_hilo<<<(BS * Dc / 4 + 255) / 256, 256>>>(x, Ah, Al, BS * Dc / 4);
    convert_wT<<<dim3(3 * Dc / 32, Dc / 32), dim3(32, 8)>>>(w_qkv, Wqh, Wql, Dc, 3 * Dc);
    convert_wT<<<dim3(Dc / 32, Dc / 32), dim3(32, 8)>>>(w_k, Wkh, Wkl, Dc, Dc);
    convert_wT<<<dim3(Dc / 32, Dc / 32), dim3(32, 8)>>>(w_v, Wvh, Wvl, Dc, Dc);
    convert_wT<<<dim3(Dc / 32, Dc / 32), dim3(32, 8)>>>(w_o, Woh, Wol, Dc, Dc);

    // --- projections on tensor cores (HMMA) ---
    gemm_bf16x3<false><<<dim3(3 * Dc / 128, BS / 128), 256, GEMM_SMEM>>>(
        Ah, Al, Wqh, Wql, b_qkv, qkvp, BS, 3 * Dc, Dc);
    gemm_bf16x3<true><<<dim3(Dc / 128, BS / 128), 256, GEMM_SMEM>>>(
        Ah, Al, Wkh, Wkl, b_k, kcol, BS, Dc, Dc);
    gemm_bf16x3<true><<<dim3(Dc / 128, BS / 128), 256, GEMM_SMEM>>>(
        Ah, Al, Wvh, Wvl, b_v, vcol, BS, Dc, Dc);

    // --- split qkv to bf16 hi/lo for attention MMA operands ---
    convert_hilo<<<(BS * 3 * Dc / 4 + 255) / 256, 256>>>(qkvp, QKVh, QKVl, BS * 3 * Dc / 4);

    // --- HMMA flash attention + exact memory-slot merge ---
    attn_mma<<<512, 256, ATTN_SMEM>>>(qkvp, QKVh, QKVl, pk, pv, ctxp);

    // --- output projection ---
    convert_hilo<<<(BS * Dc / 4 + 255) / 256, 256>>>(ctxp, Ah, Al, BS * Dc / 4);
    gemm_bf16x3<false><<<dim3(Dc / 128, BS / 128), 256, GEMM_SMEM>>>(
        Ah, Al, Woh, Wol, b_o, out, BS, Dc, Dc);
}

// round 5
// speedup vs baseline: 3.1076x; 1.2096x over previous
#include <cuda_runtime.h>
#include <cuda_bf16.h>
#include <cstdint>
#include <math.h>

// Problem constants
static constexpr int Bc  = 4;
static constexpr int Sc  = 1024;
static constexpr int Dc  = 1024;
static constexpr int Hc  = 16;
static constexpr int HDc = 64;
static constexpr int Lc  = 12;
static constexpr int BS  = Bc * Sc;       // 4096 rows

// ---------------------------------------------------------------------------
// Scratch (__device__ globals; no cudaMalloc allowed)
// ---------------------------------------------------------------------------
__device__ float g_qkv[(size_t)BS * 3 * Dc];   // 4096 x 3072
__device__ float g_ctx[(size_t)BS * Dc];       // 4096 x 1024
__device__ float g_Xt[(size_t)BS * Dc];        // tf32-rounded A (x, later ctx)
__device__ float g_WqT[(size_t)3 * Dc * Dc];   // w_qkv^T tf32 [N,K]
__device__ float g_WkT[(size_t)Dc * Dc];
__device__ float g_WvT[(size_t)Dc * Dc];
__device__ float g_WoT[(size_t)Dc * Dc];
__device__ __nv_bfloat16 g_QKVh[(size_t)BS * 3 * Dc];    // qkv hi (for attn)
__device__ __nv_bfloat16 g_QKVl[(size_t)BS * 3 * Dc];    // qkv lo

// ---------------------------------------------------------------------------
// PTX helpers (base-PTX only: cp.async / ldmatrix / mma.sync / cvt.tf32)
// ---------------------------------------------------------------------------
__device__ __forceinline__ uint32_t smem_u32(const void* p) {
    uint32_t a;
    asm("{ .reg .u64 t; cvta.to.shared.u64 t, %1; cvt.u32.u64 %0, t; }"
        : "=r"(a) : "l"(p));
    return a;
}

__device__ __forceinline__ void cp16(uint32_t saddr, const void* gaddr) {
    asm volatile("cp.async.cg.shared.global [%0], [%1], 16;"
                 :: "r"(saddr), "l"(gaddr));
}
#define CP_COMMIT() asm volatile("cp.async.commit_group;" ::: "memory")
#define CP_WAIT(n)  asm volatile("cp.async.wait_group %0;" :: "n"(n) : "memory")

#define LDSM_X4(r0, r1, r2, r3, addr) \
    asm volatile("ldmatrix.sync.aligned.m8n8.x4.shared.b16 {%0,%1,%2,%3}, [%4];" \
                 : "=r"(r0), "=r"(r1), "=r"(r2), "=r"(r3) : "r"(addr))

#define LDSM_X4_T(r0, r1, r2, r3, addr) \
    asm volatile("ldmatrix.sync.aligned.m8n8.x4.trans.shared.b16 {%0,%1,%2,%3}, [%4];" \
                 : "=r"(r0), "=r"(r1), "=r"(r2), "=r"(r3) : "r"(addr))

#define MMA16816(d, a0, a1, a2, a3, b0, b1) \
    asm volatile("mma.sync.aligned.m16n8k16.row.col.f32.bf16.bf16.f32 " \
                 "{%0,%1,%2,%3}, {%4,%5,%6,%7}, {%8,%9}, {%0,%1,%2,%3};" \
                 : "+f"((d)[0]), "+f"((d)[1]), "+f"((d)[2]), "+f"((d)[3]) \
                 : "r"(a0), "r"(a1), "r"(a2), "r"(a3), "r"(b0), "r"(b1))

#define MMATF32(d, a0, a1, a2, a3, b0, b1) \
    asm volatile("mma.sync.aligned.m16n8k8.row.col.f32.tf32.tf32.f32 " \
                 "{%0,%1,%2,%3}, {%4,%5,%6,%7}, {%8,%9}, {%0,%1,%2,%3};" \
                 : "+f"((d)[0]), "+f"((d)[1]), "+f"((d)[2]), "+f"((d)[3]) \
                 : "r"(a0), "r"(a1), "r"(a2), "r"(a3), "r"(b0), "r"(b1))

__device__ __forceinline__ float tf32r(float x) {
    uint32_t o;
    asm("cvt.rna.tf32.f32 %0, %1;" : "=r"(o) : "f"(x));
    return __uint_as_float(o);
}

// split a pair of fp32 into hi/lo bf16x2 regs
__device__ __forceinline__ void split2(float a, float b, uint32_t& h, uint32_t& l) {
    __nv_bfloat162 hh = __floats2bfloat162_rn(a, b);
    float2 hf = __bfloat1622float2(hh);
    __nv_bfloat162 ll = __floats2bfloat162_rn(a - hf.x, b - hf.y);
    h = *reinterpret_cast<uint32_t*>(&hh);
    l = *reinterpret_cast<uint32_t*>(&ll);
}

// ---------------------------------------------------------------------------
// fp32 -> (hi, lo) bf16 split, elementwise (attention operands)
// ---------------------------------------------------------------------------
__global__ __launch_bounds__(256)
void convert_hilo(const float* __restrict__ src, __nv_bfloat16* __restrict__ h,
                  __nv_bfloat16* __restrict__ l, int n4)
{
    int i = blockIdx.x * blockDim.x + threadIdx.x;
    if (i >= n4) return;
    float4 v = reinterpret_cast<const float4*>(src)[i];
    __nv_bfloat162 h01 = __floats2bfloat162_rn(v.x, v.y);
    __nv_bfloat162 h23 = __floats2bfloat162_rn(v.z, v.w);
    float2 f01 = __bfloat1622float2(h01);
    float2 f23 = __bfloat1622float2(h23);
    __nv_bfloat162 l01 = __floats2bfloat162_rn(v.x - f01.x, v.y - f01.y);
    __nv_bfloat162 l23 = __floats2bfloat162_rn(v.z - f23.x, v.w - f23.y);
    reinterpret_cast<__nv_bfloat162*>(h)[2 * i + 0] = h01;
    reinterpret_cast<__nv_bfloat162*>(h)[2 * i + 1] = h23;
    reinterpret_cast<__nv_bfloat162*>(l)[2 * i + 0] = l01;
    reinterpret_cast<__nv_bfloat162*>(l)[2 * i + 1] = l23;
}

// ---------------------------------------------------------------------------
// fp32 -> tf32-rounded fp32, elementwise
// ---------------------------------------------------------------------------
__global__ __launch_bounds__(256)
void convert_tf32(const float* __restrict__ src, float* __restrict__ dst, int n4)
{
    int i = blockIdx.x * blockDim.x + threadIdx.x;
    if (i >= n4) return;
    float4 v = reinterpret_cast<const float4*>(src)[i];
    v.x = tf32r(v.x); v.y = tf32r(v.y); v.z = tf32r(v.z); v.w = tf32r(v.w);
    reinterpret_cast<float4*>(dst)[i] = v;
}

// ---------------------------------------------------------------------------
// W[K,N] fp32 -> Wt[N,K] tf32-rounded fp32 (transpose + round)
// ---------------------------------------------------------------------------
__global__ __launch_bounds__(256)
void convert_wT_tf32(const float* __restrict__ W, float* __restrict__ T, int K, int N)
{
    __shared__ float t[32][33];
    int n0 = blockIdx.x * 32, k0 = blockIdx.y * 32;
    int tx = threadIdx.x, ty = threadIdx.y;   // (32, 8)
#pragma unroll
    for (int i = 0; i < 4; i++)
        t[ty + i * 8][tx] = W[(size_t)(k0 + ty + i * 8) * N + n0 + tx];
    __syncthreads();
#pragma unroll
    for (int i = 0; i < 4; i++) {
        int n = n0 + ty + i * 8;
        T[(size_t)n * K + k0 + tx] = tf32r(t[tx][ty + i * 8]);
    }
}

// ---------------------------------------------------------------------------
// tf32 HMMA GEMM:  C[M,N] = A @ B^T + bias  (A [M,K], B [N,K], pre-rounded)
//   Tile 128x128x32, 8 warps (4m x 2n), warp tile 32x64, cp.async dbl-buffer.
//   Smem rows padded to 36 floats: all fragment LDS are bank-conflict-free.
// ---------------------------------------------------------------------------
static constexpr int TFROW   = 36;                    // floats per smem row
static constexpr int TTILE   = 128 * TFROW * 4;       // 18432 B per operand
static constexpr int TSTAGE  = 2 * TTILE;             // A + B = 36864
static constexpr int TGEMM_SMEM = 2 * TSTAGE;         // 73728

template<bool SPLITHEAD>
__global__ __launch_bounds__(256)
void gemm_tf32(const float* __restrict__ A, const float* __restrict__ B,
               const float* __restrict__ bias, float* __restrict__ C,
               int M, int N, int K)
{
    extern __shared__ char smem[];
    const uint32_t sb = smem_u32(smem);
    const int tid  = threadIdx.x;
    const int wid  = tid >> 5, lid = tid & 31;
    const int wm   = wid >> 1, wn = wid & 1;
    const int m0   = blockIdx.y * 128, n0 = blockIdx.x * 128;

    const float* Ab = A + (size_t)m0 * K;
    const float* Bb = B + (size_t)n0 * K;

    auto load_stage = [&](int kc, int buf) {
        const uint32_t base = sb + buf * TSTAGE;
#pragma unroll
        for (int i = 0; i < 8; i++) {
            int c = tid + i * 256;              // 0..2047 16B chunks
            int op = c >> 10;                   // 0=A 1=B
            int rem = c & 1023;
            int r = rem >> 3, q = rem & 7;
            const float* s = (op ? Bb : Ab) + (size_t)r * K + kc * 32 + q * 4;
            cp16(base + op * TTILE + (r * TFROW + q * 4) * 4, s);
        }
    };

    float acc[2][8][4];
#pragma unroll
    for (int i = 0; i < 2; i++)
#pragma unroll
        for (int j = 0; j < 8; j++)
#pragma unroll
            for (int v = 0; v < 4; v++) acc[i][j][v] = 0.f;

    const int gr = lid >> 2, gc = lid & 3;

    const int nk = K >> 5;
    load_stage(0, 0);
    CP_COMMIT();

    for (int kc = 0; kc < nk; kc++) {
        const int buf = kc & 1;
        if (kc + 1 < nk) { load_stage(kc + 1, buf ^ 1); CP_COMMIT(); CP_WAIT(1); }
        else             { CP_WAIT(0); }
        __syncthreads();

        const float* As = reinterpret_cast<const float*>(smem + buf * TSTAGE);
        const float* Bs = reinterpret_cast<const float*>(smem + buf * TSTAGE + TTILE);

#pragma unroll
        for (int ks = 0; ks < 4; ks++) {
            const int k0 = ks * 8;
            uint32_t a[2][4];
#pragma unroll
            for (int mi = 0; mi < 2; mi++) {
                const int row = wm * 32 + mi * 16 + gr;
                a[mi][0] = __float_as_uint(As[row * TFROW + k0 + gc]);
                a[mi][1] = __float_as_uint(As[(row + 8) * TFROW + k0 + gc]);
                a[mi][2] = __float_as_uint(As[row * TFROW + k0 + gc + 4]);
                a[mi][3] = __float_as_uint(As[(row + 8) * TFROW + k0 + gc + 4]);
            }
            uint32_t b[8][2];
#pragma unroll
            for (int nj = 0; nj < 8; nj++) {
                const int col = wn * 64 + nj * 8 + gr;
                b[nj][0] = __float_as_uint(Bs[col * TFROW + k0 + gc]);
                b[nj][1] = __float_as_uint(Bs[col * TFROW + k0 + gc + 4]);
            }
#pragma unroll
            for (int mi = 0; mi < 2; mi++)
#pragma unroll
                for (int nj = 0; nj < 8; nj++)
                    MMATF32(acc[mi][nj], a[mi][0], a[mi][1], a[mi][2], a[mi][3],
                            b[nj][0], b[nj][1]);
        }
        __syncthreads();
    }

#pragma unroll
    for (int mi = 0; mi < 2; mi++) {
#pragma unroll
        for (int nj = 0; nj < 8; nj++) {
            const int col = n0 + wn * 64 + nj * 8 + (lid & 3) * 2;
            const float2 bv = *reinterpret_cast<const float2*>(bias + col);
#pragma unroll
            for (int half = 0; half < 2; half++) {
                const int row = m0 + wm * 32 + mi * 16 + (lid >> 2) + half * 8;
                float2 o;
                o.x = acc[mi][nj][half * 2 + 0] + bv.x;
                o.y = acc[mi][nj][half * 2 + 1] + bv.y;
                if (!SPLITHEAD) {
                    *reinterpret_cast<float2*>(&C[(size_t)row * N + col]) = o;
                } else {
                    int b = row >> 10, s = row & 1023, h = col >> 6, d = col & 63;
                    *reinterpret_cast<float2*>(
                        &C[(size_t)(((b * Hc + h) * Sc) + s) * HDc + d]) = o;
                }
            }
        }
    }
}

// ---------------------------------------------------------------------------
// HMMA flash attention (bf16x3) + exact fp32 memory-slot phase (unchanged R4)
// ---------------------------------------------------------------------------
static constexpr int ROWB = 144;
static constexpr int QREG = 2 * 128 * ROWB;
static constexpr int KSTG = 4 * 64 * ROWB;
static constexpr int ATTN_SMEM = QREG + 2 * KSTG;    // 110592

__global__ __launch_bounds__(256)
void attn_mma(const float* __restrict__ qkv,
              const __nv_bfloat16* __restrict__ qh_g,
              const __nv_bfloat16* __restrict__ ql_g,
              const float* __restrict__ pk, const float* __restrict__ pv,
              float* __restrict__ ctx)
{
    extern __shared__ char sm[];
    const uint32_t sb = smem_u32(sm);
    const int bid  = blockIdx.x;
    const int tile = 7 - (bid >> 6);
    const int h    = bid & 15;
    const int b    = (bid >> 4) & 3;
    const int tid  = threadIdx.x;
    const int wid  = tid >> 5, lid = tid & 31;

    const size_t qkv_row0 = (size_t)(b * Sc + tile * 128) * 3072;

#pragma unroll
    for (int i = 0; i < 8; i++) {
        int c = tid + i * 256;
        int half = c >> 10;
        int rem = c & 1023;
        int r = rem >> 3, o = (rem & 7) * 16;
        const __nv_bfloat16* src =
            (half ? ql_g : qh_g) + qkv_row0 + (size_t)r * 3072 + h * 64 + o / 2;
        cp16(sb + half * (128 * ROWB) + r * ROWB + o, src);
    }
    CP_COMMIT();

    const int nkt = 2 * tile + 2;
    auto load_stage = [&](int kt, int buf) {
        const uint32_t st = sb + QREG + buf * KSTG;
        const size_t row0 = (size_t)(b * Sc + kt * 64) * 3072;
#pragma unroll
        for (int i = 0; i < 8; i++) {
            int c = tid + i * 256;
            int arr = c >> 9;
            int rem = c & 511;
            int r = rem >> 3, o = (rem & 7) * 16;
            const __nv_bfloat16* base = (arr & 1) ? ql_g : qh_g;
            int colb = (arr < 2) ? 1024 : 2048;
            cp16(st + arr * (64 * ROWB) + r * ROWB + o,
                 base + row0 + (size_t)r * 3072 + colb + h * 64 + o / 2);
        }
    };
    load_stage(0, 0);
    CP_COMMIT();

    CP_WAIT(1);
    __syncthreads();
    uint32_t qfh[16], qfl[16];
    {
        const uint32_t qbase = sb + (wid * 16 + (lid & 15)) * ROWB + ((lid >> 4) << 4);
#pragma unroll
        for (int kc = 0; kc < 4; kc++) {
            LDSM_X4(qfh[kc * 4 + 0], qfh[kc * 4 + 1], qfh[kc * 4 + 2], qfh[kc * 4 + 3],
                    qbase + kc * 32);
            LDSM_X4(qfl[kc * 4 + 0], qfl[kc * 4 + 1], qfl[kc * 4 + 2], qfl[kc * 4 + 3],
                    qbase + 128 * ROWB + kc * 32);
        }
    }
    __syncthreads();

    float o_acc[8][4];
#pragma unroll
    for (int j = 0; j < 8; j++)
#pragma unroll
        for (int v = 0; v < 4; v++) o_acc[j][v] = 0.f;
    float m0 = -1e30f, m1 = -1e30f, sr0 = 0.f, sr1 = 0.f;

    const int rA = tile * 128 + wid * 16 + (lid >> 2);
    const int diag = 2 * tile;

    for (int kt = 0; kt < nkt; kt++) {
        const int buf = kt & 1;
        if (kt + 1 < nkt) { load_stage(kt + 1, buf ^ 1); CP_COMMIT(); CP_WAIT(1); }
        else              { CP_WAIT(0); }
        __syncthreads();

        const uint32_t st = sb + QREG + buf * KSTG;
        const uint32_t Kh = st, Kl = st + 64 * ROWB;
        const uint32_t Vh = st + 2 * 64 * ROWB, Vl = st + 3 * 64 * ROWB;

        float s[8][4];
#pragma unroll
        for (int j = 0; j < 8; j++)
#pragma unroll
            for (int v = 0; v < 4; v++) s[j][v] = 0.f;

#pragma unroll
        for (int np = 0; np < 4; np++) {
            const uint32_t krow = (np * 16 + ((lid >> 4) & 1) * 8 + (lid & 7)) * ROWB
                                + ((lid >> 3) & 1) * 16;
#pragma unroll
            for (int kc = 0; kc < 4; kc++) {
                uint32_t kh0, kh1, kh2, kh3, kl0, kl1, kl2, kl3;
                LDSM_X4(kh0, kh1, kh2, kh3, Kh + krow + kc * 32);
                LDSM_X4(kl0, kl1, kl2, kl3, Kl + krow + kc * 32);
                const uint32_t* qa = qfh + kc * 4;
                const uint32_t* qb = qfl + kc * 4;
                MMA16816(s[2 * np],     qa[0], qa[1], qa[2], qa[3], kh0, kh1);
                MMA16816(s[2 * np],     qb[0], qb[1], qb[2], qb[3], kh0, kh1);
                MMA16816(s[2 * np],     qa[0], qa[1], qa[2], qa[3], kl0, kl1);
                MMA16816(s[2 * np + 1], qa[0], qa[1], qa[2], qa[3], kh2, kh3);
                MMA16816(s[2 * np + 1], qb[0], qb[1], qb[2], qb[3], kh2, kh3);
                MMA16816(s[2 * np + 1], qa[0], qa[1], qa[2], qa[3], kl2, kl3);
            }
        }

#pragma unroll
        for (int j = 0; j < 8; j++)
#pragma unroll
            for (int v = 0; v < 4; v++) s[j][v] *= 0.125f;
        if (kt >= diag) {
#pragma unroll
            for (int j = 0; j < 8; j++) {
                int c0 = kt * 64 + j * 8 + (lid & 3) * 2;
                if (c0     > rA)     s[j][0] = -1e30f;
                if (c0 + 1 > rA)     s[j][1] = -1e30f;
                if (c0     > rA + 8) s[j][2] = -1e30f;
                if (c0 + 1 > rA + 8) s[j][3] = -1e30f;
            }
        }

        float mx0 = -1e30f, mx1 = -1e30f;
#pragma unroll
        for (int j = 0; j < 8; j++) {
            mx0 = fmaxf(mx0, fmaxf(s[j][0], s[j][1]));
            mx1 = fmaxf(mx1, fmaxf(s[j][2], s[j][3]));
        }
        mx0 = fmaxf(mx0, __shfl_xor_sync(0xffffffffu, mx0, 1));
        mx0 = fmaxf(mx0, __shfl_xor_sync(0xffffffffu, mx0, 2));
        mx1 = fmaxf(mx1, __shfl_xor_sync(0xffffffffu, mx1, 1));
        mx1 = fmaxf(mx1, __shfl_xor_sync(0xffffffffu, mx1, 2));
        const float mn0 = fmaxf(m0, mx0), mn1 = fmaxf(m1, mx1);
        const float cr0 = __expf(m0 - mn0), cr1 = __expf(m1 - mn1);
        m0 = mn0; m1 = mn1;
        float ps0 = 0.f, ps1 = 0.f;
#pragma unroll
        for (int j = 0; j < 8; j++) {
            s[j][0] = __expf(s[j][0] - m0); ps0 += s[j][0];
            s[j][1] = __expf(s[j][1] - m0); ps0 += s[j][1];
            s[j][2] = __expf(s[j][2] - m1); ps1 += s[j][2];
            s[j][3] = __expf(s[j][3] - m1); ps1 += s[j][3];
        }
        ps0 += __shfl_xor_sync(0xffffffffu, ps0, 1);
        ps0 += __shfl_xor_sync(0xffffffffu, ps0, 2);
        ps1 += __shfl_xor_sync(0xffffffffu, ps1, 1);
        ps1 += __shfl_xor_sync(0xffffffffu, ps1, 2);
        sr0 = sr0 * cr0 + ps0;
        sr1 = sr1 * cr1 + ps1;
#pragma unroll
        for (int j = 0; j < 8; j++) {
            o_acc[j][0] *= cr0; o_acc[j][1] *= cr0;
            o_acc[j][2] *= cr1; o_acc[j][3] *= cr1;
        }

#pragma unroll
        for (int kc = 0; kc < 4; kc++) {
            uint32_t ph[4], pl[4];
            split2(s[2 * kc][0],     s[2 * kc][1],     ph[0], pl[0]);
            split2(s[2 * kc][2],     s[2 * kc][3],     ph[1], pl[1]);
            split2(s[2 * kc + 1][0], s[2 * kc + 1][1], ph[2], pl[2]);
            split2(s[2 * kc + 1][2], s[2 * kc + 1][3], ph[3], pl[3]);
            const uint32_t vrow = (kc * 16 + ((lid >> 3) & 1) * 8 + (lid & 7)) * ROWB
                                + ((lid >> 4) & 1) * 16;
#pragma unroll
            for (int np = 0; np < 4; np++) {
                uint32_t vh0, vh1, vh2, vh3, vl0, vl1, vl2, vl3;
                LDSM_X4_T(vh0, vh1, vh2, vh3, Vh + vrow + np * 32);
                LDSM_X4_T(vl0, vl1, vl2, vl3, Vl + vrow + np * 32);
                MMA16816(o_acc[2 * np],     ph[0], ph[1], ph[2], ph[3], vh0, vh1);
                MMA16816(o_acc[2 * np],     pl[0], pl[1], pl[2], pl[3], vh0, vh1);
                MMA16816(o_acc[2 * np],     ph[0], ph[1], ph[2], ph[3], vl0, vl1);
                MMA16816(o_acc[2 * np + 1], ph[0], ph[1], ph[2], ph[3], vh2, vh3);
                MMA16816(o_acc[2 * np + 1], pl[0], pl[1], pl[2], pl[3], vh2, vh3);
                MMA16816(o_acc[2 * np + 1], ph[0], ph[1], ph[2], ph[3], vl2, vl3);
            }
        }
        __syncthreads();
    }

    float* Os = reinterpret_cast<float*>(sm);           // [128][66]
    float* Ms = reinterpret_cast<float*>(sm + 33792);   // [128]
    float* Ss = Ms + 128;                               // [128]
    {
        const int ra = wid * 16 + (lid >> 2), rb = ra + 8;
#pragma unroll
        for (int j = 0; j < 8; j++) {
            const int col = j * 8 + (lid & 3) * 2;
            Os[ra * 66 + col]     = o_acc[j][0];
            Os[ra * 66 + col + 1] = o_acc[j][1];
            Os[rb * 66 + col]     = o_acc[j][2];
            Os[rb * 66 + col + 1] = o_acc[j][3];
        }
        if ((lid & 3) == 0) {
            Ms[ra] = m0; Ms[rb] = m1;
            Ss[ra] = sr0; Ss[rb] = sr1;
        }
    }
    __syncthreads();

    {
        const int row = tid >> 1, half = tid & 1;
        const int rg = tile * 128 + row;
        float q[32];
        {
            const float* qp = qkv + (size_t)(b * Sc + rg) * 3072 + h * 64 + half * 32;
#pragma unroll
            for (int i = 0; i < 8; i++) {
                float4 v = *reinterpret_cast<const float4*>(qp + i * 4);
                q[i * 4 + 0] = v.x * 0.125f;
                q[i * 4 + 1] = v.y * 0.125f;
                q[i * 4 + 2] = v.z * 0.125f;
                q[i * 4 + 3] = v.w * 0.125f;
            }
        }
        float m = Ms[row], sr = Ss[row];
        float acc[32];
#pragma unroll
        for (int i = 0; i < 32; i++) acc[i] = Os[row * 66 + half * 32 + i];

        const size_t pbase = ((size_t)((b * Hc + h) * Sc + rg)) * (Lc * HDc) + half * 32;
        const float* pkb = pk + pbase;
        const float* pvb = pv + pbase;
#pragma unroll 1
        for (int l = 0; l < Lc; l++) {
            float d0 = 0.f;
#pragma unroll
            for (int i = 0; i < 8; i++) {
                float4 kk = *reinterpret_cast<const float4*>(pkb + l * 64 + i * 4);
                d0 = fmaf(q[i * 4 + 0], kk.x, d0);
                d0 = fmaf(q[i * 4 + 1], kk.y, d0);
                d0 = fmaf(q[i * 4 + 2], kk.z, d0);
                d0 = fmaf(q[i * 4 + 3], kk.w, d0);
            }
            d0 += __shfl_xor_sync(0xffffffffu, d0, 1);
            float mn = fmaxf(m, d0);
            float cr = __expf(m - mn);
            float p = __expf(d0 - mn);
            m = mn;
            sr = sr * cr + p;
#pragma unroll
            for (int i = 0; i < 32; i++) acc[i] *= cr;
            const float4* vv4 = reinterpret_cast<const float4*>(pvb + l * 64);
#pragma unroll
            for (int i = 0; i < 8; i++) {
                float4 vv = vv4[i];
                acc[i * 4 + 0] = fmaf(p, vv.x, acc[i * 4 + 0]);
                acc[i * 4 + 1] = fmaf(p, vv.y, acc[i * 4 + 1]);
                acc[i * 4 + 2] = fmaf(p, vv.z, acc[i * 4 + 2]);
                acc[i * 4 + 3] = fmaf(p, vv.w, acc[i * 4 + 3]);
            }
        }
        const float inv = 1.f / sr;
        float* cp = ctx + (size_t)(b * Sc + rg) * Dc + h * 64 + half * 32;
#pragma unroll
        for (int i = 0; i < 8; i++) {
            float4 o;
            o.x = acc[i * 4 + 0] * inv;
            o.y = acc[i * 4 + 1] * inv;
            o.z = acc[i * 4 + 2] * inv;
            o.w = acc[i * 4 + 3] * inv;
            *reinterpret_cast<float4*>(cp + i * 4) = o;
        }
    }
}

// ---------------------------------------------------------------------------
extern "C" void kernel_launch(void* const* d_in, const int* in_sizes, int n_in,
                              void* d_out, int out_size)
{
    const float* x     = (const float*)d_in[0];
    const float* pk    = (const float*)d_in[1];
    const float* pv    = (const float*)d_in[2];
    const float* w_qkv = (const float*)d_in[3];
    const float* b_qkv = (const float*)d_in[4];
    const float* w_k   = (const float*)d_in[5];
    const float* b_k   = (const float*)d_in[6];
    const float* w_v   = (const float*)d_in[7];
    const float* b_v   = (const float*)d_in[8];
    const float* w_o   = (const float*)d_in[9];
    const float* b_o   = (const float*)d_in[10];

    float* out  = (float*)d_out;
    float* kcol = out + (size_t)Bc * Sc * Dc;
    float* vcol = kcol + (size_t)Bc * Hc * Sc * HDc;

    static float *qkvp = nullptr, *ctxp = nullptr, *Xt = nullptr;
    static float *WqT, *WkT, *WvT, *WoT;
    static __nv_bfloat16 *QKVh, *QKVl;
    static bool inited = false;
    if (!inited) {
        inited = true;
        cudaGetSymbolAddress((void**)&qkvp, g_qkv);
        cudaGetSymbolAddress((void**)&ctxp, g_ctx);
        cudaGetSymbolAddress((void**)&Xt, g_Xt);
        cudaGetSymbolAddress((void**)&WqT, g_WqT);
        cudaGetSymbolAddress((void**)&WkT, g_WkT);
        cudaGetSymbolAddress((void**)&WvT, g_WvT);
        cudaGetSymbolAddress((void**)&WoT, g_WoT);
        cudaGetSymbolAddress((void**)&QKVh, g_QKVh);
        cudaGetSymbolAddress((void**)&QKVl, g_QKVl);
        cudaFuncSetAttribute(gemm_tf32<false>,
                             cudaFuncAttributeMaxDynamicSharedMemorySize, TGEMM_SMEM);
        cudaFuncSetAttribute(gemm_tf32<true>,
                             cudaFuncAttributeMaxDynamicSharedMemorySize, TGEMM_SMEM);
        cudaFuncSetAttribute(attn_mma,
                             cudaFuncAttributeMaxDynamicSharedMemorySize, ATTN_SMEM);
    }

    // --- operand conversions (tf32 pre-rounding) ---
    convert_tf32<<<(BS * Dc / 4 + 255) / 256, 256>>>(x, Xt, BS * Dc / 4);
    convert_wT_tf32<<<dim3(3 * Dc / 32, Dc / 32), dim3(32, 8)>>>(w_qkv, WqT, Dc, 3 * Dc);
    convert_wT_tf32<<<dim3(Dc / 32, Dc / 32), dim3(32, 8)>>>(w_k, WkT, Dc, Dc);
    convert_wT_tf32<<<dim3(Dc / 32, Dc / 32), dim3(32, 8)>>>(w_v, WvT, Dc, Dc);
    convert_wT_tf32<<<dim3(Dc / 32, Dc / 32), dim3(32, 8)>>>(w_o, WoT, Dc, Dc);

    // --- projections on tensor cores (tf32 single-pass) ---
    gemm_tf32<false><<<dim3(3 * Dc / 128, BS / 128), 256, TGEMM_SMEM>>>(
        Xt, WqT, b_qkv, qkvp, BS, 3 * Dc, Dc);
    gemm_tf32<true><<<dim3(Dc / 128, BS / 128), 256, TGEMM_SMEM>>>(
        Xt, WkT, b_k, kcol, BS, Dc, Dc);
    gemm_tf32<true><<<dim3(Dc / 128, BS / 128), 256, TGEMM_SMEM>>>(
        Xt, WvT, b_v, vcol, BS, Dc, Dc);

    // --- split qkv to bf16 hi/lo for attention MMA operands ---
    convert_hilo<<<(BS * 3 * Dc / 4 + 255) / 256, 256>>>(qkvp, QKVh, QKVl, BS * 3 * Dc / 4);

    // --- HMMA flash attention + exact memory-slot merge ---
    attn_mma<<<512, 256, ATTN_SMEM>>>(qkvp, QKVh, QKVl, pk, pv, ctxp);

    // --- output projection ---
    convert_tf32<<<(BS * Dc / 4 + 255) / 256, 256>>>(ctxp, Xt, BS * Dc / 4);
    gemm_tf32<false><<<dim3(Dc / 128, BS / 128), 256, TGEMM_SMEM>>>(
        Xt, WoT, b_o, out, BS, Dc, Dc);
}

// round 6
// speedup vs baseline: 3.2885x; 1.0582x over previous
#include <cuda_runtime.h>
#include <cuda_bf16.h>
#include <cstdint>
#include <math.h>

// Problem constants
static constexpr int Bc  = 4;
static constexpr int Sc  = 1024;
static constexpr int Dc  = 1024;
static constexpr int Hc  = 16;
static constexpr int HDc = 64;
static constexpr int Lc  = 12;
static constexpr int BS  = Bc * Sc;       // 4096 rows

// ---------------------------------------------------------------------------
// Scratch (__device__ globals; no cudaMalloc allowed)
// ---------------------------------------------------------------------------
__device__ float g_Xt[(size_t)BS * Dc];        // tf32-rounded A (x, later ctx)
__device__ float g_WqT[(size_t)3 * Dc * Dc];   // w_qkv^T tf32 [N,K]
__device__ float g_WkT[(size_t)Dc * Dc];
__device__ float g_WvT[(size_t)Dc * Dc];
__device__ float g_WoT[(size_t)Dc * Dc];
__device__ __nv_bfloat16 g_QKVh[(size_t)BS * 3 * Dc];    // qkv hi (attn operands)
__device__ __nv_bfloat16 g_QKVl[(size_t)BS * 3 * Dc];    // qkv lo

// ---------------------------------------------------------------------------
// PTX helpers (base-PTX only: cp.async / ldmatrix / mma.sync / cvt.tf32)
// ---------------------------------------------------------------------------
__device__ __forceinline__ uint32_t smem_u32(const void* p) {
    uint32_t a;
    asm("{ .reg .u64 t; cvta.to.shared.u64 t, %1; cvt.u32.u64 %0, t; }"
        : "=r"(a) : "l"(p));
    return a;
}

__device__ __forceinline__ void cp16(uint32_t saddr, const void* gaddr) {
    asm volatile("cp.async.cg.shared.global [%0], [%1], 16;"
                 :: "r"(saddr), "l"(gaddr));
}
#define CP_COMMIT() asm volatile("cp.async.commit_group;" ::: "memory")
#define CP_WAIT(n)  asm volatile("cp.async.wait_group %0;" :: "n"(n) : "memory")

#define LDSM_X4(r0, r1, r2, r3, addr) \
    asm volatile("ldmatrix.sync.aligned.m8n8.x4.shared.b16 {%0,%1,%2,%3}, [%4];" \
                 : "=r"(r0), "=r"(r1), "=r"(r2), "=r"(r3) : "r"(addr))

#define LDSM_X4_T(r0, r1, r2, r3, addr) \
    asm volatile("ldmatrix.sync.aligned.m8n8.x4.trans.shared.b16 {%0,%1,%2,%3}, [%4];" \
                 : "=r"(r0), "=r"(r1), "=r"(r2), "=r"(r3) : "r"(addr))

#define MMA16816(d, a0, a1, a2, a3, b0, b1) \
    asm volatile("mma.sync.aligned.m16n8k16.row.col.f32.bf16.bf16.f32 " \
                 "{%0,%1,%2,%3}, {%4,%5,%6,%7}, {%8,%9}, {%0,%1,%2,%3};" \
                 : "+f"((d)[0]), "+f"((d)[1]), "+f"((d)[2]), "+f"((d)[3]) \
                 : "r"(a0), "r"(a1), "r"(a2), "r"(a3), "r"(b0), "r"(b1))

#define MMATF32(d, a0, a1, a2, a3, b0, b1) \
    asm volatile("mma.sync.aligned.m16n8k8.row.col.f32.tf32.tf32.f32 " \
                 "{%0,%1,%2,%3}, {%4,%5,%6,%7}, {%8,%9}, {%0,%1,%2,%3};" \
                 : "+f"((d)[0]), "+f"((d)[1]), "+f"((d)[2]), "+f"((d)[3]) \
                 : "r"(a0), "r"(a1), "r"(a2), "r"(a3), "r"(b0), "r"(b1))

__device__ __forceinline__ float tf32r(float x) {
    uint32_t o;
    asm("cvt.rna.tf32.f32 %0, %1;" : "=r"(o) : "f"(x));
    return __uint_as_float(o);
}

// split a pair of fp32 into hi/lo bf16x2 regs
__device__ __forceinline__ void split2(float a, float b, uint32_t& h, uint32_t& l) {
    __nv_bfloat162 hh = __floats2bfloat162_rn(a, b);
    float2 hf = __bfloat1622float2(hh);
    __nv_bfloat162 ll = __floats2bfloat162_rn(a - hf.x, b - hf.y);
    h = *reinterpret_cast<uint32_t*>(&hh);
    l = *reinterpret_cast<uint32_t*>(&ll);
}

// ---------------------------------------------------------------------------
// fp32 -> tf32-rounded fp32, elementwise
// ---------------------------------------------------------------------------
__global__ __launch_bounds__(256)
void convert_tf32(const float* __restrict__ src, float* __restrict__ dst, int n4)
{
    int i = blockIdx.x * blockDim.x + threadIdx.x;
    if (i >= n4) return;
    float4 v = reinterpret_cast<const float4*>(src)[i];
    v.x = tf32r(v.x); v.y = tf32r(v.y); v.z = tf32r(v.z); v.w = tf32r(v.w);
    reinterpret_cast<float4*>(dst)[i] = v;
}

// ---------------------------------------------------------------------------
// W[K,N] fp32 -> Wt[N,K] tf32-rounded fp32 (transpose + round)
// ---------------------------------------------------------------------------
__global__ __launch_bounds__(256)
void convert_wT_tf32(const float* __restrict__ W, float* __restrict__ T, int K, int N)
{
    __shared__ float t[32][33];
    int n0 = blockIdx.x * 32, k0 = blockIdx.y * 32;
    int tx = threadIdx.x, ty = threadIdx.y;   // (32, 8)
#pragma unroll
    for (int i = 0; i < 4; i++)
        t[ty + i * 8][tx] = W[(size_t)(k0 + ty + i * 8) * N + n0 + tx];
    __syncthreads();
#pragma unroll
    for (int i = 0; i < 4; i++) {
        int n = n0 + ty + i * 8;
        T[(size_t)n * K + k0 + tx] = tf32r(t[tx][ty + i * 8]);
    }
}

// ---------------------------------------------------------------------------
// tf32 HMMA GEMM:  C = A @ B^T + bias  (A [M,K], B [N,K], pre-rounded)
// EPI: 0 = fp32 row-major, 1 = fp32 split-head, 2 = bf16 hi/lo pair buffers
// ---------------------------------------------------------------------------
static constexpr int TFROW   = 36;                    // floats per smem row
static constexpr int TTILE   = 128 * TFROW * 4;       // 18432 B per operand
static constexpr int TSTAGE  = 2 * TTILE;             // A + B = 36864
static constexpr int TGEMM_SMEM = 2 * TSTAGE;         // 73728

template<int EPI>
__global__ __launch_bounds__(256)
void gemm_tf32(const float* __restrict__ A, const float* __restrict__ B,
               const float* __restrict__ bias, float* __restrict__ C,
               __nv_bfloat16* __restrict__ Ch, __nv_bfloat16* __restrict__ Cl,
               int M, int N, int K)
{
    extern __shared__ char smem[];
    const uint32_t sb = smem_u32(smem);
    const int tid  = threadIdx.x;
    const int wid  = tid >> 5, lid = tid & 31;
    const int wm   = wid >> 1, wn = wid & 1;
    const int m0   = blockIdx.y * 128, n0 = blockIdx.x * 128;

    const float* Ab = A + (size_t)m0 * K;
    const float* Bb = B + (size_t)n0 * K;

    auto load_stage = [&](int kc, int buf) {
        const uint32_t base = sb + buf * TSTAGE;
#pragma unroll
        for (int i = 0; i < 8; i++) {
            int c = tid + i * 256;              // 0..2047 16B chunks
            int op = c >> 10;                   // 0=A 1=B
            int rem = c & 1023;
            int r = rem >> 3, q = rem & 7;
            const float* s = (op ? Bb : Ab) + (size_t)r * K + kc * 32 + q * 4;
            cp16(base + op * TTILE + (r * TFROW + q * 4) * 4, s);
        }
    };

    float acc[2][8][4];
#pragma unroll
    for (int i = 0; i < 2; i++)
#pragma unroll
        for (int j = 0; j < 8; j++)
#pragma unroll
            for (int v = 0; v < 4; v++) acc[i][j][v] = 0.f;

    const int gr = lid >> 2, gc = lid & 3;

    const int nk = K >> 5;
    load_stage(0, 0);
    CP_COMMIT();

    for (int kc = 0; kc < nk; kc++) {
        const int buf = kc & 1;
        if (kc + 1 < nk) { load_stage(kc + 1, buf ^ 1); CP_COMMIT(); CP_WAIT(1); }
        else             { CP_WAIT(0); }
        __syncthreads();

        const float* As = reinterpret_cast<const float*>(smem + buf * TSTAGE);
        const float* Bs = reinterpret_cast<const float*>(smem + buf * TSTAGE + TTILE);

#pragma unroll
        for (int ks = 0; ks < 4; ks++) {
            const int k0 = ks * 8;
            uint32_t a[2][4];
#pragma unroll
            for (int mi = 0; mi < 2; mi++) {
                const int row = wm * 32 + mi * 16 + gr;
                a[mi][0] = __float_as_uint(As[row * TFROW + k0 + gc]);
                a[mi][1] = __float_as_uint(As[(row + 8) * TFROW + k0 + gc]);
                a[mi][2] = __float_as_uint(As[row * TFROW + k0 + gc + 4]);
                a[mi][3] = __float_as_uint(As[(row + 8) * TFROW + k0 + gc + 4]);
            }
            uint32_t b[8][2];
#pragma unroll
            for (int nj = 0; nj < 8; nj++) {
                const int col = wn * 64 + nj * 8 + gr;
                b[nj][0] = __float_as_uint(Bs[col * TFROW + k0 + gc]);
                b[nj][1] = __float_as_uint(Bs[col * TFROW + k0 + gc + 4]);
            }
#pragma unroll
            for (int mi = 0; mi < 2; mi++)
#pragma unroll
                for (int nj = 0; nj < 8; nj++)
                    MMATF32(acc[mi][nj], a[mi][0], a[mi][1], a[mi][2], a[mi][3],
                            b[nj][0], b[nj][1]);
        }
        __syncthreads();
    }

#pragma unroll
    for (int mi = 0; mi < 2; mi++) {
#pragma unroll
        for (int nj = 0; nj < 8; nj++) {
            const int col = n0 + wn * 64 + nj * 8 + (lid & 3) * 2;
            const float2 bv = *reinterpret_cast<const float2*>(bias + col);
#pragma unroll
            for (int half = 0; half < 2; half++) {
                const int row = m0 + wm * 32 + mi * 16 + (lid >> 2) + half * 8;
                float2 o;
                o.x = acc[mi][nj][half * 2 + 0] + bv.x;
                o.y = acc[mi][nj][half * 2 + 1] + bv.y;
                if (EPI == 0) {
                    *reinterpret_cast<float2*>(&C[(size_t)row * N + col]) = o;
                } else if (EPI == 1) {
                    int b = row >> 10, s = row & 1023, h = col >> 6, d = col & 63;
                    *reinterpret_cast<float2*>(
                        &C[(size_t)(((b * Hc + h) * Sc) + s) * HDc + d]) = o;
                } else {
                    uint32_t hreg, lreg;
                    split2(o.x, o.y, hreg, lreg);
                    *reinterpret_cast<uint32_t*>(&Ch[(size_t)row * N + col]) = hreg;
                    *reinterpret_cast<uint32_t*>(&Cl[(size_t)row * N + col]) = lreg;
                }
            }
        }
    }
}

// ---------------------------------------------------------------------------
// HMMA flash attention (bf16x3) + exact fp32 memory-slot phase.
// Reads qkv as bf16 hi/lo; writes tf32-rounded ctx (ready for out-projection).
// ---------------------------------------------------------------------------
static constexpr int ROWB = 144;
static constexpr int QREG = 2 * 128 * ROWB;
static constexpr int KSTG = 4 * 64 * ROWB;
static constexpr int ATTN_SMEM = QREG + 2 * KSTG;    // 110592

__global__ __launch_bounds__(256)
void attn_mma(const __nv_bfloat16* __restrict__ qh_g,
              const __nv_bfloat16* __restrict__ ql_g,
              const float* __restrict__ pk, const float* __restrict__ pv,
              float* __restrict__ ctx)
{
    extern __shared__ char sm[];
    const uint32_t sb = smem_u32(sm);
    const int bid  = blockIdx.x;
    const int tile = 7 - (bid >> 6);
    const int h    = bid & 15;
    const int b    = (bid >> 4) & 3;
    const int tid  = threadIdx.x;
    const int wid  = tid >> 5, lid = tid & 31;

    const size_t qkv_row0 = (size_t)(b * Sc + tile * 128) * 3072;

#pragma unroll
    for (int i = 0; i < 8; i++) {
        int c = tid + i * 256;
        int half = c >> 10;
        int rem = c & 1023;
        int r = rem >> 3, o = (rem & 7) * 16;
        const __nv_bfloat16* src =
            (half ? ql_g : qh_g) + qkv_row0 + (size_t)r * 3072 + h * 64 + o / 2;
        cp16(sb + half * (128 * ROWB) + r * ROWB + o, src);
    }
    CP_COMMIT();

    const int nkt = 2 * tile + 2;
    auto load_stage = [&](int kt, int buf) {
        const uint32_t st = sb + QREG + buf * KSTG;
        const size_t row0 = (size_t)(b * Sc + kt * 64) * 3072;
#pragma unroll
        for (int i = 0; i < 8; i++) {
            int c = tid + i * 256;
            int arr = c >> 9;
            int rem = c & 511;
            int r = rem >> 3, o = (rem & 7) * 16;
            const __nv_bfloat16* base = (arr & 1) ? ql_g : qh_g;
            int colb = (arr < 2) ? 1024 : 2048;
            cp16(st + arr * (64 * ROWB) + r * ROWB + o,
                 base + row0 + (size_t)r * 3072 + colb + h * 64 + o / 2);
        }
    };
    load_stage(0, 0);
    CP_COMMIT();

    CP_WAIT(1);
    __syncthreads();
    uint32_t qfh[16], qfl[16];
    {
        const uint32_t qbase = sb + (wid * 16 + (lid & 15)) * ROWB + ((lid >> 4) << 4);
#pragma unroll
        for (int kc = 0; kc < 4; kc++) {
            LDSM_X4(qfh[kc * 4 + 0], qfh[kc * 4 + 1], qfh[kc * 4 + 2], qfh[kc * 4 + 3],
                    qbase + kc * 32);
            LDSM_X4(qfl[kc * 4 + 0], qfl[kc * 4 + 1], qfl[kc * 4 + 2], qfl[kc * 4 + 3],
                    qbase + 128 * ROWB + kc * 32);
        }
    }
    __syncthreads();

    float o_acc[8][4];
#pragma unroll
    for (int j = 0; j < 8; j++)
#pragma unroll
        for (int v = 0; v < 4; v++) o_acc[j][v] = 0.f;
    float m0 = -1e30f, m1 = -1e30f, sr0 = 0.f, sr1 = 0.f;

    const int rA = tile * 128 + wid * 16 + (lid >> 2);
    const int diag = 2 * tile;

    for (int kt = 0; kt < nkt; kt++) {
        const int buf = kt & 1;
        if (kt + 1 < nkt) { load_stage(kt + 1, buf ^ 1); CP_COMMIT(); CP_WAIT(1); }
        else              { CP_WAIT(0); }
        __syncthreads();

        const uint32_t st = sb + QREG + buf * KSTG;
        const uint32_t Kh = st, Kl = st + 64 * ROWB;
        const uint32_t Vh = st + 2 * 64 * ROWB, Vl = st + 3 * 64 * ROWB;

        float s[8][4];
#pragma unroll
        for (int j = 0; j < 8; j++)
#pragma unroll
            for (int v = 0; v < 4; v++) s[j][v] = 0.f;

#pragma unroll
        for (int np = 0; np < 4; np++) {
            const uint32_t krow = (np * 16 + ((lid >> 4) & 1) * 8 + (lid & 7)) * ROWB
                                + ((lid >> 3) & 1) * 16;
#pragma unroll
            for (int kc = 0; kc < 4; kc++) {
                uint32_t kh0, kh1, kh2, kh3, kl0, kl1, kl2, kl3;
                LDSM_X4(kh0, kh1, kh2, kh3, Kh + krow + kc * 32);
                LDSM_X4(kl0, kl1, kl2, kl3, Kl + krow + kc * 32);
                const uint32_t* qa = qfh + kc * 4;
                const uint32_t* qb = qfl + kc * 4;
                MMA16816(s[2 * np],     qa[0], qa[1], qa[2], qa[3], kh0, kh1);
                MMA16816(s[2 * np],     qb[0], qb[1], qb[2], qb[3], kh0, kh1);
                MMA16816(s[2 * np],     qa[0], qa[1], qa[2], qa[3], kl0, kl1);
                MMA16816(s[2 * np + 1], qa[0], qa[1], qa[2], qa[3], kh2, kh3);
                MMA16816(s[2 * np + 1], qb[0], qb[1], qb[2], qb[3], kh2, kh3);
                MMA16816(s[2 * np + 1], qa[0], qa[1], qa[2], qa[3], kl2, kl3);
            }
        }

#pragma unroll
        for (int j = 0; j < 8; j++)
#pragma unroll
            for (int v = 0; v < 4; v++) s[j][v] *= 0.125f;
        if (kt >= diag) {
#pragma unroll
            for (int j = 0; j < 8; j++) {
                int c0 = kt * 64 + j * 8 + (lid & 3) * 2;
                if (c0     > rA)     s[j][0] = -1e30f;
                if (c0 + 1 > rA)     s[j][1] = -1e30f;
                if (c0     > rA + 8) s[j][2] = -1e30f;
                if (c0 + 1 > rA + 8) s[j][3] = -1e30f;
            }
        }

        float mx0 = -1e30f, mx1 = -1e30f;
#pragma unroll
        for (int j = 0; j < 8; j++) {
            mx0 = fmaxf(mx0, fmaxf(s[j][0], s[j][1]));
            mx1 = fmaxf(mx1, fmaxf(s[j][2], s[j][3]));
        }
        mx0 = fmaxf(mx0, __shfl_xor_sync(0xffffffffu, mx0, 1));
        mx0 = fmaxf(mx0, __shfl_xor_sync(0xffffffffu, mx0, 2));
        mx1 = fmaxf(mx1, __shfl_xor_sync(0xffffffffu, mx1, 1));
        mx1 = fmaxf(mx1, __shfl_xor_sync(0xffffffffu, mx1, 2));
        const float mn0 = fmaxf(m0, mx0), mn1 = fmaxf(m1, mx1);
        const float cr0 = __expf(m0 - mn0), cr1 = __expf(m1 - mn1);
        m0 = mn0; m1 = mn1;
        float ps0 = 0.f, ps1 = 0.f;
#pragma unroll
        for (int j = 0; j < 8; j++) {
            s[j][0] = __expf(s[j][0] - m0); ps0 += s[j][0];
            s[j][1] = __expf(s[j][1] - m0); ps0 += s[j][1];
            s[j][2] = __expf(s[j][2] - m1); ps1 += s[j][2];
            s[j][3] = __expf(s[j][3] - m1); ps1 += s[j][3];
        }
        ps0 += __shfl_xor_sync(0xffffffffu, ps0, 1);
        ps0 += __shfl_xor_sync(0xffffffffu, ps0, 2);
        ps1 += __shfl_xor_sync(0xffffffffu, ps1, 1);
        ps1 += __shfl_xor_sync(0xffffffffu, ps1, 2);
        sr0 = sr0 * cr0 + ps0;
        sr1 = sr1 * cr1 + ps1;
#pragma unroll
        for (int j = 0; j < 8; j++) {
            o_acc[j][0] *= cr0; o_acc[j][1] *= cr0;
            o_acc[j][2] *= cr1; o_acc[j][3] *= cr1;
        }

#pragma unroll
        for (int kc = 0; kc < 4; kc++) {
            uint32_t ph[4], pl[4];
            split2(s[2 * kc][0],     s[2 * kc][1],     ph[0], pl[0]);
            split2(s[2 * kc][2],     s[2 * kc][3],     ph[1], pl[1]);
            split2(s[2 * kc + 1][0], s[2 * kc + 1][1], ph[2], pl[2]);
            split2(s[2 * kc + 1][2], s[2 * kc + 1][3], ph[3], pl[3]);
            const uint32_t vrow = (kc * 16 + ((lid >> 3) & 1) * 8 + (lid & 7)) * ROWB
                                + ((lid >> 4) & 1) * 16;
#pragma unroll
            for (int np = 0; np < 4; np++) {
                uint32_t vh0, vh1, vh2, vh3, vl0, vl1, vl2, vl3;
                LDSM_X4_T(vh0, vh1, vh2, vh3, Vh + vrow + np * 32);
                LDSM_X4_T(vl0, vl1, vl2, vl3, Vl + vrow + np * 32);
                MMA16816(o_acc[2 * np],     ph[0], ph[1], ph[2], ph[3], vh0, vh1);
                MMA16816(o_acc[2 * np],     pl[0], pl[1], pl[2], pl[3], vh0, vh1);
                MMA16816(o_acc[2 * np],     ph[0], ph[1], ph[2], ph[3], vl0, vl1);
                MMA16816(o_acc[2 * np + 1], ph[0], ph[1], ph[2], ph[3], vh2, vh3);
                MMA16816(o_acc[2 * np + 1], pl[0], pl[1], pl[2], pl[3], vh2, vh3);
                MMA16816(o_acc[2 * np + 1], ph[0], ph[1], ph[2], ph[3], vl2, vl3);
            }
        }
        __syncthreads();
    }

    float* Os = reinterpret_cast<float*>(sm);           // [128][66]
    float* Ms = reinterpret_cast<float*>(sm + 33792);   // [128]
    float* Ss = Ms + 128;                               // [128]
    {
        const int ra = wid * 16 + (lid >> 2), rb = ra + 8;
#pragma unroll
        for (int j = 0; j < 8; j++) {
            const int col = j * 8 + (lid & 3) * 2;
            Os[ra * 66 + col]     = o_acc[j][0];
            Os[ra * 66 + col + 1] = o_acc[j][1];
            Os[rb * 66 + col]     = o_acc[j][2];
            Os[rb * 66 + col + 1] = o_acc[j][3];
        }
        if ((lid & 3) == 0) {
            Ms[ra] = m0; Ms[rb] = m1;
            Ss[ra] = sr0; Ss[rb] = sr1;
        }
    }
    __syncthreads();

    {
        const int row = tid >> 1, half = tid & 1;
        const int rg = tile * 128 + row;
        // reconstruct q = hi + lo (fp32 to within bf16-lo rounding)
        float q[32];
        {
            const size_t qo = (size_t)(b * Sc + rg) * 3072 + h * 64 + half * 32;
            const __nv_bfloat162* qh2 = reinterpret_cast<const __nv_bfloat162*>(qh_g + qo);
            const __nv_bfloat162* ql2 = reinterpret_cast<const __nv_bfloat162*>(ql_g + qo);
#pragma unroll
            for (int i = 0; i < 16; i++) {
                float2 hf = __bfloat1622float2(qh2[i]);
                float2 lf = __bfloat1622float2(ql2[i]);
                q[2 * i + 0] = (hf.x + lf.x) * 0.125f;
                q[2 * i + 1] = (hf.y + lf.y) * 0.125f;
            }
        }
        float m = Ms[row], sr = Ss[row];
        float acc[32];
#pragma unroll
        for (int i = 0; i < 32; i++) acc[i] = Os[row * 66 + half * 32 + i];

        const size_t pbase = ((size_t)((b * Hc + h) * Sc + rg)) * (Lc * HDc) + half * 32;
        const float* pkb = pk + pbase;
        const float* pvb = pv + pbase;
#pragma unroll 1
        for (int l = 0; l < Lc; l++) {
            float d0 = 0.f;
#pragma unroll
            for (int i = 0; i < 8; i++) {
                float4 kk = *reinterpret_cast<const float4*>(pkb + l * 64 + i * 4);
                d0 = fmaf(q[i * 4 + 0], kk.x, d0);
                d0 = fmaf(q[i * 4 + 1], kk.y, d0);
                d0 = fmaf(q[i * 4 + 2], kk.z, d0);
                d0 = fmaf(q[i * 4 + 3], kk.w, d0);
            }
            d0 += __shfl_xor_sync(0xffffffffu, d0, 1);
            float mn = fmaxf(m, d0);
            float cr = __expf(m - mn);
            float p = __expf(d0 - mn);
            m = mn;
            sr = sr * cr + p;
#pragma unroll
            for (int i = 0; i < 32; i++) acc[i] *= cr;
            const float4* vv4 = reinterpret_cast<const float4*>(pvb + l * 64);
#pragma unroll
            for (int i = 0; i < 8; i++) {
                float4 vv = vv4[i];
                acc[i * 4 + 0] = fmaf(p, vv.x, acc[i * 4 + 0]);
                acc[i * 4 + 1] = fmaf(p, vv.y, acc[i * 4 + 1]);
                acc[i * 4 + 2] = fmaf(p, vv.z, acc[i * 4 + 2]);
                acc[i * 4 + 3] = fmaf(p, vv.w, acc[i * 4 + 3]);
            }
        }
        const float inv = 1.f / sr;
        // write tf32-rounded ctx directly (feeds out-projection GEMM)
        float* cp = ctx + (size_t)(b * Sc + rg) * Dc + h * 64 + half * 32;
#pragma unroll
        for (int i = 0; i < 8; i++) {
            float4 o;
            o.x = tf32r(acc[i * 4 + 0] * inv);
            o.y = tf32r(acc[i * 4 + 1] * inv);
            o.z = tf32r(acc[i * 4 + 2] * inv);
            o.w = tf32r(acc[i * 4 + 3] * inv);
            *reinterpret_cast<float4*>(cp + i * 4) = o;
        }
    }
}

// ---------------------------------------------------------------------------
extern "C" void kernel_launch(void* const* d_in, const int* in_sizes, int n_in,
                              void* d_out, int out_size)
{
    const float* x     = (const float*)d_in[0];
    const float* pk    = (const float*)d_in[1];
    const float* pv    = (const float*)d_in[2];
    const float* w_qkv = (const float*)d_in[3];
    const float* b_qkv = (const float*)d_in[4];
    const float* w_k   = (const float*)d_in[5];
    const float* b_k   = (const float*)d_in[6];
    const float* w_v   = (const float*)d_in[7];
    const float* b_v   = (const float*)d_in[8];
    const float* w_o   = (const float*)d_in[9];
    const float* b_o   = (const float*)d_in[10];

    float* out  = (float*)d_out;
    float* kcol = out + (size_t)Bc * Sc * Dc;
    float* vcol = kcol + (size_t)Bc * Hc * Sc * HDc;

    static float *Xt = nullptr;
    static float *WqT, *WkT, *WvT, *WoT;
    static __nv_bfloat16 *QKVh, *QKVl;
    static bool inited = false;
    if (!inited) {
        inited = true;
        cudaGetSymbolAddress((void**)&Xt, g_Xt);
        cudaGetSymbolAddress((void**)&WqT, g_WqT);
        cudaGetSymbolAddress((void**)&WkT, g_WkT);
        cudaGetSymbolAddress((void**)&WvT, g_WvT);
        cudaGetSymbolAddress((void**)&WoT, g_WoT);
        cudaGetSymbolAddress((void**)&QKVh, g_QKVh);
        cudaGetSymbolAddress((void**)&QKVl, g_QKVl);
        cudaFuncSetAttribute(gemm_tf32<0>,
                             cudaFuncAttributeMaxDynamicSharedMemorySize, TGEMM_SMEM);
        cudaFuncSetAttribute(gemm_tf32<1>,
                             cudaFuncAttributeMaxDynamicSharedMemorySize, TGEMM_SMEM);
        cudaFuncSetAttribute(gemm_tf32<2>,
                             cudaFuncAttributeMaxDynamicSharedMemorySize, TGEMM_SMEM);
        cudaFuncSetAttribute(attn_mma,
                             cudaFuncAttributeMaxDynamicSharedMemorySize, ATTN_SMEM);
    }

    // --- operand conversions (tf32 pre-rounding) ---
    convert_tf32<<<(BS * Dc / 4 + 255) / 256, 256>>>(x, Xt, BS * Dc / 4);
    convert_wT_tf32<<<dim3(3 * Dc / 32, Dc / 32), dim3(32, 8)>>>(w_qkv, WqT, Dc, 3 * Dc);
    convert_wT_tf32<<<dim3(Dc / 32, Dc / 32), dim3(32, 8)>>>(w_k, WkT, Dc, Dc);
    convert_wT_tf32<<<dim3(Dc / 32, Dc / 32), dim3(32, 8)>>>(w_v, WvT, Dc, Dc);
    convert_wT_tf32<<<dim3(Dc / 32, Dc / 32), dim3(32, 8)>>>(w_o, WoT, Dc, Dc);

    // --- projections (tf32 HMMA); qkv writes bf16 hi/lo directly ---
    gemm_tf32<2><<<dim3(3 * Dc / 128, BS / 128), 256, TGEMM_SMEM>>>(
        Xt, WqT, b_qkv, nullptr, QKVh, QKVl, BS, 3 * Dc, Dc);
    gemm_tf32<1><<<dim3(Dc / 128, BS / 128), 256, TGEMM_SMEM>>>(
        Xt, WkT, b_k, kcol, nullptr, nullptr, BS, Dc, Dc);
    gemm_tf32<1><<<dim3(Dc / 128, BS / 128), 256, TGEMM_SMEM>>>(
        Xt, WvT, b_v, vcol, nullptr, nullptr, BS, Dc, Dc);

    // --- HMMA flash attention + exact memory-slot merge (writes tf32 ctx) ---
    attn_mma<<<512, 256, ATTN_SMEM>>>(QKVh, QKVl, pk, pv, Xt);

    // --- output projection ---
    gemm_tf32<0><<<dim3(Dc / 128, BS / 128), 256, TGEMM_SMEM>>>(
        Xt, WoT, b_o, out, nullptr, nullptr, BS, Dc, Dc);
}

// round 7
// speedup vs baseline: 5.2265x; 1.5893x over previous
#include <cuda_runtime.h>
#include <cuda_fp16.h>
#include <cstdint>
#include <math.h>

// Problem constants
static constexpr int Bc  = 4;
static constexpr int Sc  = 1024;
static constexpr int Dc  = 1024;
static constexpr int Hc  = 16;
static constexpr int HDc = 64;
static constexpr int Lc  = 12;
static constexpr int BS  = Bc * Sc;       // 4096 rows

// ---------------------------------------------------------------------------
// Scratch (__device__ globals; no cudaMalloc allowed)
// ---------------------------------------------------------------------------
__device__ __half g_Xh[(size_t)BS * Dc];         // fp16 A operand (x, later ctx)
__device__ __half g_WqH[(size_t)3 * Dc * Dc];    // w_qkv^T fp16 [N,K]
__device__ __half g_WkH[(size_t)Dc * Dc];
__device__ __half g_WvH[(size_t)Dc * Dc];
__device__ __half g_WoH[(size_t)Dc * Dc];
__device__ __half g_QKVH[(size_t)BS * 3 * Dc];   // qkv fp16 (attn operands)

// ---------------------------------------------------------------------------
// PTX helpers (base-PTX only: cp.async / ldmatrix / mma.sync)
// ---------------------------------------------------------------------------
__device__ __forceinline__ uint32_t smem_u32(const void* p) {
    uint32_t a;
    asm("{ .reg .u64 t; cvta.to.shared.u64 t, %1; cvt.u32.u64 %0, t; }"
        : "=r"(a) : "l"(p));
    return a;
}

__device__ __forceinline__ void cp16(uint32_t saddr, const void* gaddr) {
    asm volatile("cp.async.cg.shared.global [%0], [%1], 16;"
                 :: "r"(saddr), "l"(gaddr));
}
#define CP_COMMIT() asm volatile("cp.async.commit_group;" ::: "memory")
#define CP_WAIT(n)  asm volatile("cp.async.wait_group %0;" :: "n"(n) : "memory")

#define LDSM_X4(r0, r1, r2, r3, addr) \
    asm volatile("ldmatrix.sync.aligned.m8n8.x4.shared.b16 {%0,%1,%2,%3}, [%4];" \
                 : "=r"(r0), "=r"(r1), "=r"(r2), "=r"(r3) : "r"(addr))

#define LDSM_X4_T(r0, r1, r2, r3, addr) \
    asm volatile("ldmatrix.sync.aligned.m8n8.x4.trans.shared.b16 {%0,%1,%2,%3}, [%4];" \
                 : "=r"(r0), "=r"(r1), "=r"(r2), "=r"(r3) : "r"(addr))

#define MMAF16(d, a0, a1, a2, a3, b0, b1) \
    asm volatile("mma.sync.aligned.m16n8k16.row.col.f32.f16.f16.f32 " \
                 "{%0,%1,%2,%3}, {%4,%5,%6,%7}, {%8,%9}, {%0,%1,%2,%3};" \
                 : "+f"((d)[0]), "+f"((d)[1]), "+f"((d)[2]), "+f"((d)[3]) \
                 : "r"(a0), "r"(a1), "r"(a2), "r"(a3), "r"(b0), "r"(b1))

__device__ __forceinline__ uint32_t packh2(float a, float b) {
    __half2 h = __floats2half2_rn(a, b);
    return *reinterpret_cast<uint32_t*>(&h);
}

// ---------------------------------------------------------------------------
// fp32 -> fp16, elementwise
// ---------------------------------------------------------------------------
__global__ __launch_bounds__(256)
void convert_f16(const float* __restrict__ src, __half* __restrict__ dst, int n4)
{
    int i = blockIdx.x * blockDim.x + threadIdx.x;
    if (i >= n4) return;
    float4 v = reinterpret_cast<const float4*>(src)[i];
    __half2 h01 = __floats2half2_rn(v.x, v.y);
    __half2 h23 = __floats2half2_rn(v.z, v.w);
    reinterpret_cast<__half2*>(dst)[2 * i + 0] = h01;
    reinterpret_cast<__half2*>(dst)[2 * i + 1] = h23;
}

// ---------------------------------------------------------------------------
// W[K,N] fp32 -> Wt[N,K] fp16 (transpose + convert)
// ---------------------------------------------------------------------------
__global__ __launch_bounds__(256)
void convert_wT_f16(const float* __restrict__ W, __half* __restrict__ T, int K, int N)
{
    __shared__ float t[32][33];
    int n0 = blockIdx.x * 32, k0 = blockIdx.y * 32;
    int tx = threadIdx.x, ty = threadIdx.y;   // (32, 8)
#pragma unroll
    for (int i = 0; i < 4; i++)
        t[ty + i * 8][tx] = W[(size_t)(k0 + ty + i * 8) * N + n0 + tx];
    __syncthreads();
#pragma unroll
    for (int i = 0; i < 4; i++) {
        int n = n0 + ty + i * 8;
        T[(size_t)n * K + k0 + tx] = __float2half_rn(t[tx][ty + i * 8]);
    }
}

// ---------------------------------------------------------------------------
// fp16 HMMA GEMM:  C = A @ B^T + bias  (A [M,K] fp16, B [N,K] fp16)
//   Tile 128x128x32, 8 warps (4m x 2n), warp tile 32x64, cp.async dbl-buffer.
//   Smem rows padded to 80B: ldmatrix / cp.async stores are conflict-free.
// EPI: 0 = fp32 row-major, 1 = fp32 split-head, 2 = fp16 row-major
// ---------------------------------------------------------------------------
static constexpr int HROW   = 80;                 // bytes per 32-half row
static constexpr int HTILE  = 128 * HROW;         // 10240 per operand tile
static constexpr int HSTAGE = 2 * HTILE;          // A + B = 20480
static constexpr int HGEMM_SMEM = 2 * HSTAGE;     // 40960

template<int EPI>
__global__ __launch_bounds__(256)
void gemm_f16(const __half* __restrict__ A, const __half* __restrict__ B,
              const float* __restrict__ bias, float* __restrict__ C,
              __half* __restrict__ Ch, int M, int N, int K)
{
    extern __shared__ char smem[];
    const uint32_t sb = smem_u32(smem);
    const int tid  = threadIdx.x;
    const int wid  = tid >> 5, lid = tid & 31;
    const int wm   = wid >> 1, wn = wid & 1;
    const int m0   = blockIdx.y * 128, n0 = blockIdx.x * 128;

    const __half* Ab = A + (size_t)m0 * K;
    const __half* Bb = B + (size_t)n0 * K;

    auto load_stage = [&](int kc, int buf) {
        const uint32_t base = sb + buf * HSTAGE;
#pragma unroll
        for (int i = 0; i < 4; i++) {
            int c = tid + i * 256;              // 0..1023 16B chunks
            int op = c >> 9;                    // 0=A 1=B
            int rem = c & 511;
            int r = rem >> 2, q = rem & 3;
            const __half* s = (op ? Bb : Ab) + (size_t)r * K + kc * 32 + q * 8;
            cp16(base + op * HTILE + r * HROW + q * 16, s);
        }
    };

    float acc[2][8][4];
#pragma unroll
    for (int i = 0; i < 2; i++)
#pragma unroll
        for (int j = 0; j < 8; j++)
#pragma unroll
            for (int v = 0; v < 4; v++) acc[i][j][v] = 0.f;

    const int lr = lid & 15;
    const int lh = (lid >> 4) << 4;

    const int nk = K >> 5;
    load_stage(0, 0);
    CP_COMMIT();

    for (int kc = 0; kc < nk; kc++) {
        const int buf = kc & 1;
        if (kc + 1 < nk) { load_stage(kc + 1, buf ^ 1); CP_COMMIT(); CP_WAIT(1); }
        else             { CP_WAIT(0); }
        __syncthreads();

        const uint32_t base = sb + buf * HSTAGE;
        const uint32_t aB = base +         (wm * 32 + lr) * HROW + lh;
        const uint32_t bB = base + HTILE + (wn * 64 + lr) * HROW + lh;

#pragma unroll
        for (int ks = 0; ks < 2; ks++) {
            const uint32_t ko = ks * 32;
            uint32_t a[2][4];
#pragma unroll
            for (int mi = 0; mi < 2; mi++)
                LDSM_X4(a[mi][0], a[mi][1], a[mi][2], a[mi][3],
                        aB + mi * 16 * HROW + ko);
            uint32_t b[8][2];
#pragma unroll
            for (int np = 0; np < 4; np++) {
                uint32_t t0, t1, t2, t3;
                LDSM_X4(t0, t1, t2, t3, bB + np * 16 * HROW + ko);
                b[np * 2][0] = t0; b[np * 2][1] = t2;
                b[np * 2 + 1][0] = t1; b[np * 2 + 1][1] = t3;
            }
#pragma unroll
            for (int mi = 0; mi < 2; mi++)
#pragma unroll
                for (int nj = 0; nj < 8; nj++)
                    MMAF16(acc[mi][nj], a[mi][0], a[mi][1], a[mi][2], a[mi][3],
                           b[nj][0], b[nj][1]);
        }
        __syncthreads();
    }

#pragma unroll
    for (int mi = 0; mi < 2; mi++) {
#pragma unroll
        for (int nj = 0; nj < 8; nj++) {
            const int col = n0 + wn * 64 + nj * 8 + (lid & 3) * 2;
            const float2 bv = *reinterpret_cast<const float2*>(bias + col);
#pragma unroll
            for (int half_ = 0; half_ < 2; half_++) {
                const int row = m0 + wm * 32 + mi * 16 + (lid >> 2) + half_ * 8;
                float2 o;
                o.x = acc[mi][nj][half_ * 2 + 0] + bv.x;
                o.y = acc[mi][nj][half_ * 2 + 1] + bv.y;
                if (EPI == 0) {
                    *reinterpret_cast<float2*>(&C[(size_t)row * N + col]) = o;
                } else if (EPI == 1) {
                    int b = row >> 10, s = row & 1023, h = col >> 6, d = col & 63;
                    *reinterpret_cast<float2*>(
                        &C[(size_t)(((b * Hc + h) * Sc) + s) * HDc + d]) = o;
                } else {
                    *reinterpret_cast<uint32_t*>(&Ch[(size_t)row * N + col]) =
                        packh2(o.x, o.y);
                }
            }
        }
    }
}

// ---------------------------------------------------------------------------
// fp16 HMMA flash attention + exact fp32 memory-slot phase.
// Block = (b, h, 128-row q tile); 8 warps x 16 rows. Writes fp16 ctx.
// ---------------------------------------------------------------------------
static constexpr int ROWB = 144;                  // 64 fp16 + 16B pad
static constexpr int QREG = 128 * ROWB;           // 18432
static constexpr int KSTG = 2 * 64 * ROWB;        // K + V per stage: 18432
static constexpr int ATTN_SMEM = QREG + 2 * KSTG; // 55296

__global__ __launch_bounds__(256)
void attn_f16(const __half* __restrict__ qkvh,
              const float* __restrict__ pk, const float* __restrict__ pv,
              __half* __restrict__ ctxh)
{
    extern __shared__ char sm[];
    const uint32_t sb = smem_u32(sm);
    const int bid  = blockIdx.x;
    const int tile = 7 - (bid >> 6);
    const int h    = bid & 15;
    const int b    = (bid >> 4) & 3;
    const int tid  = threadIdx.x;
    const int wid  = tid >> 5, lid = tid & 31;

    const size_t qkv_row0 = (size_t)(b * Sc + tile * 128) * 3072;

    // ---- stage Q (128 rows x 64 fp16) ----
#pragma unroll
    for (int i = 0; i < 4; i++) {
        int c = tid + i * 256;                // 0..1023
        int r = c >> 3, o = (c & 7) * 16;
        cp16(sb + r * ROWB + o, qkvh + qkv_row0 + (size_t)r * 3072 + h * 64 + o / 2);
    }
    CP_COMMIT();

    const int nkt = 2 * tile + 2;
    auto load_stage = [&](int kt, int buf) {
        const uint32_t st = sb + QREG + buf * KSTG;
        const size_t row0 = (size_t)(b * Sc + kt * 64) * 3072;
#pragma unroll
        for (int i = 0; i < 4; i++) {
            int c = tid + i * 256;            // 0..1023
            int arr = c >> 9;                 // 0:K 1:V
            int rem = c & 511;
            int r = rem >> 3, o = (rem & 7) * 16;
            int colb = arr ? 2048 : 1024;
            cp16(st + arr * (64 * ROWB) + r * ROWB + o,
                 qkvh + row0 + (size_t)r * 3072 + colb + h * 64 + o / 2);
        }
    };
    load_stage(0, 0);
    CP_COMMIT();

    CP_WAIT(1);
    __syncthreads();
    uint32_t qf[16];
    {
        const uint32_t qbase = sb + (wid * 16 + (lid & 15)) * ROWB + ((lid >> 4) << 4);
#pragma unroll
        for (int kc = 0; kc < 4; kc++)
            LDSM_X4(qf[kc * 4 + 0], qf[kc * 4 + 1], qf[kc * 4 + 2], qf[kc * 4 + 3],
                    qbase + kc * 32);
    }
    __syncthreads();

    float o_acc[8][4];
#pragma unroll
    for (int j = 0; j < 8; j++)
#pragma unroll
        for (int v = 0; v < 4; v++) o_acc[j][v] = 0.f;
    float m0 = -1e30f, m1 = -1e30f, sr0 = 0.f, sr1 = 0.f;

    const int rA = tile * 128 + wid * 16 + (lid >> 2);
    const int diag = 2 * tile;

    for (int kt = 0; kt < nkt; kt++) {
        const int buf = kt & 1;
        if (kt + 1 < nkt) { load_stage(kt + 1, buf ^ 1); CP_COMMIT(); CP_WAIT(1); }
        else              { CP_WAIT(0); }
        __syncthreads();

        const uint32_t st = sb + QREG + buf * KSTG;
        const uint32_t Ks = st, Vs = st + 64 * ROWB;

        // ---- S = Q K^T ----
        float s[8][4];
#pragma unroll
        for (int j = 0; j < 8; j++)
#pragma unroll
            for (int v = 0; v < 4; v++) s[j][v] = 0.f;

#pragma unroll
        for (int np = 0; np < 4; np++) {
            const uint32_t krow = (np * 16 + ((lid >> 4) & 1) * 8 + (lid & 7)) * ROWB
                                + ((lid >> 3) & 1) * 16;
#pragma unroll
            for (int kc = 0; kc < 4; kc++) {
                uint32_t k0, k1, k2, k3;
                LDSM_X4(k0, k1, k2, k3, Ks + krow + kc * 32);
                const uint32_t* qa = qf + kc * 4;
                MMAF16(s[2 * np],     qa[0], qa[1], qa[2], qa[3], k0, k1);
                MMAF16(s[2 * np + 1], qa[0], qa[1], qa[2], qa[3], k2, k3);
            }
        }

        // ---- scale + causal mask ----
#pragma unroll
        for (int j = 0; j < 8; j++)
#pragma unroll
            for (int v = 0; v < 4; v++) s[j][v] *= 0.125f;
        if (kt >= diag) {
#pragma unroll
            for (int j = 0; j < 8; j++) {
                int c0 = kt * 64 + j * 8 + (lid & 3) * 2;
                if (c0     > rA)     s[j][0] = -1e30f;
                if (c0 + 1 > rA)     s[j][1] = -1e30f;
                if (c0     > rA + 8) s[j][2] = -1e30f;
                if (c0 + 1 > rA + 8) s[j][3] = -1e30f;
            }
        }

        // ---- online softmax ----
        float mx0 = -1e30f, mx1 = -1e30f;
#pragma unroll
        for (int j = 0; j < 8; j++) {
            mx0 = fmaxf(mx0, fmaxf(s[j][0], s[j][1]));
            mx1 = fmaxf(mx1, fmaxf(s[j][2], s[j][3]));
        }
        mx0 = fmaxf(mx0, __shfl_xor_sync(0xffffffffu, mx0, 1));
        mx0 = fmaxf(mx0, __shfl_xor_sync(0xffffffffu, mx0, 2));
        mx1 = fmaxf(mx1, __shfl_xor_sync(0xffffffffu, mx1, 1));
        mx1 = fmaxf(mx1, __shfl_xor_sync(0xffffffffu, mx1, 2));
        const float mn0 = fmaxf(m0, mx0), mn1 = fmaxf(m1, mx1);
        const float cr0 = __expf(m0 - mn0), cr1 = __expf(m1 - mn1);
        m0 = mn0; m1 = mn1;
        float ps0 = 0.f, ps1 = 0.f;
#pragma unroll
        for (int j = 0; j < 8; j++) {
            s[j][0] = __expf(s[j][0] - m0); ps0 += s[j][0];
            s[j][1] = __expf(s[j][1] - m0); ps0 += s[j][1];
            s[j][2] = __expf(s[j][2] - m1); ps1 += s[j][2];
            s[j][3] = __expf(s[j][3] - m1); ps1 += s[j][3];
        }
        ps0 += __shfl_xor_sync(0xffffffffu, ps0, 1);
        ps0 += __shfl_xor_sync(0xffffffffu, ps0, 2);
        ps1 += __shfl_xor_sync(0xffffffffu, ps1, 1);
        ps1 += __shfl_xor_sync(0xffffffffu, ps1, 2);
        sr0 = sr0 * cr0 + ps0;
        sr1 = sr1 * cr1 + ps1;
#pragma unroll
        for (int j = 0; j < 8; j++) {
            o_acc[j][0] *= cr0; o_acc[j][1] *= cr0;
            o_acc[j][2] *= cr1; o_acc[j][3] *= cr1;
        }

        // ---- O += P V ----
#pragma unroll
        for (int kc = 0; kc < 4; kc++) {
            uint32_t ph[4];
            ph[0] = packh2(s[2 * kc][0],     s[2 * kc][1]);
            ph[1] = packh2(s[2 * kc][2],     s[2 * kc][3]);
            ph[2] = packh2(s[2 * kc + 1][0], s[2 * kc + 1][1]);
            ph[3] = packh2(s[2 * kc + 1][2], s[2 * kc + 1][3]);
            const uint32_t vrow = (kc * 16 + ((lid >> 3) & 1) * 8 + (lid & 7)) * ROWB
                                + ((lid >> 4) & 1) * 16;
#pragma unroll
            for (int np = 0; np < 4; np++) {
                uint32_t v0, v1, v2, v3;
                LDSM_X4_T(v0, v1, v2, v3, Vs + vrow + np * 32);
                MMAF16(o_acc[2 * np],     ph[0], ph[1], ph[2], ph[3], v0, v1);
                MMAF16(o_acc[2 * np + 1], ph[0], ph[1], ph[2], ph[3], v2, v3);
            }
        }
        __syncthreads();
    }

    // ---- stage unnormalized O + stats to smem ----
    float* Os = reinterpret_cast<float*>(sm);           // [128][66]
    float* Ms = reinterpret_cast<float*>(sm + 33792);   // [128]
    float* Ss = Ms + 128;                               // [128]
    {
        const int ra = wid * 16 + (lid >> 2), rb = ra + 8;
#pragma unroll
        for (int j = 0; j < 8; j++) {
            const int col = j * 8 + (lid & 3) * 2;
            Os[ra * 66 + col]     = o_acc[j][0];
            Os[ra * 66 + col + 1] = o_acc[j][1];
            Os[rb * 66 + col]     = o_acc[j][2];
            Os[rb * 66 + col + 1] = o_acc[j][3];
        }
        if ((lid & 3) == 0) {
            Ms[ra] = m0; Ms[rb] = m1;
            Ss[ra] = sr0; Ss[rb] = sr1;
        }
    }
    __syncthreads();

    // ---- exact fp32 memory-slot phase: 2 threads per row ----
    {
        const int row = tid >> 1, half_ = tid & 1;
        const int rg = tile * 128 + row;
        float q[32];
        {
            const size_t qo = (size_t)(b * Sc + rg) * 3072 + h * 64 + half_ * 32;
            const __half2* qh2 = reinterpret_cast<const __half2*>(qkvh + qo);
#pragma unroll
            for (int i = 0; i < 16; i++) {
                float2 f = __half22float2(qh2[i]);
                q[2 * i + 0] = f.x * 0.125f;
                q[2 * i + 1] = f.y * 0.125f;
            }
        }
        float m = Ms[row], sr = Ss[row];
        float acc[32];
#pragma unroll
        for (int i = 0; i < 32; i++) acc[i] = Os[row * 66 + half_ * 32 + i];

        const size_t pbase = ((size_t)((b * Hc + h) * Sc + rg)) * (Lc * HDc) + half_ * 32;
        const float* pkb = pk + pbase;
        const float* pvb = pv + pbase;
#pragma unroll 1
        for (int l = 0; l < Lc; l++) {
            float d0 = 0.f;
#pragma unroll
            for (int i = 0; i < 8; i++) {
                float4 kk = *reinterpret_cast<const float4*>(pkb + l * 64 + i * 4);
                d0 = fmaf(q[i * 4 + 0], kk.x, d0);
                d0 = fmaf(q[i * 4 + 1], kk.y, d0);
                d0 = fmaf(q[i * 4 + 2], kk.z, d0);
                d0 = fmaf(q[i * 4 + 3], kk.w, d0);
            }
            d0 += __shfl_xor_sync(0xffffffffu, d0, 1);
            float mn = fmaxf(m, d0);
            float cr = __expf(m - mn);
            float p = __expf(d0 - mn);
            m = mn;
            sr = sr * cr + p;
#pragma unroll
            for (int i = 0; i < 32; i++) acc[i] *= cr;
            const float4* vv4 = reinterpret_cast<const float4*>(pvb + l * 64);
#pragma unroll
            for (int i = 0; i < 8; i++) {
                float4 vv = vv4[i];
                acc[i * 4 + 0] = fmaf(p, vv.x, acc[i * 4 + 0]);
                acc[i * 4 + 1] = fmaf(p, vv.y, acc[i * 4 + 1]);
                acc[i * 4 + 2] = fmaf(p, vv.z, acc[i * 4 + 2]);
                acc[i * 4 + 3] = fmaf(p, vv.w, acc[i * 4 + 3]);
            }
        }
        const float inv = 1.f / sr;
        // write fp16 ctx directly (A operand of the out-projection GEMM)
        __half2* cp = reinterpret_cast<__half2*>(
            ctxh + (size_t)(b * Sc + rg) * Dc + h * 64 + half_ * 32);
#pragma unroll
        for (int i = 0; i < 16; i++)
            cp[i] = __floats2half2_rn(acc[2 * i] * inv, acc[2 * i + 1] * inv);
    }
}

// ---------------------------------------------------------------------------
extern "C" void kernel_launch(void* const* d_in, const int* in_sizes, int n_in,
                              void* d_out, int out_size)
{
    const float* x     = (const float*)d_in[0];
    const float* pk    = (const float*)d_in[1];
    const float* pv    = (const float*)d_in[2];
    const float* w_qkv = (const float*)d_in[3];
    const float* b_qkv = (const float*)d_in[4];
    const float* w_k   = (const float*)d_in[5];
    const float* b_k   = (const float*)d_in[6];
    const float* w_v   = (const float*)d_in[7];
    const float* b_v   = (const float*)d_in[8];
    const float* w_o   = (const float*)d_in[9];
    const float* b_o   = (const float*)d_in[10];

    float* out  = (float*)d_out;
    float* kcol = out + (size_t)Bc * Sc * Dc;
    float* vcol = kcol + (size_t)Bc * Hc * Sc * HDc;

    static __half *Xh, *WqH, *WkH, *WvH, *WoH, *QKVH;
    static bool inited = false;
    if (!inited) {
        inited = true;
        cudaGetSymbolAddress((void**)&Xh, g_Xh);
        cudaGetSymbolAddress((void**)&WqH, g_WqH);
        cudaGetSymbolAddress((void**)&WkH, g_WkH);
        cudaGetSymbolAddress((void**)&WvH, g_WvH);
        cudaGetSymbolAddress((void**)&WoH, g_WoH);
        cudaGetSymbolAddress((void**)&QKVH, g_QKVH);
        cudaFuncSetAttribute(gemm_f16<0>,
                             cudaFuncAttributeMaxDynamicSharedMemorySize, HGEMM_SMEM);
        cudaFuncSetAttribute(gemm_f16<1>,
                             cudaFuncAttributeMaxDynamicSharedMemorySize, HGEMM_SMEM);
        cudaFuncSetAttribute(gemm_f16<2>,
                             cudaFuncAttributeMaxDynamicSharedMemorySize, HGEMM_SMEM);
        cudaFuncSetAttribute(attn_f16,
                             cudaFuncAttributeMaxDynamicSharedMemorySize, ATTN_SMEM);
    }

    // --- operand conversions (fp16) ---
    convert_f16<<<(BS * Dc / 4 + 255) / 256, 256>>>(x, Xh, BS * Dc / 4);
    convert_wT_f16<<<dim3(3 * Dc / 32, Dc / 32), dim3(32, 8)>>>(w_qkv, WqH, Dc, 3 * Dc);
    convert_wT_f16<<<dim3(Dc / 32, Dc / 32), dim3(32, 8)>>>(w_k, WkH, Dc, Dc);
    convert_wT_f16<<<dim3(Dc / 32, Dc / 32), dim3(32, 8)>>>(w_v, WvH, Dc, Dc);
    convert_wT_f16<<<dim3(Dc / 32, Dc / 32), dim3(32, 8)>>>(w_o, WoH, Dc, Dc);

    // --- projections (fp16 HMMA); qkv writes fp16 directly ---
    gemm_f16<2><<<dim3(3 * Dc / 128, BS / 128), 256, HGEMM_SMEM>>>(
        Xh, WqH, b_qkv, nullptr, QKVH, BS, 3 * Dc, Dc);
    gemm_f16<1><<<dim3(Dc / 128, BS / 128), 256, HGEMM_SMEM>>>(
        Xh, WkH, b_k, kcol, nullptr, BS, Dc, Dc);
    gemm_f16<1><<<dim3(Dc / 128, BS / 128), 256, HGEMM_SMEM>>>(
        Xh, WvH, b_v, vcol, nullptr, BS, Dc, Dc);

    // --- fp16 flash attention + exact memory-slot merge (writes fp16 ctx) ---
    attn_f16<<<512, 256, ATTN_SMEM>>>(QKVH, pk, pv, Xh);

    // --- output projection ---
    gemm_f16<0><<<dim3(Dc / 128, BS / 128), 256, HGEMM_SMEM>>>(
        Xh, WoH, b_o, out, nullptr, BS, Dc, Dc);
}

// round 8
// speedup vs baseline: 6.1280x; 1.1725x over previous
#include <cuda_runtime.h>
#include <cuda_fp16.h>
#include <cstdint>
#include <math.h>

// Problem constants
static constexpr int Bc  = 4;
static constexpr int Sc  = 1024;
static constexpr int Dc  = 1024;
static constexpr int Hc  = 16;
static constexpr int HDc = 64;
static constexpr int Lc  = 12;
static constexpr int BS  = Bc * Sc;       // 4096 rows

// ---------------------------------------------------------------------------
// Scratch (__device__ globals; no cudaMalloc allowed)
// ---------------------------------------------------------------------------
__device__ __half g_Xh[(size_t)BS * Dc];          // fp16 A operand (x, later ctx)
__device__ __half g_WH[(size_t)5 * Dc * Dc];      // [wqkv^T; wk^T; wv^T] fp16 [5120,1024]
__device__ __half g_WoH[(size_t)Dc * Dc];         // w_o^T fp16
__device__ __half g_QKVH[(size_t)BS * 3 * Dc];    // qkv fp16 (attn operands)

// ---------------------------------------------------------------------------
// PTX helpers (base-PTX only: cp.async / ldmatrix / mma.sync)
// ---------------------------------------------------------------------------
__device__ __forceinline__ uint32_t smem_u32(const void* p) {
    uint32_t a;
    asm("{ .reg .u64 t; cvta.to.shared.u64 t, %1; cvt.u32.u64 %0, t; }"
        : "=r"(a) : "l"(p));
    return a;
}

__device__ __forceinline__ void cp16(uint32_t saddr, const void* gaddr) {
    asm volatile("cp.async.cg.shared.global [%0], [%1], 16;"
                 :: "r"(saddr), "l"(gaddr));
}
#define CP_COMMIT() asm volatile("cp.async.commit_group;" ::: "memory")
#define CP_WAIT(n)  asm volatile("cp.async.wait_group %0;" :: "n"(n) : "memory")

#define LDSM_X4(r0, r1, r2, r3, addr) \
    asm volatile("ldmatrix.sync.aligned.m8n8.x4.shared.b16 {%0,%1,%2,%3}, [%4];" \
                 : "=r"(r0), "=r"(r1), "=r"(r2), "=r"(r3) : "r"(addr))

#define LDSM_X4_T(r0, r1, r2, r3, addr) \
    asm volatile("ldmatrix.sync.aligned.m8n8.x4.trans.shared.b16 {%0,%1,%2,%3}, [%4];" \
                 : "=r"(r0), "=r"(r1), "=r"(r2), "=r"(r3) : "r"(addr))

#define MMAF16(d, a0, a1, a2, a3, b0, b1) \
    asm volatile("mma.sync.aligned.m16n8k16.row.col.f32.f16.f16.f32 " \
                 "{%0,%1,%2,%3}, {%4,%5,%6,%7}, {%8,%9}, {%0,%1,%2,%3};" \
                 : "+f"((d)[0]), "+f"((d)[1]), "+f"((d)[2]), "+f"((d)[3]) \
                 : "r"(a0), "r"(a1), "r"(a2), "r"(a3), "r"(b0), "r"(b1))

__device__ __forceinline__ uint32_t packh2(float a, float b) {
    __half2 h = __floats2half2_rn(a, b);
    return *reinterpret_cast<uint32_t*>(&h);
}

// ---------------------------------------------------------------------------
// Mega-convert: blocks [0,1024): x -> fp16 elementwise
//               blocks [1024,..): 32x32 transpose tiles of the four weights
// ---------------------------------------------------------------------------
__global__ __launch_bounds__(256)
void convert_all(const float* __restrict__ x,
                 const float* __restrict__ w_qkv, const float* __restrict__ w_k,
                 const float* __restrict__ w_v,  const float* __restrict__ w_o,
                 __half* __restrict__ Xh, __half* __restrict__ WH,
                 __half* __restrict__ WoH)
{
    const int tx = threadIdx.x, ty = threadIdx.y;      // (32, 8)
    const int tid = ty * 32 + tx;
    const int bid = blockIdx.x;

    if (bid < 1024) {
        // elementwise x -> Xh: 1M float4 over 262144 threads, 4 each
        const int idx = bid * 256 + tid;
#pragma unroll
        for (int j = 0; j < 4; j++) {
            int i = idx + j * 262144;
            float4 v = reinterpret_cast<const float4*>(x)[i];
            __half2 h01 = __floats2half2_rn(v.x, v.y);
            __half2 h23 = __floats2half2_rn(v.z, v.w);
            reinterpret_cast<__half2*>(Xh)[2 * i + 0] = h01;
            reinterpret_cast<__half2*>(Xh)[2 * i + 1] = h23;
        }
        return;
    }

    // transpose tiles
    int t = bid - 1024;
    const float* W;
    __half* T;
    int N, tilesx;
    if (t < 3072)      { W = w_qkv; T = WH;                N = 3072; tilesx = 96; }
    else if (t < 4096) { W = w_k;   T = WH + 3072 * 1024;  N = 1024; tilesx = 32; t -= 3072; }
    else if (t < 5120) { W = w_v;   T = WH + 4096 * 1024;  N = 1024; tilesx = 32; t -= 4096; }
    else               { W = w_o;   T = WoH;               N = 1024; tilesx = 32; t -= 5120; }
    const int n0 = (t % tilesx) * 32;
    const int k0 = (t / tilesx) * 32;
    const int K = 1024;

    __shared__ float tt[32][33];
#pragma unroll
    for (int i = 0; i < 4; i++)
        tt[ty + i * 8][tx] = W[(size_t)(k0 + ty + i * 8) * N + n0 + tx];
    __syncthreads();
#pragma unroll
    for (int i = 0; i < 4; i++) {
        int n = n0 + ty + i * 8;
        T[(size_t)n * K + k0 + tx] = __float2half_rn(tt[tx][ty + i * 8]);
    }
}

// ---------------------------------------------------------------------------
// fp16 HMMA GEMM core: tile 128x128x64, 8 warps (4m x 2n), cp.async 2-stage.
// 144B rows (64 halfs + 16B pad): conflict-free ldmatrix / cp.async.
// ---------------------------------------------------------------------------
static constexpr int HROW   = 144;
static constexpr int HTILE  = 128 * HROW;         // 18432 per operand tile
static constexpr int HSTAGE = 2 * HTILE;          // A + B = 36864
static constexpr int HGEMM_SMEM = 2 * HSTAGE;     // 73728

// Computes acc for this block; A [M,K] from Ab(row m0), B row-block at Bb(n0).
// K = 1024 fixed.
__device__ __forceinline__ void gemm_core(const __half* Ab, const __half* Bb,
                                          char* smem, uint32_t sb,
                                          int tid, int wm, int wn, int lid,
                                          float acc[2][8][4])
{
    constexpr int K = 1024;
    auto load_stage = [&](int kc, int buf) {
        const uint32_t base = sb + buf * HSTAGE;
#pragma unroll
        for (int i = 0; i < 8; i++) {
            int c = tid + i * 256;              // 0..2047 16B chunks
            int op = c >> 10;                   // 0=A 1=B
            int rem = c & 1023;
            int r = rem >> 3, q = rem & 7;
            const __half* s = (op ? Bb : Ab) + (size_t)r * K + kc * 64 + q * 8;
            cp16(base + op * HTILE + r * HROW + q * 16, s);
        }
    };

    const int lr = lid & 15;
    const int lh = (lid >> 4) << 4;

    load_stage(0, 0);
    CP_COMMIT();

    constexpr int nk = K >> 6;                   // 16
    for (int kc = 0; kc < nk; kc++) {
        const int buf = kc & 1;
        if (kc + 1 < nk) { load_stage(kc + 1, buf ^ 1); CP_COMMIT(); CP_WAIT(1); }
        else             { CP_WAIT(0); }
        __syncthreads();

        const uint32_t base = sb + buf * HSTAGE;
        const uint32_t aB = base +         (wm * 32 + lr) * HROW + lh;
        const uint32_t bB = base + HTILE + (wn * 64 + lr) * HROW + lh;

#pragma unroll
        for (int ks = 0; ks < 4; ks++) {
            const uint32_t ko = ks * 32;
            uint32_t a[2][4];
#pragma unroll
            for (int mi = 0; mi < 2; mi++)
                LDSM_X4(a[mi][0], a[mi][1], a[mi][2], a[mi][3],
                        aB + mi * 16 * HROW + ko);
            uint32_t b[8][2];
#pragma unroll
            for (int np = 0; np < 4; np++) {
                uint32_t t0, t1, t2, t3;
                LDSM_X4(t0, t1, t2, t3, bB + np * 16 * HROW + ko);
                b[np * 2][0] = t0; b[np * 2][1] = t2;
                b[np * 2 + 1][0] = t1; b[np * 2 + 1][1] = t3;
            }
#pragma unroll
            for (int mi = 0; mi < 2; mi++)
#pragma unroll
                for (int nj = 0; nj < 8; nj++)
                    MMAF16(acc[mi][nj], a[mi][0], a[mi][1], a[mi][2], a[mi][3],
                           b[nj][0], b[nj][1]);
        }
        __syncthreads();
    }
}

// ---------------------------------------------------------------------------
// Fused projection GEMM: A = Xh [4096,1024], B = WH [5120,1024].
// n0 <  3072 : qkv  -> fp16 QKVH [4096,3072]
// n0 in [3072,4096): k_col -> fp32 split-head kcol
// n0 >= 4096 : v_col -> fp32 split-head vcol
// ---------------------------------------------------------------------------
__global__ __launch_bounds__(256)
void gemm_fused(const __half* __restrict__ A, const __half* __restrict__ B,
                const float* __restrict__ b_qkv, const float* __restrict__ b_k,
                const float* __restrict__ b_v,
                __half* __restrict__ QKVH, float* __restrict__ kcol,
                float* __restrict__ vcol)
{
    extern __shared__ char smem[];
    const uint32_t sb = smem_u32(smem);
    const int tid = threadIdx.x;
    const int wid = tid >> 5, lid = tid & 31;
    const int wm  = wid >> 1, wn = wid & 1;
    const int m0  = blockIdx.y * 128, n0 = blockIdx.x * 128;

    float acc[2][8][4];
#pragma unroll
    for (int i = 0; i < 2; i++)
#pragma unroll
        for (int j = 0; j < 8; j++)
#pragma unroll
            for (int v = 0; v < 4; v++) acc[i][j][v] = 0.f;

    gemm_core(A + (size_t)m0 * 1024, B + (size_t)n0 * 1024,
              smem, sb, tid, wm, wn, lid, acc);

    const int seg = (n0 < 3072) ? 0 : (n0 < 4096 ? 1 : 2);
    const float* bias = (seg == 0) ? b_qkv : (seg == 1 ? b_k : b_v);
    const int segbase = (seg == 0) ? 0 : (seg == 1 ? 3072 : 4096);

#pragma unroll
    for (int mi = 0; mi < 2; mi++) {
#pragma unroll
        for (int nj = 0; nj < 8; nj++) {
            const int col = n0 + wn * 64 + nj * 8 + (lid & 3) * 2;
            const int c = col - segbase;
            const float2 bv = *reinterpret_cast<const float2*>(bias + c);
#pragma unroll
            for (int half_ = 0; half_ < 2; half_++) {
                const int row = m0 + wm * 32 + mi * 16 + (lid >> 2) + half_ * 8;
                float2 o;
                o.x = acc[mi][nj][half_ * 2 + 0] + bv.x;
                o.y = acc[mi][nj][half_ * 2 + 1] + bv.y;
                if (seg == 0) {
                    *reinterpret_cast<uint32_t*>(&QKVH[(size_t)row * 3072 + c]) =
                        packh2(o.x, o.y);
                } else {
                    float* dst = (seg == 1) ? kcol : vcol;
                    int b = row >> 10, s = row & 1023, h = c >> 6, d = c & 63;
                    *reinterpret_cast<float2*>(
                        &dst[(size_t)(((b * Hc + h) * Sc) + s) * HDc + d]) = o;
                }
            }
        }
    }
}

// ---------------------------------------------------------------------------
// Output projection GEMM: fp32 row-major out
// ---------------------------------------------------------------------------
__global__ __launch_bounds__(256)
void gemm_out(const __half* __restrict__ A, const __half* __restrict__ B,
              const float* __restrict__ bias, float* __restrict__ C)
{
    extern __shared__ char smem[];
    const uint32_t sb = smem_u32(smem);
    const int tid = threadIdx.x;
    const int wid = tid >> 5, lid = tid & 31;
    const int wm  = wid >> 1, wn = wid & 1;
    const int m0  = blockIdx.y * 128, n0 = blockIdx.x * 128;

    float acc[2][8][4];
#pragma unroll
    for (int i = 0; i < 2; i++)
#pragma unroll
        for (int j = 0; j < 8; j++)
#pragma unroll
            for (int v = 0; v < 4; v++) acc[i][j][v] = 0.f;

    gemm_core(A + (size_t)m0 * 1024, B + (size_t)n0 * 1024,
              smem, sb, tid, wm, wn, lid, acc);

#pragma unroll
    for (int mi = 0; mi < 2; mi++) {
#pragma unroll
        for (int nj = 0; nj < 8; nj++) {
            const int col = n0 + wn * 64 + nj * 8 + (lid & 3) * 2;
            const float2 bv = *reinterpret_cast<const float2*>(bias + col);
#pragma unroll
            for (int half_ = 0; half_ < 2; half_++) {
                const int row = m0 + wm * 32 + mi * 16 + (lid >> 2) + half_ * 8;
                float2 o;
                o.x = acc[mi][nj][half_ * 2 + 0] + bv.x;
                o.y = acc[mi][nj][half_ * 2 + 1] + bv.y;
                *reinterpret_cast<float2*>(&C[(size_t)row * Dc + col]) = o;
            }
        }
    }
}

// ---------------------------------------------------------------------------
// fp16 HMMA flash attention + exact fp32 memory-slot phase (unchanged R7).
// ---------------------------------------------------------------------------
static constexpr int ROWB = 144;                  // 64 fp16 + 16B pad
static constexpr int QREG = 128 * ROWB;           // 18432
static constexpr int KSTG = 2 * 64 * ROWB;        // K + V per stage: 18432
static constexpr int ATTN_SMEM = QREG + 2 * KSTG; // 55296

__global__ __launch_bounds__(256)
void attn_f16(const __half* __restrict__ qkvh,
              const float* __restrict__ pk, const float* __restrict__ pv,
              __half* __restrict__ ctxh)
{
    extern __shared__ char sm[];
    const uint32_t sb = smem_u32(sm);
    const int bid  = blockIdx.x;
    const int tile = 7 - (bid >> 6);
    const int h    = bid & 15;
    const int b    = (bid >> 4) & 3;
    const int tid  = threadIdx.x;
    const int wid  = tid >> 5, lid = tid & 31;

    const size_t qkv_row0 = (size_t)(b * Sc + tile * 128) * 3072;

#pragma unroll
    for (int i = 0; i < 4; i++) {
        int c = tid + i * 256;
        int r = c >> 3, o = (c & 7) * 16;
        cp16(sb + r * ROWB + o, qkvh + qkv_row0 + (size_t)r * 3072 + h * 64 + o / 2);
    }
    CP_COMMIT();

    const int nkt = 2 * tile + 2;
    auto load_stage = [&](int kt, int buf) {
        const uint32_t st = sb + QREG + buf * KSTG;
        const size_t row0 = (size_t)(b * Sc + kt * 64) * 3072;
#pragma unroll
        for (int i = 0; i < 4; i++) {
            int c = tid + i * 256;
            int arr = c >> 9;
            int rem = c & 511;
            int r = rem >> 3, o = (rem & 7) * 16;
            int colb = arr ? 2048 : 1024;
            cp16(st + arr * (64 * ROWB) + r * ROWB + o,
                 qkvh + row0 + (size_t)r * 3072 + colb + h * 64 + o / 2);
        }
    };
    load_stage(0, 0);
    CP_COMMIT();

    CP_WAIT(1);
    __syncthreads();
    uint32_t qf[16];
    {
        const uint32_t qbase = sb + (wid * 16 + (lid & 15)) * ROWB + ((lid >> 4) << 4);
#pragma unroll
        for (int kc = 0; kc < 4; kc++)
            LDSM_X4(qf[kc * 4 + 0], qf[kc * 4 + 1], qf[kc * 4 + 2], qf[kc * 4 + 3],
                    qbase + kc * 32);
    }
    __syncthreads();

    float o_acc[8][4];
#pragma unroll
    for (int j = 0; j < 8; j++)
#pragma unroll
        for (int v = 0; v < 4; v++) o_acc[j][v] = 0.f;
    float m0 = -1e30f, m1 = -1e30f, sr0 = 0.f, sr1 = 0.f;

    const int rA = tile * 128 + wid * 16 + (lid >> 2);
    const int diag = 2 * tile;

    for (int kt = 0; kt < nkt; kt++) {
        const int buf = kt & 1;
        if (kt + 1 < nkt) { load_stage(kt + 1, buf ^ 1); CP_COMMIT(); CP_WAIT(1); }
        else              { CP_WAIT(0); }
        __syncthreads();

        const uint32_t st = sb + QREG + buf * KSTG;
        const uint32_t Ks = st, Vs = st + 64 * ROWB;

        float s[8][4];
#pragma unroll
        for (int j = 0; j < 8; j++)
#pragma unroll
            for (int v = 0; v < 4; v++) s[j][v] = 0.f;

#pragma unroll
        for (int np = 0; np < 4; np++) {
            const uint32_t krow = (np * 16 + ((lid >> 4) & 1) * 8 + (lid & 7)) * ROWB
                                + ((lid >> 3) & 1) * 16;
#pragma unroll
            for (int kc = 0; kc < 4; kc++) {
                uint32_t k0, k1, k2, k3;
                LDSM_X4(k0, k1, k2, k3, Ks + krow + kc * 32);
                const uint32_t* qa = qf + kc * 4;
                MMAF16(s[2 * np],     qa[0], qa[1], qa[2], qa[3], k0, k1);
                MMAF16(s[2 * np + 1], qa[0], qa[1], qa[2], qa[3], k2, k3);
            }
        }

#pragma unroll
        for (int j = 0; j < 8; j++)
#pragma unroll
            for (int v = 0; v < 4; v++) s[j][v] *= 0.125f;
        if (kt >= diag) {
#pragma unroll
            for (int j = 0; j < 8; j++) {
                int c0 = kt * 64 + j * 8 + (lid & 3) * 2;
                if (c0     > rA)     s[j][0] = -1e30f;
                if (c0 + 1 > rA)     s[j][1] = -1e30f;
                if (c0     > rA + 8) s[j][2] = -1e30f;
                if (c0 + 1 > rA + 8) s[j][3] = -1e30f;
            }
        }

        float mx0 = -1e30f, mx1 = -1e30f;
#pragma unroll
        for (int j = 0; j < 8; j++) {
            mx0 = fmaxf(mx0, fmaxf(s[j][0], s[j][1]));
            mx1 = fmaxf(mx1, fmaxf(s[j][2], s[j][3]));
        }
        mx0 = fmaxf(mx0, __shfl_xor_sync(0xffffffffu, mx0, 1));
        mx0 = fmaxf(mx0, __shfl_xor_sync(0xffffffffu, mx0, 2));
        mx1 = fmaxf(mx1, __shfl_xor_sync(0xffffffffu, mx1, 1));
        mx1 = fmaxf(mx1, __shfl_xor_sync(0xffffffffu, mx1, 2));
        const float mn0 = fmaxf(m0, mx0), mn1 = fmaxf(m1, mx1);
        const float cr0 = __expf(m0 - mn0), cr1 = __expf(m1 - mn1);
        m0 = mn0; m1 = mn1;
        float ps0 = 0.f, ps1 = 0.f;
#pragma unroll
        for (int j = 0; j < 8; j++) {
            s[j][0] = __expf(s[j][0] - m0); ps0 += s[j][0];
            s[j][1] = __expf(s[j][1] - m0); ps0 += s[j][1];
            s[j][2] = __expf(s[j][2] - m1); ps1 += s[j][2];
            s[j][3] = __expf(s[j][3] - m1); ps1 += s[j][3];
        }
        ps0 += __shfl_xor_sync(0xffffffffu, ps0, 1);
        ps0 += __shfl_xor_sync(0xffffffffu, ps0, 2);
        ps1 += __shfl_xor_sync(0xffffffffu, ps1, 1);
        ps1 += __shfl_xor_sync(0xffffffffu, ps1, 2);
        sr0 = sr0 * cr0 + ps0;
        sr1 = sr1 * cr1 + ps1;
#pragma unroll
        for (int j = 0; j < 8; j++) {
            o_acc[j][0] *= cr0; o_acc[j][1] *= cr0;
            o_acc[j][2] *= cr1; o_acc[j][3] *= cr1;
        }

#pragma unroll
        for (int kc = 0; kc < 4; kc++) {
            uint32_t ph[4];
            ph[0] = packh2(s[2 * kc][0],     s[2 * kc][1]);
            ph[1] = packh2(s[2 * kc][2],     s[2 * kc][3]);
            ph[2] = packh2(s[2 * kc + 1][0], s[2 * kc + 1][1]);
            ph[3] = packh2(s[2 * kc + 1][2], s[2 * kc + 1][3]);
            const uint32_t vrow = (kc * 16 + ((lid >> 3) & 1) * 8 + (lid & 7)) * ROWB
                                + ((lid >> 4) & 1) * 16;
#pragma unroll
            for (int np = 0; np < 4; np++) {
                uint32_t v0, v1, v2, v3;
                LDSM_X4_T(v0, v1, v2, v3, Vs + vrow + np * 32);
                MMAF16(o_acc[2 * np],     ph[0], ph[1], ph[2], ph[3], v0, v1);
                MMAF16(o_acc[2 * np + 1], ph[0], ph[1], ph[2], ph[3], v2, v3);
            }
        }
        __syncthreads();
    }

    float* Os = reinterpret_cast<float*>(sm);           // [128][66]
    float* Ms = reinterpret_cast<float*>(sm + 33792);   // [128]
    float* Ss = Ms + 128;                               // [128]
    {
        const int ra = wid * 16 + (lid >> 2), rb = ra + 8;
#pragma unroll
        for (int j = 0; j < 8; j++) {
            const int col = j * 8 + (lid & 3) * 2;
            Os[ra * 66 + col]     = o_acc[j][0];
            Os[ra * 66 + col + 1] = o_acc[j][1];
            Os[rb * 66 + col]     = o_acc[j][2];
            Os[rb * 66 + col + 1] = o_acc[j][3];
        }
        if ((lid & 3) == 0) {
            Ms[ra] = m0; Ms[rb] = m1;
            Ss[ra] = sr0; Ss[rb] = sr1;
        }
    }
    __syncthreads();

    {
        const int row = tid >> 1, half_ = tid & 1;
        const int rg = tile * 128 + row;
        float q[32];
        {
            const size_t qo = (size_t)(b * Sc + rg) * 3072 + h * 64 + half_ * 32;
            const __half2* qh2 = reinterpret_cast<const __half2*>(qkvh + qo);
#pragma unroll
            for (int i = 0; i < 16; i++) {
                float2 f = __half22float2(qh2[i]);
                q[2 * i + 0] = f.x * 0.125f;
                q[2 * i + 1] = f.y * 0.125f;
            }
        }
        float m = Ms[row], sr = Ss[row];
        float acc[32];
#pragma unroll
        for (int i = 0; i < 32; i++) acc[i] = Os[row * 66 + half_ * 32 + i];

        const size_t pbase = ((size_t)((b * Hc + h) * Sc + rg)) * (Lc * HDc) + half_ * 32;
        const float* pkb = pk + pbase;
        const float* pvb = pv + pbase;
#pragma unroll 1
        for (int l = 0; l < Lc; l++) {
            float d0 = 0.f;
#pragma unroll
            for (int i = 0; i < 8; i++) {
                float4 kk = *reinterpret_cast<const float4*>(pkb + l * 64 + i * 4);
                d0 = fmaf(q[i * 4 + 0], kk.x, d0);
                d0 = fmaf(q[i * 4 + 1], kk.y, d0);
                d0 = fmaf(q[i * 4 + 2], kk.z, d0);
                d0 = fmaf(q[i * 4 + 3], kk.w, d0);
            }
            d0 += __shfl_xor_sync(0xffffffffu, d0, 1);
            float mn = fmaxf(m, d0);
            float cr = __expf(m - mn);
            float p = __expf(d0 - mn);
            m = mn;
            sr = sr * cr + p;
#pragma unroll
            for (int i = 0; i < 32; i++) acc[i] *= cr;
            const float4* vv4 = reinterpret_cast<const float4*>(pvb + l * 64);
#pragma unroll
            for (int i = 0; i < 8; i++) {
                float4 vv = vv4[i];
                acc[i * 4 + 0] = fmaf(p, vv.x, acc[i * 4 + 0]);
                acc[i * 4 + 1] = fmaf(p, vv.y, acc[i * 4 + 1]);
                acc[i * 4 + 2] = fmaf(p, vv.z, acc[i * 4 + 2]);
                acc[i * 4 + 3] = fmaf(p, vv.w, acc[i * 4 + 3]);
            }
        }
        const float inv = 1.f / sr;
        __half2* cp = reinterpret_cast<__half2*>(
            ctxh + (size_t)(b * Sc + rg) * Dc + h * 64 + half_ * 32);
#pragma unroll
        for (int i = 0; i < 16; i++)
            cp[i] = __floats2half2_rn(acc[2 * i] * inv, acc[2 * i + 1] * inv);
    }
}

// ---------------------------------------------------------------------------
extern "C" void kernel_launch(void* const* d_in, const int* in_sizes, int n_in,
                              void* d_out, int out_size)
{
    const float* x     = (const float*)d_in[0];
    const float* pk    = (const float*)d_in[1];
    const float* pv    = (const float*)d_in[2];
    const float* w_qkv = (const float*)d_in[3];
    const float* b_qkv = (const float*)d_in[4];
    const float* w_k   = (const float*)d_in[5];
    const float* b_k   = (const float*)d_in[6];
    const float* w_v   = (const float*)d_in[7];
    const float* b_v   = (const float*)d_in[8];
    const float* w_o   = (const float*)d_in[9];
    const float* b_o   = (const float*)d_in[10];

    float* out  = (float*)d_out;
    float* kcol = out + (size_t)Bc * Sc * Dc;
    float* vcol = kcol + (size_t)Bc * Hc * Sc * HDc;

    static __half *Xh, *WH, *WoH, *QKVH;
    static bool inited = false;
    if (!inited) {
        inited = true;
        cudaGetSymbolAddress((void**)&Xh, g_Xh);
        cudaGetSymbolAddress((void**)&WH, g_WH);
        cudaGetSymbolAddress((void**)&WoH, g_WoH);
        cudaGetSymbolAddress((void**)&QKVH, g_QKVH);
        cudaFuncSetAttribute(gemm_fused,
                             cudaFuncAttributeMaxDynamicSharedMemorySize, HGEMM_SMEM);
        cudaFuncSetAttribute(gemm_out,
                             cudaFuncAttributeMaxDynamicSharedMemorySize, HGEMM_SMEM);
        cudaFuncSetAttribute(attn_f16,
                             cudaFuncAttributeMaxDynamicSharedMemorySize, ATTN_SMEM);
    }

    // --- all operand conversions in one launch ---
    convert_all<<<7168, dim3(32, 8)>>>(x, w_qkv, w_k, w_v, w_o, Xh, WH, WoH);

    // --- fused qkv + k_col + v_col projection (one GEMM, N=5120) ---
    gemm_fused<<<dim3(40, 32), 256, HGEMM_SMEM>>>(
        Xh, WH, b_qkv, b_k, b_v, QKVH, kcol, vcol);

    // --- fp16 flash attention + exact memory-slot merge (writes fp16 ctx) ---
    attn_f16<<<512, 256, ATTN_SMEM>>>(QKVH, pk, pv, Xh);

    // --- output projection ---
    gemm_out<<<dim3(8, 32), 256, HGEMM_SMEM>>>(Xh, WoH, b_o, out);
}

// round 10
// speedup vs baseline: 6.2018x; 1.0121x over previous
#include <cuda_runtime.h>
#include <cuda_fp16.h>
#include <cstdint>
#include <math.h>

// Problem constants
static constexpr int Bc  = 4;
static constexpr int Sc  = 1024;
static constexpr int Dc  = 1024;
static constexpr int Hc  = 16;
static constexpr int HDc = 64;
static constexpr int Lc  = 12;
static constexpr int BS  = Bc * Sc;       // 4096 rows

// ---------------------------------------------------------------------------
// Scratch (__device__ globals; no cudaMalloc allowed)
// ---------------------------------------------------------------------------
__device__ __half g_Xh[(size_t)BS * Dc];          // fp16 x operand
__device__ __half g_CtxH[(size_t)BS * Dc];        // fp16 ctx (attn output)
__device__ __half g_WH[(size_t)5 * Dc * Dc];      // [wqkv^T; wk^T; wv^T] fp16 [5120,1024]
__device__ __half g_WoH[(size_t)Dc * Dc];         // w_o^T fp16
__device__ __half g_QKVH[(size_t)BS * 3 * Dc];    // qkv fp16 (attn operands)

// ---------------------------------------------------------------------------
// PTX helpers (base-PTX only: cp.async / ldmatrix / mma.sync)
// ---------------------------------------------------------------------------
__device__ __forceinline__ uint32_t smem_u32(const void* p) {
    uint32_t a;
    asm("{ .reg .u64 t; cvta.to.shared.u64 t, %1; cvt.u32.u64 %0, t; }"
        : "=r"(a) : "l"(p));
    return a;
}

__device__ __forceinline__ void cp16(uint32_t saddr, const void* gaddr) {
    asm volatile("cp.async.cg.shared.global [%0], [%1], 16;"
                 :: "r"(saddr), "l"(gaddr));
}
#define CP_COMMIT() asm volatile("cp.async.commit_group;" ::: "memory")
#define CP_WAIT(n)  asm volatile("cp.async.wait_group %0;" :: "n"(n) : "memory")

#define LDSM_X4(r0, r1, r2, r3, addr) \
    asm volatile("ldmatrix.sync.aligned.m8n8.x4.shared.b16 {%0,%1,%2,%3}, [%4];" \
                 : "=r"(r0), "=r"(r1), "=r"(r2), "=r"(r3) : "r"(addr))

#define LDSM_X4_T(r0, r1, r2, r3, addr) \
    asm volatile("ldmatrix.sync.aligned.m8n8.x4.trans.shared.b16 {%0,%1,%2,%3}, [%4];" \
                 : "=r"(r0), "=r"(r1), "=r"(r2), "=r"(r3) : "r"(addr))

#define MMAF16(d, a0, a1, a2, a3, b0, b1) \
    asm volatile("mma.sync.aligned.m16n8k16.row.col.f32.f16.f16.f32 " \
                 "{%0,%1,%2,%3}, {%4,%5,%6,%7}, {%8,%9}, {%0,%1,%2,%3};" \
                 : "+f"((d)[0]), "+f"((d)[1]), "+f"((d)[2]), "+f"((d)[3]) \
                 : "r"(a0), "r"(a1), "r"(a2), "r"(a3), "r"(b0), "r"(b1))

__device__ __forceinline__ uint32_t packh2(float a, float b) {
    __half2 h = __floats2half2_rn(a, b);
    return *reinterpret_cast<uint32_t*>(&h);
}

// ---------------------------------------------------------------------------
// Mega-convert: blocks [0,1024): x -> fp16 elementwise
//               blocks [1024,..): 32x32 transpose tiles of the four weights
// ---------------------------------------------------------------------------
__global__ __launch_bounds__(256)
void convert_all(const float* __restrict__ x,
                 const float* __restrict__ w_qkv, const float* __restrict__ w_k,
                 const float* __restrict__ w_v,  const float* __restrict__ w_o,
                 __half* __restrict__ Xh, __half* __restrict__ WH,
                 __half* __restrict__ WoH)
{
    const int tx = threadIdx.x, ty = threadIdx.y;      // (32, 8)
    const int tid = ty * 32 + tx;
    const int bid = blockIdx.x;

    if (bid < 1024) {
        const int idx = bid * 256 + tid;
#pragma unroll
        for (int j = 0; j < 4; j++) {
            int i = idx + j * 262144;
            float4 v = reinterpret_cast<const float4*>(x)[i];
            __half2 h01 = __floats2half2_rn(v.x, v.y);
            __half2 h23 = __floats2half2_rn(v.z, v.w);
            reinterpret_cast<__half2*>(Xh)[2 * i + 0] = h01;
            reinterpret_cast<__half2*>(Xh)[2 * i + 1] = h23;
        }
        return;
    }

    int t = bid - 1024;
    const float* W;
    __half* T;
    int N, tilesx;
    if (t < 3072)      { W = w_qkv; T = WH;                N = 3072; tilesx = 96; }
    else if (t < 4096) { W = w_k;   T = WH + 3072 * 1024;  N = 1024; tilesx = 32; t -= 3072; }
    else if (t < 5120) { W = w_v;   T = WH + 4096 * 1024;  N = 1024; tilesx = 32; t -= 4096; }
    else               { W = w_o;   T = WoH;               N = 1024; tilesx = 32; t -= 5120; }
    const int n0 = (t % tilesx) * 32;
    const int k0 = (t / tilesx) * 32;
    const int K = 1024;

    __shared__ float tt[32][33];
#pragma unroll
    for (int i = 0; i < 4; i++)
        tt[ty + i * 8][tx] = W[(size_t)(k0 + ty + i * 8) * N + n0 + tx];
    __syncthreads();
#pragma unroll
    for (int i = 0; i < 4; i++) {
        int n = n0 + ty + i * 8;
        T[(size_t)n * K + k0 + tx] = __float2half_rn(tt[tx][ty + i * 8]);
    }
}

// ---------------------------------------------------------------------------
// fp16 HMMA GEMM core: tile 128x128x64, 8 warps (4m x 2n), cp.async 2-stage.
// ---------------------------------------------------------------------------
static constexpr int HROW   = 144;
static constexpr int HTILE  = 128 * HROW;         // 18432 per operand tile
static constexpr int HSTAGE = 2 * HTILE;          // A + B = 36864
static constexpr int HGEMM_SMEM = 2 * HSTAGE;     // 73728

__device__ __forceinline__ void gemm_core(const __half* Ab, const __half* Bb,
                                          uint32_t sb,
                                          int tid, int wm, int wn, int lid,
                                          float acc[2][8][4])
{
    constexpr int K = 1024;
    auto load_stage = [&](int kc, int buf) {
        const uint32_t base = sb + buf * HSTAGE;
#pragma unroll
        for (int i = 0; i < 8; i++) {
            int c = tid + i * 256;              // 0..2047 16B chunks
            int op = c >> 10;                   // 0=A 1=B
            int rem = c & 1023;
            int r = rem >> 3, q = rem & 7;
            const __half* s = (op ? Bb : Ab) + (size_t)r * K + kc * 64 + q * 8;
            cp16(base + op * HTILE + r * HROW + q * 16, s);
        }
    };

    const int lr = lid & 15;
    const int lh = (lid >> 4) << 4;

    load_stage(0, 0);
    CP_COMMIT();

    constexpr int nk = K >> 6;                   // 16
    for (int kc = 0; kc < nk; kc++) {
        const int buf = kc & 1;
        if (kc + 1 < nk) { load_stage(kc + 1, buf ^ 1); CP_COMMIT(); CP_WAIT(1); }
        else             { CP_WAIT(0); }
        __syncthreads();

        const uint32_t base = sb + buf * HSTAGE;
        const uint32_t aB = base +         (wm * 32 + lr) * HROW + lh;
        const uint32_t bB = base + HTILE + (wn * 64 + lr) * HROW + lh;

#pragma unroll
        for (int ks = 0; ks < 4; ks++) {
            const uint32_t ko = ks * 32;
            uint32_t a[2][4];
#pragma unroll
            for (int mi = 0; mi < 2; mi++)
                LDSM_X4(a[mi][0], a[mi][1], a[mi][2], a[mi][3],
                        aB + mi * 16 * HROW + ko);
            uint32_t b[8][2];
#pragma unroll
            for (int np = 0; np < 4; np++) {
                uint32_t t0, t1, t2, t3;
                LDSM_X4(t0, t1, t2, t3, bB + np * 16 * HROW + ko);
                b[np * 2][0] = t0; b[np * 2][1] = t2;
                b[np * 2 + 1][0] = t1; b[np * 2 + 1][1] = t3;
            }
#pragma unroll
            for (int mi = 0; mi < 2; mi++)
#pragma unroll
                for (int nj = 0; nj < 8; nj++)
                    MMAF16(acc[mi][nj], a[mi][0], a[mi][1], a[mi][2], a[mi][3],
                           b[nj][0], b[nj][1]);
        }
        __syncthreads();
    }
}

// ---------------------------------------------------------------------------
// qkv projection GEMM (N = 3072): fp16 output
// ---------------------------------------------------------------------------
__global__ __launch_bounds__(256, 2)
void gemm_qkv(const __half* __restrict__ A, const __half* __restrict__ B,
              const float* __restrict__ b_qkv, __half* __restrict__ QKVH)
{
    extern __shared__ char smem[];
    const uint32_t sb = smem_u32(smem);
    const int tid = threadIdx.x;
    const int wid = tid >> 5, lid = tid & 31;
    const int wm  = wid >> 1, wn = wid & 1;
    const int m0  = blockIdx.y * 128, n0 = blockIdx.x * 128;

    float acc[2][8][4];
#pragma unroll
    for (int i = 0; i < 2; i++)
#pragma unroll
        for (int j = 0; j < 8; j++)
#pragma unroll
            for (int v = 0; v < 4; v++) acc[i][j][v] = 0.f;

    gemm_core(A + (size_t)m0 * 1024, B + (size_t)n0 * 1024, sb, tid, wm, wn, lid, acc);

#pragma unroll
    for (int mi = 0; mi < 2; mi++) {
#pragma unroll
        for (int nj = 0; nj < 8; nj++) {
            const int col = n0 + wn * 64 + nj * 8 + (lid & 3) * 2;
            const float2 bv = *reinterpret_cast<const float2*>(b_qkv + col);
#pragma unroll
            for (int half_ = 0; half_ < 2; half_++) {
                const int row = m0 + wm * 32 + mi * 16 + (lid >> 2) + half_ * 8;
                *reinterpret_cast<uint32_t*>(&QKVH[(size_t)row * 3072 + col]) =
                    packh2(acc[mi][nj][half_ * 2 + 0] + bv.x,
                           acc[mi][nj][half_ * 2 + 1] + bv.y);
            }
        }
    }
}

// ---------------------------------------------------------------------------
// MEGA kernel: bid < 512 -> fp16 flash attention (+ exact mem-slot phase)
//              bid >= 512 -> k_col / v_col projection GEMM tiles
// Attention writes ctx into g_CtxH (NOT Xh) — Xh is still live as the
// A operand of the concurrent k/v GEMM blocks.
// ---------------------------------------------------------------------------
static constexpr int ROWB = 144;                  // 64 fp16 + 16B pad
static constexpr int QREG = 128 * ROWB;           // 18432
static constexpr int KSTG = 2 * 64 * ROWB;        // K + V per stage: 18432

__global__ __launch_bounds__(256, 2)
void attn_kv(const __half* __restrict__ qkvh, const __half* __restrict__ WH,
             const float* __restrict__ pk, const float* __restrict__ pv,
             const float* __restrict__ b_k, const float* __restrict__ b_v,
             const __half* __restrict__ Xh,
             __half* __restrict__ ctxh, float* __restrict__ kcol,
             float* __restrict__ vcol)
{
    extern __shared__ char sm[];
    const uint32_t sb = smem_u32(sm);
    const int bid = blockIdx.x;
    const int tid = threadIdx.x;
    const int wid = tid >> 5, lid = tid & 31;

    if (bid >= 512) {
        // ---------------- k/v projection GEMM tile ----------------
        const int t  = bid - 512;
        const int n0 = 3072 + (t & 15) * 128;     // rows of WH in [3072,5120)
        const int m0 = (t >> 4) * 128;
        const int wm = wid >> 1, wn = wid & 1;

        float acc[2][8][4];
#pragma unroll
        for (int i = 0; i < 2; i++)
#pragma unroll
            for (int j = 0; j < 8; j++)
#pragma unroll
                for (int v = 0; v < 4; v++) acc[i][j][v] = 0.f;

        gemm_core(Xh + (size_t)m0 * 1024, WH + (size_t)n0 * 1024,
                  sb, tid, wm, wn, lid, acc);

        const int seg = (n0 < 4096) ? 1 : 2;
        const float* bias = (seg == 1) ? b_k : b_v;
        const int segbase = (seg == 1) ? 3072 : 4096;
        float* dst = (seg == 1) ? kcol : vcol;

#pragma unroll
        for (int mi = 0; mi < 2; mi++) {
#pragma unroll
            for (int nj = 0; nj < 8; nj++) {
                const int col = n0 + wn * 64 + nj * 8 + (lid & 3) * 2;
                const int c = col - segbase;
                const float2 bv = *reinterpret_cast<const float2*>(bias + c);
#pragma unroll
                for (int half_ = 0; half_ < 2; half_++) {
                    const int row = m0 + wm * 32 + mi * 16 + (lid >> 2) + half_ * 8;
                    float2 o;
                    o.x = acc[mi][nj][half_ * 2 + 0] + bv.x;
                    o.y = acc[mi][nj][half_ * 2 + 1] + bv.y;
                    int b = row >> 10, s = row & 1023, h = c >> 6, d = c & 63;
                    *reinterpret_cast<float2*>(
                        &dst[(size_t)(((b * Hc + h) * Sc) + s) * HDc + d]) = o;
                }
            }
        }
        return;
    }

    // ---------------- attention path ----------------
    const int tile = 7 - (bid >> 6);
    const int h    = bid & 15;
    const int b    = (bid >> 4) & 3;

    const size_t qkv_row0 = (size_t)(b * Sc + tile * 128) * 3072;

#pragma unroll
    for (int i = 0; i < 4; i++) {
        int c = tid + i * 256;
        int r = c >> 3, o = (c & 7) * 16;
        cp16(sb + r * ROWB + o, qkvh + qkv_row0 + (size_t)r * 3072 + h * 64 + o / 2);
    }
    CP_COMMIT();

    const int nkt = 2 * tile + 2;
    auto load_stage = [&](int kt, int buf) {
        const uint32_t st = sb + QREG + buf * KSTG;
        const size_t row0 = (size_t)(b * Sc + kt * 64) * 3072;
#pragma unroll
        for (int i = 0; i < 4; i++) {
            int c = tid + i * 256;
            int arr = c >> 9;
            int rem = c & 511;
            int r = rem >> 3, o = (rem & 7) * 16;
            int colb = arr ? 2048 : 1024;
            cp16(st + arr * (64 * ROWB) + r * ROWB + o,
                 qkvh + row0 + (size_t)r * 3072 + colb + h * 64 + o / 2);
        }
    };
    load_stage(0, 0);
    CP_COMMIT();

    CP_WAIT(1);
    __syncthreads();
    uint32_t qf[16];
    {
        const uint32_t qbase = sb + (wid * 16 + (lid & 15)) * ROWB + ((lid >> 4) << 4);
#pragma unroll
        for (int kc = 0; kc < 4; kc++)
            LDSM_X4(qf[kc * 4 + 0], qf[kc * 4 + 1], qf[kc * 4 + 2], qf[kc * 4 + 3],
                    qbase + kc * 32);
    }
    __syncthreads();

    float o_acc[8][4];
#pragma unroll
    for (int j = 0; j < 8; j++)
#pragma unroll
        for (int v = 0; v < 4; v++) o_acc[j][v] = 0.f;
    float m0 = -1e30f, m1 = -1e30f, sr0 = 0.f, sr1 = 0.f;

    const int rA = tile * 128 + wid * 16 + (lid >> 2);
    const int diag = 2 * tile;

    for (int kt = 0; kt < nkt; kt++) {
        const int buf = kt & 1;
        if (kt + 1 < nkt) { load_stage(kt + 1, buf ^ 1); CP_COMMIT(); CP_WAIT(1); }
        else              { CP_WAIT(0); }
        __syncthreads();

        const uint32_t st = sb + QREG + buf * KSTG;
        const uint32_t Ks = st, Vs = st + 64 * ROWB;

        float s[8][4];
#pragma unroll
        for (int j = 0; j < 8; j++)
#pragma unroll
            for (int v = 0; v < 4; v++) s[j][v] = 0.f;

#pragma unroll
        for (int np = 0; np < 4; np++) {
            const uint32_t krow = (np * 16 + ((lid >> 4) & 1) * 8 + (lid & 7)) * ROWB
                                + ((lid >> 3) & 1) * 16;
#pragma unroll
            for (int kc = 0; kc < 4; kc++) {
                uint32_t k0, k1, k2, k3;
                LDSM_X4(k0, k1, k2, k3, Ks + krow + kc * 32);
                const uint32_t* qa = qf + kc * 4;
                MMAF16(s[2 * np],     qa[0], qa[1], qa[2], qa[3], k0, k1);
                MMAF16(s[2 * np + 1], qa[0], qa[1], qa[2], qa[3], k2, k3);
            }
        }

#pragma unroll
        for (int j = 0; j < 8; j++)
#pragma unroll
            for (int v = 0; v < 4; v++) s[j][v] *= 0.125f;
        if (kt >= diag) {
#pragma unroll
            for (int j = 0; j < 8; j++) {
                int c0 = kt * 64 + j * 8 + (lid & 3) * 2;
                if (c0     > rA)     s[j][0] = -1e30f;
                if (c0 + 1 > rA)     s[j][1] = -1e30f;
                if (c0     > rA + 8) s[j][2] = -1e30f;
                if (c0 + 1 > rA + 8) s[j][3] = -1e30f;
            }
        }

        float mx0 = -1e30f, mx1 = -1e30f;
#pragma unroll
        for (int j = 0; j < 8; j++) {
            mx0 = fmaxf(mx0, fmaxf(s[j][0], s[j][1]));
            mx1 = fmaxf(mx1, fmaxf(s[j][2], s[j][3]));
        }
        mx0 = fmaxf(mx0, __shfl_xor_sync(0xffffffffu, mx0, 1));
        mx0 = fmaxf(mx0, __shfl_xor_sync(0xffffffffu, mx0, 2));
        mx1 = fmaxf(mx1, __shfl_xor_sync(0xffffffffu, mx1, 1));
        mx1 = fmaxf(mx1, __shfl_xor_sync(0xffffffffu, mx1, 2));
        const float mn0 = fmaxf(m0, mx0), mn1 = fmaxf(m1, mx1);
        const float cr0 = __expf(m0 - mn0), cr1 = __expf(m1 - mn1);
        m0 = mn0; m1 = mn1;
        float ps0 = 0.f, ps1 = 0.f;
#pragma unroll
        for (int j = 0; j < 8; j++) {
            s[j][0] = __expf(s[j][0] - m0); ps0 += s[j][0];
            s[j][1] = __expf(s[j][1] - m0); ps0 += s[j][1];
            s[j][2] = __expf(s[j][2] - m1); ps1 += s[j][2];
            s[j][3] = __expf(s[j][3] - m1); ps1 += s[j][3];
        }
        ps0 += __shfl_xor_sync(0xffffffffu, ps0, 1);
        ps0 += __shfl_xor_sync(0xffffffffu, ps0, 2);
        ps1 += __shfl_xor_sync(0xffffffffu, ps1, 1);
        ps1 += __shfl_xor_sync(0xffffffffu, ps1, 2);
        sr0 = sr0 * cr0 + ps0;
        sr1 = sr1 * cr1 + ps1;
#pragma unroll
        for (int j = 0; j < 8; j++) {
            o_acc[j][0] *= cr0; o_acc[j][1] *= cr0;
            o_acc[j][2] *= cr1; o_acc[j][3] *= cr1;
        }

#pragma unroll
        for (int kc = 0; kc < 4; kc++) {
            uint32_t ph[4];
            ph[0] = packh2(s[2 * kc][0],     s[2 * kc][1]);
            ph[1] = packh2(s[2 * kc][2],     s[2 * kc][3]);
            ph[2] = packh2(s[2 * kc + 1][0], s[2 * kc + 1][1]);
            ph[3] = packh2(s[2 * kc + 1][2], s[2 * kc + 1][3]);
            const uint32_t vrow = (kc * 16 + ((lid >> 3) & 1) * 8 + (lid & 7)) * ROWB
                                + ((lid >> 4) & 1) * 16;
#pragma unroll
            for (int np = 0; np < 4; np++) {
                uint32_t v0, v1, v2, v3;
                LDSM_X4_T(v0, v1, v2, v3, Vs + vrow + np * 32);
                MMAF16(o_acc[2 * np],     ph[0], ph[1], ph[2], ph[3], v0, v1);
                MMAF16(o_acc[2 * np + 1], ph[0], ph[1], ph[2], ph[3], v2, v3);
            }
        }
        __syncthreads();
    }

    float* Os = reinterpret_cast<float*>(sm);           // [128][66]
    float* Ms = reinterpret_cast<float*>(sm + 33792);   // [128]
    float* Ss = Ms + 128;                               // [128]
    {
        const int ra = wid * 16 + (lid >> 2), rb = ra + 8;
#pragma unroll
        for (int j = 0; j < 8; j++) {
            const int col = j * 8 + (lid & 3) * 2;
            Os[ra * 66 + col]     = o_acc[j][0];
            Os[ra * 66 + col + 1] = o_acc[j][1];
            Os[rb * 66 + col]     = o_acc[j][2];
            Os[rb * 66 + col + 1] = o_acc[j][3];
        }
        if ((lid & 3) == 0) {
            Ms[ra] = m0; Ms[rb] = m1;
            Ss[ra] = sr0; Ss[rb] = sr1;
        }
    }
    __syncthreads();

    {
        const int row = tid >> 1, half_ = tid & 1;
        const int rg = tile * 128 + row;
        float q[32];
        {
            const size_t qo = (size_t)(b * Sc + rg) * 3072 + h * 64 + half_ * 32;
            const __half2* qh2 = reinterpret_cast<const __half2*>(qkvh + qo);
#pragma unroll
            for (int i = 0; i < 16; i++) {
                float2 f = __half22float2(qh2[i]);
                q[2 * i + 0] = f.x * 0.125f;
                q[2 * i + 1] = f.y * 0.125f;
            }
        }
        float m = Ms[row], sr = Ss[row];
        float acc[32];
#pragma unroll
        for (int i = 0; i < 32; i++) acc[i] = Os[row * 66 + half_ * 32 + i];

        const size_t pbase = ((size_t)((b * Hc + h) * Sc + rg)) * (Lc * HDc) + half_ * 32;
        const float* pkb = pk + pbase;
        const float* pvb = pv + pbase;
#pragma unroll 1
        for (int l = 0; l < Lc; l++) {
            float d0 = 0.f;
#pragma unroll
            for (int i = 0; i < 8; i++) {
                float4 kk = *reinterpret_cast<const float4*>(pkb + l * 64 + i * 4);
                d0 = fmaf(q[i * 4 + 0], kk.x, d0);
                d0 = fmaf(q[i * 4 + 1], kk.y, d0);
                d0 = fmaf(q[i * 4 + 2], kk.z, d0);
                d0 = fmaf(q[i * 4 + 3], kk.w, d0);
            }
            d0 += __shfl_xor_sync(0xffffffffu, d0, 1);
            float mn = fmaxf(m, d0);
            float cr = __expf(m - mn);
            float p = __expf(d0 - mn);
            m = mn;
            sr = sr * cr + p;
#pragma unroll
            for (int i = 0; i < 32; i++) acc[i] *= cr;
            const float4* vv4 = reinterpret_cast<const float4*>(pvb + l * 64);
#pragma unroll
            for (int i = 0; i < 8; i++) {
                float4 vv = vv4[i];
                acc[i * 4 + 0] = fmaf(p, vv.x, acc[i * 4 + 0]);
                acc[i * 4 + 1] = fmaf(p, vv.y, acc[i * 4 + 1]);
                acc[i * 4 + 2] = fmaf(p, vv.z, acc[i * 4 + 2]);
                acc[i * 4 + 3] = fmaf(p, vv.w, acc[i * 4 + 3]);
            }
        }
        const float inv = 1.f / sr;
        __half2* cp = reinterpret_cast<__half2*>(
            ctxh + (size_t)(b * Sc + rg) * Dc + h * 64 + half_ * 32);
#pragma unroll
        for (int i = 0; i < 16; i++)
            cp[i] = __floats2half2_rn(acc[2 * i] * inv, acc[2 * i + 1] * inv);
    }
}

// ---------------------------------------------------------------------------
// Output projection GEMM: fp32 row-major out
// ---------------------------------------------------------------------------
__global__ __launch_bounds__(256, 2)
void gemm_out(const __half* __restrict__ A, const __half* __restrict__ B,
              const float* __restrict__ bias, float* __restrict__ C)
{
    extern __shared__ char smem[];
    const uint32_t sb = smem_u32(smem);
    const int tid = threadIdx.x;
    const int wid = tid >> 5, lid = tid & 31;
    const int wm  = wid >> 1, wn = wid & 1;
    const int m0  = blockIdx.y * 128, n0 = blockIdx.x * 128;

    float acc[2][8][4];
#pragma unroll
    for (int i = 0; i < 2; i++)
#pragma unroll
        for (int j = 0; j < 8; j++)
#pragma unroll
            for (int v = 0; v < 4; v++) acc[i][j][v] = 0.f;

    gemm_core(A + (size_t)m0 * 1024, B + (size_t)n0 * 1024, sb, tid, wm, wn, lid, acc);

#pragma unroll
    for (int mi = 0; mi < 2; mi++) {
#pragma unroll
        for (int nj = 0; nj < 8; nj++) {
            const int col = n0 + wn * 64 + nj * 8 + (lid & 3) * 2;
            const float2 bv = *reinterpret_cast<const float2*>(bias + col);
#pragma unroll
            for (int half_ = 0; half_ < 2; half_++) {
                const int row = m0 + wm * 32 + mi * 16 + (lid >> 2) + half_ * 8;
                float2 o;
                o.x = acc[mi][nj][half_ * 2 + 0] + bv.x;
                o.y = acc[mi][nj][half_ * 2 + 1] + bv.y;
                *reinterpret_cast<float2*>(&C[(size_t)row * Dc + col]) = o;
            }
        }
    }
}

// ---------------------------------------------------------------------------
extern "C" void kernel_launch(void* const* d_in, const int* in_sizes, int n_in,
                              void* d_out, int out_size)
{
    const float* x     = (const float*)d_in[0];
    const float* pk    = (const float*)d_in[1];
    const float* pv    = (const float*)d_in[2];
    const float* w_qkv = (const float*)d_in[3];
    const float* b_qkv = (const float*)d_in[4];
    const float* b_k   = (const float*)d_in[6];
    const float* w_k   = (const float*)d_in[5];
    const float* w_v   = (const float*)d_in[7];
    const float* b_v   = (const float*)d_in[8];
    const float* w_o   = (const float*)d_in[9];
    const float* b_o   = (const float*)d_in[10];

    float* out  = (float*)d_out;
    float* kcol = out + (size_t)Bc * Sc * Dc;
    float* vcol = kcol + (size_t)Bc * Hc * Sc * HDc;

    static __half *Xh, *CtxH, *WH, *WoH, *QKVH;
    static bool inited = false;
    if (!inited) {
        inited = true;
        cudaGetSymbolAddress((void**)&Xh, g_Xh);
        cudaGetSymbolAddress((void**)&CtxH, g_CtxH);
        cudaGetSymbolAddress((void**)&WH, g_WH);
        cudaGetSymbolAddress((void**)&WoH, g_WoH);
        cudaGetSymbolAddress((void**)&QKVH, g_QKVH);
        cudaFuncSetAttribute(gemm_qkv,
                             cudaFuncAttributeMaxDynamicSharedMemorySize, HGEMM_SMEM);
        cudaFuncSetAttribute(attn_kv,
                             cudaFuncAttributeMaxDynamicSharedMemorySize, HGEMM_SMEM);
        cudaFuncSetAttribute(gemm_out,
                             cudaFuncAttributeMaxDynamicSharedMemorySize, HGEMM_SMEM);
    }

    // --- all operand conversions in one launch ---
    convert_all<<<7168, dim3(32, 8)>>>(x, w_qkv, w_k, w_v, w_o, Xh, WH, WoH);

    // --- qkv projection (N = 3072) ---
    gemm_qkv<<<dim3(24, 32), 256, HGEMM_SMEM>>>(Xh, WH, b_qkv, QKVH);

    // --- MEGA: attention (blocks 0-511, writes CtxH) + k/v projection
    //     (blocks 512-1023, reads Xh) — no aliasing between the families ---
    attn_kv<<<1024, 256, HGEMM_SMEM>>>(QKVH, WH, pk, pv, b_k, b_v, Xh,
                                       CtxH, kcol, vcol);

    // --- output projection (reads CtxH) ---
    gemm_out<<<dim3(8, 32), 256, HGEMM_SMEM>>>(CtxH, WoH, b_o, out);
}

// round 11
// speedup vs baseline: 6.7528x; 1.0888x over previous
#include <cuda_runtime.h>
#include <cuda_fp16.h>
#include <cstdint>
#include <math.h>

// Problem constants
static constexpr int Bc  = 4;
static constexpr int Sc  = 1024;
static constexpr int Dc  = 1024;
static constexpr int Hc  = 16;
static constexpr int HDc = 64;
static constexpr int Lc  = 12;
static constexpr int BS  = Bc * Sc;       // 4096 rows

// ---------------------------------------------------------------------------
// Scratch (__device__ globals; no cudaMalloc allowed)
// ---------------------------------------------------------------------------
__device__ __half g_Xh[(size_t)BS * Dc];          // fp16 x operand
__device__ __half g_CtxH[(size_t)BS * Dc];        // fp16 ctx (attn output)
__device__ __half g_WH[(size_t)5 * Dc * Dc];      // [wqkv^T; wk^T; wv^T] fp16
__device__ __half g_WoH[(size_t)Dc * Dc];         // w_o^T fp16
__device__ __half g_QKVH[(size_t)BS * 3 * Dc];    // qkv fp16 (attn operands)
__device__ int    g_mcnt[32];                     // qkv m-block done (-> 24)
__device__ int    g_actx[32];                     // ctx m-block done (-> 16)

// ---------------------------------------------------------------------------
// PTX helpers (base-PTX only: cp.async / ldmatrix / mma.sync)
// ---------------------------------------------------------------------------
__device__ __forceinline__ uint32_t smem_u32(const void* p) {
    uint32_t a;
    asm("{ .reg .u64 t; cvta.to.shared.u64 t, %1; cvt.u32.u64 %0, t; }"
        : "=r"(a) : "l"(p));
    return a;
}

__device__ __forceinline__ void cp16(uint32_t saddr, const void* gaddr) {
    asm volatile("cp.async.cg.shared.global [%0], [%1], 16;"
                 :: "r"(saddr), "l"(gaddr));
}
#define CP_COMMIT() asm volatile("cp.async.commit_group;" ::: "memory")
#define CP_WAIT(n)  asm volatile("cp.async.wait_group %0;" :: "n"(n) : "memory")

#define LDSM_X4(r0, r1, r2, r3, addr) \
    asm volatile("ldmatrix.sync.aligned.m8n8.x4.shared.b16 {%0,%1,%2,%3}, [%4];" \
                 : "=r"(r0), "=r"(r1), "=r"(r2), "=r"(r3) : "r"(addr))

#define LDSM_X4_T(r0, r1, r2, r3, addr) \
    asm volatile("ldmatrix.sync.aligned.m8n8.x4.trans.shared.b16 {%0,%1,%2,%3}, [%4];" \
                 : "=r"(r0), "=r"(r1), "=r"(r2), "=r"(r3) : "r"(addr))

#define MMAF16(d, a0, a1, a2, a3, b0, b1) \
    asm volatile("mma.sync.aligned.m16n8k16.row.col.f32.f16.f16.f32 " \
                 "{%0,%1,%2,%3}, {%4,%5,%6,%7}, {%8,%9}, {%0,%1,%2,%3};" \
                 : "+f"((d)[0]), "+f"((d)[1]), "+f"((d)[2]), "+f"((d)[3]) \
                 : "r"(a0), "r"(a1), "r"(a2), "r"(a3), "r"(b0), "r"(b1))

__device__ __forceinline__ uint32_t packh2(float a, float b) {
    __half2 h = __floats2half2_rn(a, b);
    return *reinterpret_cast<uint32_t*>(&h);
}

__device__ __forceinline__ void wait_cnt(const int* p, int target) {
    const volatile int* vp = (const volatile int*)p;
    while (*vp < target) __nanosleep(200);
}

// ---------------------------------------------------------------------------
// Mega-convert: blocks [0,1024): x -> fp16; blocks [1024,..): weight transposes
// Block 0 also zeroes the dependency counters for this invocation.
// ---------------------------------------------------------------------------
__global__ __launch_bounds__(256)
void convert_all(const float* __restrict__ x,
                 const float* __restrict__ w_qkv, const float* __restrict__ w_k,
                 const float* __restrict__ w_v,  const float* __restrict__ w_o,
                 __half* __restrict__ Xh, __half* __restrict__ WH,
                 __half* __restrict__ WoH)
{
    const int tx = threadIdx.x, ty = threadIdx.y;      // (32, 8)
    const int tid = ty * 32 + tx;
    const int bid = blockIdx.x;

    if (bid == 0 && tid < 32) { g_mcnt[tid] = 0; g_actx[tid] = 0; }

    if (bid < 1024) {
        const int idx = bid * 256 + tid;
#pragma unroll
        for (int j = 0; j < 4; j++) {
            int i = idx + j * 262144;
            float4 v = reinterpret_cast<const float4*>(x)[i];
            __half2 h01 = __floats2half2_rn(v.x, v.y);
            __half2 h23 = __floats2half2_rn(v.z, v.w);
            reinterpret_cast<__half2*>(Xh)[2 * i + 0] = h01;
            reinterpret_cast<__half2*>(Xh)[2 * i + 1] = h23;
        }
        return;
    }

    int t = bid - 1024;
    const float* W;
    __half* T;
    int N, tilesx;
    if (t < 3072)      { W = w_qkv; T = WH;                N = 3072; tilesx = 96; }
    else if (t < 4096) { W = w_k;   T = WH + 3072 * 1024;  N = 1024; tilesx = 32; t -= 3072; }
    else if (t < 5120) { W = w_v;   T = WH + 4096 * 1024;  N = 1024; tilesx = 32; t -= 4096; }
    else               { W = w_o;   T = WoH;               N = 1024; tilesx = 32; t -= 5120; }
    const int n0 = (t % tilesx) * 32;
    const int k0 = (t / tilesx) * 32;
    const int K = 1024;

    __shared__ float tt[32][33];
#pragma unroll
    for (int i = 0; i < 4; i++)
        tt[ty + i * 8][tx] = W[(size_t)(k0 + ty + i * 8) * N + n0 + tx];
    __syncthreads();
#pragma unroll
    for (int i = 0; i < 4; i++) {
        int n = n0 + ty + i * 8;
        T[(size_t)n * K + k0 + tx] = __float2half_rn(tt[tx][ty + i * 8]);
    }
}

// ---------------------------------------------------------------------------
// fp16 HMMA GEMM core: tile 128x128x64, 8 warps (4m x 2n), cp.async 2-stage.
// ---------------------------------------------------------------------------
static constexpr int HROW   = 144;
static constexpr int HTILE  = 128 * HROW;         // 18432 per operand tile
static constexpr int HSTAGE = 2 * HTILE;          // A + B = 36864
static constexpr int HGEMM_SMEM = 2 * HSTAGE;     // 73728

__device__ __forceinline__ void gemm_core(const __half* Ab, const __half* Bb,
                                          uint32_t sb,
                                          int tid, int wm, int wn, int lid,
                                          float acc[2][8][4])
{
    constexpr int K = 1024;
    auto load_stage = [&](int kc, int buf) {
        const uint32_t base = sb + buf * HSTAGE;
#pragma unroll
        for (int i = 0; i < 8; i++) {
            int c = tid + i * 256;              // 0..2047 16B chunks
            int op = c >> 10;                   // 0=A 1=B
            int rem = c & 1023;
            int r = rem >> 3, q = rem & 7;
            const __half* s = (op ? Bb : Ab) + (size_t)r * K + kc * 64 + q * 8;
            cp16(base + op * HTILE + r * HROW + q * 16, s);
        }
    };

    const int lr = lid & 15;
    const int lh = (lid >> 4) << 4;

    load_stage(0, 0);
    CP_COMMIT();

    constexpr int nk = K >> 6;                   // 16
    for (int kc = 0; kc < nk; kc++) {
        const int buf = kc & 1;
        if (kc + 1 < nk) { load_stage(kc + 1, buf ^ 1); CP_COMMIT(); CP_WAIT(1); }
        else             { CP_WAIT(0); }
        __syncthreads();

        const uint32_t base = sb + buf * HSTAGE;
        const uint32_t aB = base +         (wm * 32 + lr) * HROW + lh;
        const uint32_t bB = base + HTILE + (wn * 64 + lr) * HROW + lh;

#pragma unroll
        for (int ks = 0; ks < 4; ks++) {
            const uint32_t ko = ks * 32;
            uint32_t a[2][4];
#pragma unroll
            for (int mi = 0; mi < 2; mi++)
                LDSM_X4(a[mi][0], a[mi][1], a[mi][2], a[mi][3],
                        aB + mi * 16 * HROW + ko);
            uint32_t b[8][2];
#pragma unroll
            for (int np = 0; np < 4; np++) {
                uint32_t t0, t1, t2, t3;
                LDSM_X4(t0, t1, t2, t3, bB + np * 16 * HROW + ko);
                b[np * 2][0] = t0; b[np * 2][1] = t2;
                b[np * 2 + 1][0] = t1; b[np * 2 + 1][1] = t3;
            }
#pragma unroll
            for (int mi = 0; mi < 2; mi++)
#pragma unroll
                for (int nj = 0; nj < 8; nj++)
                    MMAF16(acc[mi][nj], a[mi][0], a[mi][1], a[mi][2], a[mi][3],
                           b[nj][0], b[nj][1]);
        }
        __syncthreads();
    }
}

// ---------------------------------------------------------------------------
// MEGA kernel — all four dependent families in one launch:
//  bid [0,768):     qkv GEMM    (producer of QKVH; bumps g_mcnt[m-block])
//  bid [768,1280):  attention   (gated on g_mcnt; bumps g_actx; writes CtxH)
//  bid [1280,1792): k/v GEMM    (independent filler; writes kcol/vcol)
//  bid [1792,2048): out GEMM    (gated on g_actx; writes out)
// All dependencies point to lower bids -> in-order dispatch = no deadlock.
// ---------------------------------------------------------------------------
static constexpr int ROWB = 144;
static constexpr int QREG = 128 * ROWB;           // 18432
static constexpr int KSTG = 2 * 64 * ROWB;        // 18432

__global__ __launch_bounds__(256, 2)
void mega(const __half* __restrict__ Xh, const __half* __restrict__ WH,
          const __half* __restrict__ WoH,
          const float* __restrict__ b_qkv, const float* __restrict__ b_k,
          const float* __restrict__ b_v,  const float* __restrict__ b_o,
          const float* __restrict__ pk,   const float* __restrict__ pv,
          __half* __restrict__ QKVH, __half* __restrict__ ctxh,
          float* __restrict__ out, float* __restrict__ kcol,
          float* __restrict__ vcol)
{
    extern __shared__ char sm[];
    const uint32_t sb = smem_u32(sm);
    const int bid = blockIdx.x;
    const int tid = threadIdx.x;
    const int wid = tid >> 5, lid = tid & 31;
    const int wm  = wid >> 1, wn = wid & 1;

    if (bid < 768) {
        // ---------------- qkv projection GEMM ----------------
        const int mIdx = bid / 24;
        const int mb   = (mIdx & 3) * 8 + (mIdx >> 2);   // tile-0 of all b first
        const int m0   = mb * 128;
        const int n0   = (bid % 24) * 128;

        float acc[2][8][4];
#pragma unroll
        for (int i = 0; i < 2; i++)
#pragma unroll
            for (int j = 0; j < 8; j++)
#pragma unroll
                for (int v = 0; v < 4; v++) acc[i][j][v] = 0.f;

        gemm_core(Xh + (size_t)m0 * 1024, WH + (size_t)n0 * 1024,
                  sb, tid, wm, wn, lid, acc);

#pragma unroll
        for (int mi = 0; mi < 2; mi++) {
#pragma unroll
            for (int nj = 0; nj < 8; nj++) {
                const int col = n0 + wn * 64 + nj * 8 + (lid & 3) * 2;
                const float2 bv = *reinterpret_cast<const float2*>(b_qkv + col);
#pragma unroll
                for (int half_ = 0; half_ < 2; half_++) {
                    const int row = m0 + wm * 32 + mi * 16 + (lid >> 2) + half_ * 8;
                    *reinterpret_cast<uint32_t*>(&QKVH[(size_t)row * 3072 + col]) =
                        packh2(acc[mi][nj][half_ * 2 + 0] + bv.x,
                               acc[mi][nj][half_ * 2 + 1] + bv.y);
                }
            }
        }
        __threadfence();
        __syncthreads();
        if (tid == 0) atomicAdd(&g_mcnt[mb], 1);
        return;
    }

    if (bid >= 1792) {
        // ---------------- output projection GEMM (gated on ctx) ----------------
        const int obid = bid - 1792;
        const int mb   = obid >> 3;
        const int m0   = mb * 128;
        const int n0   = (obid & 7) * 128;

        wait_cnt(&g_actx[mb], 16);
        __threadfence();

        float acc[2][8][4];
#pragma unroll
        for (int i = 0; i < 2; i++)
#pragma unroll
            for (int j = 0; j < 8; j++)
#pragma unroll
                for (int v = 0; v < 4; v++) acc[i][j][v] = 0.f;

        gemm_core(ctxh + (size_t)m0 * 1024, WoH + (size_t)n0 * 1024,
                  sb, tid, wm, wn, lid, acc);

#pragma unroll
        for (int mi = 0; mi < 2; mi++) {
#pragma unroll
            for (int nj = 0; nj < 8; nj++) {
                const int col = n0 + wn * 64 + nj * 8 + (lid & 3) * 2;
                const float2 bv = *reinterpret_cast<const float2*>(b_o + col);
#pragma unroll
                for (int half_ = 0; half_ < 2; half_++) {
                    const int row = m0 + wm * 32 + mi * 16 + (lid >> 2) + half_ * 8;
                    float2 o;
                    o.x = acc[mi][nj][half_ * 2 + 0] + bv.x;
                    o.y = acc[mi][nj][half_ * 2 + 1] + bv.y;
                    *reinterpret_cast<float2*>(&out[(size_t)row * Dc + col]) = o;
                }
            }
        }
        return;
    }

    if (bid >= 1280) {
        // ---------------- k/v projection GEMM (independent) ----------------
        const int t  = bid - 1280;
        const int n0 = 3072 + (t & 15) * 128;
        const int m0 = (t >> 4) * 128;

        float acc[2][8][4];
#pragma unroll
        for (int i = 0; i < 2; i++)
#pragma unroll
            for (int j = 0; j < 8; j++)
#pragma unroll
                for (int v = 0; v < 4; v++) acc[i][j][v] = 0.f;

        gemm_core(Xh + (size_t)m0 * 1024, WH + (size_t)n0 * 1024,
                  sb, tid, wm, wn, lid, acc);

        const int seg = (n0 < 4096) ? 1 : 2;
        const float* bias = (seg == 1) ? b_k : b_v;
        const int segbase = (seg == 1) ? 3072 : 4096;
        float* dst = (seg == 1) ? kcol : vcol;

#pragma unroll
        for (int mi = 0; mi < 2; mi++) {
#pragma unroll
            for (int nj = 0; nj < 8; nj++) {
                const int col = n0 + wn * 64 + nj * 8 + (lid & 3) * 2;
                const int c = col - segbase;
                const float2 bv = *reinterpret_cast<const float2*>(bias + c);
#pragma unroll
                for (int half_ = 0; half_ < 2; half_++) {
                    const int row = m0 + wm * 32 + mi * 16 + (lid >> 2) + half_ * 8;
                    float2 o;
                    o.x = acc[mi][nj][half_ * 2 + 0] + bv.x;
                    o.y = acc[mi][nj][half_ * 2 + 1] + bv.y;
                    int b = row >> 10, s = row & 1023, h = c >> 6, d = c & 63;
                    *reinterpret_cast<float2*>(
                        &dst[(size_t)(((b * Hc + h) * Sc) + s) * HDc + d]) = o;
                }
            }
        }
        return;
    }

    // ---------------- attention path (gated per-stage on qkv) ----------------
    const int abid = bid - 768;
    const int tile = abid >> 6;                  // ascending: matches producer order
    const int h    = abid & 15;
    const int b    = (abid >> 4) & 3;
    const int b8   = b * 8;

    const size_t qkv_row0 = (size_t)(b * Sc + tile * 128) * 3072;

    // Q tile gate + load
    wait_cnt(&g_mcnt[b8 + tile], 24);
#pragma unroll
    for (int i = 0; i < 4; i++) {
        int c = tid + i * 256;
        int r = c >> 3, o = (c & 7) * 16;
        cp16(sb + r * ROWB + o, QKVH + qkv_row0 + (size_t)r * 3072 + h * 64 + o / 2);
    }
    CP_COMMIT();

    const int nkt = 2 * tile + 2;
    auto load_stage = [&](int kt, int buf) {
        const uint32_t st = sb + QREG + buf * KSTG;
        const size_t row0 = (size_t)(b * Sc + kt * 64) * 3072;
#pragma unroll
        for (int i = 0; i < 4; i++) {
            int c = tid + i * 256;
            int arr = c >> 9;
            int rem = c & 511;
            int r = rem >> 3, o = (rem & 7) * 16;
            int colb = arr ? 2048 : 1024;
            cp16(st + arr * (64 * ROWB) + r * ROWB + o,
                 QKVH + row0 + (size_t)r * 3072 + colb + h * 64 + o / 2);
        }
    };
    wait_cnt(&g_mcnt[b8], 24);
    load_stage(0, 0);
    CP_COMMIT();

    CP_WAIT(1);
    __syncthreads();
    uint32_t qf[16];
    {
        const uint32_t qbase = sb + (wid * 16 + (lid & 15)) * ROWB + ((lid >> 4) << 4);
#pragma unroll
        for (int kc = 0; kc < 4; kc++)
            LDSM_X4(qf[kc * 4 + 0], qf[kc * 4 + 1], qf[kc * 4 + 2], qf[kc * 4 + 3],
                    qbase + kc * 32);
    }
    __syncthreads();

    float o_acc[8][4];
#pragma unroll
    for (int j = 0; j < 8; j++)
#pragma unroll
        for (int v = 0; v < 4; v++) o_acc[j][v] = 0.f;
    float m0 = -1e30f, m1 = -1e30f, sr0 = 0.f, sr1 = 0.f;

    const int rA = tile * 128 + wid * 16 + (lid >> 2);
    const int diag = 2 * tile;

    for (int kt = 0; kt < nkt; kt++) {
        const int buf = kt & 1;
        if (kt + 1 < nkt) {
            wait_cnt(&g_mcnt[b8 + ((kt + 1) >> 1)], 24);
            load_stage(kt + 1, buf ^ 1); CP_COMMIT(); CP_WAIT(1);
        } else {
            CP_WAIT(0);
        }
        __syncthreads();

        const uint32_t st = sb + QREG + buf * KSTG;
        const uint32_t Ks = st, Vs = st + 64 * ROWB;

        float s[8][4];
#pragma unroll
        for (int j = 0; j < 8; j++)
#pragma unroll
            for (int v = 0; v < 4; v++) s[j][v] = 0.f;

#pragma unroll
        for (int np = 0; np < 4; np++) {
            const uint32_t krow = (np * 16 + ((lid >> 4) & 1) * 8 + (lid & 7)) * ROWB
                                + ((lid >> 3) & 1) * 16;
#pragma unroll
            for (int kc = 0; kc < 4; kc++) {
                uint32_t k0, k1, k2, k3;
                LDSM_X4(k0, k1, k2, k3, Ks + krow + kc * 32);
                const uint32_t* qa = qf + kc * 4;
                MMAF16(s[2 * np],     qa[0], qa[1], qa[2], qa[3], k0, k1);
                MMAF16(s[2 * np + 1], qa[0], qa[1], qa[2], qa[3], k2, k3);
            }
        }

#pragma unroll
        for (int j = 0; j < 8; j++)
#pragma unroll
            for (int v = 0; v < 4; v++) s[j][v] *= 0.125f;
        if (kt >= diag) {
#pragma unroll
            for (int j = 0; j < 8; j++) {
                int c0 = kt * 64 + j * 8 + (lid & 3) * 2;
                if (c0     > rA)     s[j][0] = -1e30f;
                if (c0 + 1 > rA)     s[j][1] = -1e30f;
                if (c0     > rA + 8) s[j][2] = -1e30f;
                if (c0 + 1 > rA + 8) s[j][3] = -1e30f;
            }
        }

        float mx0 = -1e30f, mx1 = -1e30f;
#pragma unroll
        for (int j = 0; j < 8; j++) {
            mx0 = fmaxf(mx0, fmaxf(s[j][0], s[j][1]));
            mx1 = fmaxf(mx1, fmaxf(s[j][2], s[j][3]));
        }
        mx0 = fmaxf(mx0, __shfl_xor_sync(0xffffffffu, mx0, 1));
        mx0 = fmaxf(mx0, __shfl_xor_sync(0xffffffffu, mx0, 2));
        mx1 = fmaxf(mx1, __shfl_xor_sync(0xffffffffu, mx1, 1));
        mx1 = fmaxf(mx1, __shfl_xor_sync(0xffffffffu, mx1, 2));
        const float mn0 = fmaxf(m0, mx0), mn1 = fmaxf(m1, mx1);
        const float cr0 = __expf(m0 - mn0), cr1 = __expf(m1 - mn1);
        m0 = mn0; m1 = mn1;
        float ps0 = 0.f, ps1 = 0.f;
#pragma unroll
        for (int j = 0; j < 8; j++) {
            s[j][0] = __expf(s[j][0] - m0); ps0 += s[j][0];
            s[j][1] = __expf(s[j][1] - m0); ps0 += s[j][1];
            s[j][2] = __expf(s[j][2] - m1); ps1 += s[j][2];
            s[j][3] = __expf(s[j][3] - m1); ps1 += s[j][3];
        }
        ps0 += __shfl_xor_sync(0xffffffffu, ps0, 1);
        ps0 += __shfl_xor_sync(0xffffffffu, ps0, 2);
        ps1 += __shfl_xor_sync(0xffffffffu, ps1, 1);
        ps1 += __shfl_xor_sync(0xffffffffu, ps1, 2);
        sr0 = sr0 * cr0 + ps0;
        sr1 = sr1 * cr1 + ps1;
#pragma unroll
        for (int j = 0; j < 8; j++) {
            o_acc[j][0] *= cr0; o_acc[j][1] *= cr0;
            o_acc[j][2] *= cr1; o_acc[j][3] *= cr1;
        }

#pragma unroll
        for (int kc = 0; kc < 4; kc++) {
            uint32_t ph[4];
            ph[0] = packh2(s[2 * kc][0],     s[2 * kc][1]);
            ph[1] = packh2(s[2 * kc][2],     s[2 * kc][3]);
            ph[2] = packh2(s[2 * kc + 1][0], s[2 * kc + 1][1]);
            ph[3] = packh2(s[2 * kc + 1][2], s[2 * kc + 1][3]);
            const uint32_t vrow = (kc * 16 + ((lid >> 3) & 1) * 8 + (lid & 7)) * ROWB
                                + ((lid >> 4) & 1) * 16;
#pragma unroll
            for (int np = 0; np < 4; np++) {
                uint32_t v0, v1, v2, v3;
                LDSM_X4_T(v0, v1, v2, v3, Vs + vrow + np * 32);
                MMAF16(o_acc[2 * np],     ph[0], ph[1], ph[2], ph[3], v0, v1);
                MMAF16(o_acc[2 * np + 1], ph[0], ph[1], ph[2], ph[3], v2, v3);
            }
        }
        __syncthreads();
    }

    float* Os = reinterpret_cast<float*>(sm);           // [128][66]
    float* Ms = reinterpret_cast<float*>(sm + 33792);   // [128]
    float* Ss = Ms + 128;                               // [128]
    {
        const int ra = wid * 16 + (lid >> 2), rb = ra + 8;
#pragma unroll
        for (int j = 0; j < 8; j++) {
            const int col = j * 8 + (lid & 3) * 2;
            Os[ra * 66 + col]     = o_acc[j][0];
            Os[ra * 66 + col + 1] = o_acc[j][1];
            Os[rb * 66 + col]     = o_acc[j][2];
            Os[rb * 66 + col + 1] = o_acc[j][3];
        }
        if ((lid & 3) == 0) {
            Ms[ra] = m0; Ms[rb] = m1;
            Ss[ra] = sr0; Ss[rb] = sr1;
        }
    }
    __syncthreads();

    {
        const int row = tid >> 1, half_ = tid & 1;
        const int rg = tile * 128 + row;
        float q[32];
        {
            const size_t qo = (size_t)(b * Sc + rg) * 3072 + h * 64 + half_ * 32;
            const __half2* qh2 = reinterpret_cast<const __half2*>(QKVH + qo);
#pragma unroll
            for (int i = 0; i < 16; i++) {
                float2 f = __half22float2(qh2[i]);
                q[2 * i + 0] = f.x * 0.125f;
                q[2 * i + 1] = f.y * 0.125f;
            }
        }
        float m = Ms[row], sr = Ss[row];
        float acc[32];
#pragma unroll
        for (int i = 0; i < 32; i++) acc[i] = Os[row * 66 + half_ * 32 + i];

        const size_t pbase = ((size_t)((b * Hc + h) * Sc + rg)) * (Lc * HDc) + half_ * 32;
        const float* pkb = pk + pbase;
        const float* pvb = pv + pbase;
#pragma unroll 1
        for (int l = 0; l < Lc; l++) {
            float d0 = 0.f;
#pragma unroll
            for (int i = 0; i < 8; i++) {
                float4 kk = *reinterpret_cast<const float4*>(pkb + l * 64 + i * 4);
                d0 = fmaf(q[i * 4 + 0], kk.x, d0);
                d0 = fmaf(q[i * 4 + 1], kk.y, d0);
                d0 = fmaf(q[i * 4 + 2], kk.z, d0);
                d0 = fmaf(q[i * 4 + 3], kk.w, d0);
            }
            d0 += __shfl_xor_sync(0xffffffffu, d0, 1);
            float mn = fmaxf(m, d0);
            float cr = __expf(m - mn);
            float p = __expf(d0 - mn);
            m = mn;
            sr = sr * cr + p;
#pragma unroll
            for (int i = 0; i < 32; i++) acc[i] *= cr;
            const float4* vv4 = reinterpret_cast<const float4*>(pvb + l * 64);
#pragma unroll
            for (int i = 0; i < 8; i++) {
                float4 vv = vv4[i];
                acc[i * 4 + 0] = fmaf(p, vv.x, acc[i * 4 + 0]);
                acc[i * 4 + 1] = fmaf(p, vv.y, acc[i * 4 + 1]);
                acc[i * 4 + 2] = fmaf(p, vv.z, acc[i * 4 + 2]);
                acc[i * 4 + 3] = fmaf(p, vv.w, acc[i * 4 + 3]);
            }
        }
        const float inv = 1.f / sr;
        __half2* cp = reinterpret_cast<__half2*>(
            ctxh + (size_t)(b * Sc + rg) * Dc + h * 64 + half_ * 32);
#pragma unroll
        for (int i = 0; i < 16; i++)
            cp[i] = __floats2half2_rn(acc[2 * i] * inv, acc[2 * i + 1] * inv);
    }

    __threadfence();
    __syncthreads();
    if (tid == 0) atomicAdd(&g_actx[b8 + tile], 1);
}

// ---------------------------------------------------------------------------
extern "C" void kernel_launch(void* const* d_in, const int* in_sizes, int n_in,
                              void* d_out, int out_size)
{
    const float* x     = (const float*)d_in[0];
    const float* pk    = (const float*)d_in[1];
    const float* pv    = (const float*)d_in[2];
    const float* w_qkv = (const float*)d_in[3];
    const float* b_qkv = (const float*)d_in[4];
    const float* w_k   = (const float*)d_in[5];
    const float* b_k   = (const float*)d_in[6];
    const float* w_v   = (const float*)d_in[7];
    const float* b_v   = (const float*)d_in[8];
    const float* w_o   = (const float*)d_in[9];
    const float* b_o   = (const float*)d_in[10];

    float* out  = (float*)d_out;
    float* kcol = out + (size_t)Bc * Sc * Dc;
    float* vcol = kcol + (size_t)Bc * Hc * Sc * HDc;

    static __half *Xh, *CtxH, *WH, *WoH, *QKVH;
    static bool inited = false;
    if (!inited) {
        inited = true;
        cudaGetSymbolAddress((void**)&Xh, g_Xh);
        cudaGetSymbolAddress((void**)&CtxH, g_CtxH);
        cudaGetSymbolAddress((void**)&WH, g_WH);
        cudaGetSymbolAddress((void**)&WoH, g_WoH);
        cudaGetSymbolAddress((void**)&QKVH, g_QKVH);
        cudaFuncSetAttribute(mega,
                             cudaFuncAttributeMaxDynamicSharedMemorySize, HGEMM_SMEM);
    }

    // --- conversions + counter reset ---
    convert_all<<<7168, dim3(32, 8)>>>(x, w_qkv, w_k, w_v, w_o, Xh, WH, WoH);

    // --- everything else: one dependency-pipelined launch ---
    mega<<<2048, 256, HGEMM_SMEM>>>(Xh, WH, WoH, b_qkv, b_k, b_v, b_o,
                                    pk, pv, QKVH, CtxH, out, kcol, vcol);
}